// round 1
// baseline (speedup 1.0000x reference)
#include <cuda_runtime.h>
#include <math.h>

#define Bc 2
#define Sc 2048
#define Dc 1024
#define Hc 16
#define Lc 6
#define Fc 4096
#define Vc 32000
#define DHc 64
#define MR (Bc*Sc)   // 4096 rows

// ---------------- scratch (no allocs allowed) ----------------
__device__ float g_x[MR*Dc];
__device__ float g_h[MR*Dc];
__device__ float g_q[MR*Dc];
__device__ float g_k[MR*Dc];
__device__ float g_v[MR*Dc];
__device__ float g_o[MR*Dc];
__device__ float g_f[MR*Fc];

// ---------------- embed ----------------
__global__ void embed_kernel(const int* __restrict__ ids,
                             const float* __restrict__ tok,
                             const float* __restrict__ pos,
                             float* __restrict__ x) {
    int row = blockIdx.x;           // 0..MR-1
    int s = row % Sc;
    int id = ids[row];
    const float* tr = tok + (size_t)id * Dc;
    const float* pr = pos + (size_t)s * Dc;
    float* xr = x + (size_t)row * Dc;
    for (int d = threadIdx.x; d < Dc; d += blockDim.x)
        xr[d] = tr[d] + pr[d];
}

// ---------------- layernorm (one block per row) ----------------
__global__ void ln_kernel(const float* __restrict__ x,
                          const float* __restrict__ w,
                          const float* __restrict__ b,
                          float* __restrict__ y) {
    int row = blockIdx.x;
    const float* xr = x + (size_t)row * Dc;
    float* yr = y + (size_t)row * Dc;
    __shared__ float r1[256], r2[256];
    float s = 0.f, s2 = 0.f;
    for (int d = threadIdx.x; d < Dc; d += 256) {
        float v = xr[d];
        s += v; s2 += v * v;
    }
    r1[threadIdx.x] = s; r2[threadIdx.x] = s2;
    __syncthreads();
    for (int st = 128; st > 0; st >>= 1) {
        if (threadIdx.x < st) {
            r1[threadIdx.x] += r1[threadIdx.x + st];
            r2[threadIdx.x] += r2[threadIdx.x + st];
        }
        __syncthreads();
    }
    float mean = r1[0] * (1.0f / Dc);
    float var = r2[0] * (1.0f / Dc) - mean * mean;
    float rstd = rsqrtf(var + 1e-5f);
    for (int d = threadIdx.x; d < Dc; d += 256)
        yr[d] = (xr[d] - mean) * rstd * w[d] + b[d];
}

// ---------------- gelu (exact, erf) ----------------
__global__ void gelu_kernel(float* __restrict__ x, int n) {
    int i = blockIdx.x * 256 + threadIdx.x;
    if (i < n) {
        float v = x[i];
        x[i] = 0.5f * v * (1.0f + erff(v * 0.70710678118654752f));
    }
}

// ---------------- SGEMM 128x128x8, 8x8 microtile ----------------
// C[M,N] = A[M,K] @ op(B) + bias + res
// transB=0: B is [K,N] row-major.  transB=1: B is [N,K] row-major (C = A @ B^T)
#define BM 128
#define BN 128
#define BK 8

__global__ __launch_bounds__(256, 2)
void gemm_kernel(const float* __restrict__ A, const float* __restrict__ B,
                 const float* __restrict__ bias, const float* __restrict__ res,
                 float* __restrict__ C, int M, int N, int K, int transB) {
    __shared__ float As[BK][BM];
    __shared__ float Bs[BK][BN];

    const int bm = blockIdx.y * BM;
    const int bn = blockIdx.x * BN;
    const int tid = threadIdx.x;
    const int tx = tid & 15;   // column group
    const int ty = tid >> 4;   // row group

    float acc[8][8];
#pragma unroll
    for (int i = 0; i < 8; i++)
#pragma unroll
        for (int j = 0; j < 8; j++) acc[i][j] = 0.f;

    // A-load mapping: each thread one float4 along K
    const int am = tid >> 1;            // 0..127
    const int ak = (tid & 1) * 4;       // 0 or 4
    // B-load mapping (NN): each thread one float4 along N
    const int bkk = tid >> 5;           // 0..7
    const int bnn = (tid & 31) * 4;     // 0..124
    // B-load mapping (NT): each thread one float4 along K
    const int tn = tid >> 1;            // 0..127
    const int tk = (tid & 1) * 4;

    for (int k0 = 0; k0 < K; k0 += BK) {
        {
            float4 a4 = *(const float4*)(A + (size_t)(bm + am) * K + k0 + ak);
            As[ak + 0][am] = a4.x; As[ak + 1][am] = a4.y;
            As[ak + 2][am] = a4.z; As[ak + 3][am] = a4.w;
        }
        if (!transB) {
            float4 b4 = *(const float4*)(B + (size_t)(k0 + bkk) * N + bn + bnn);
            *(float4*)&Bs[bkk][bnn] = b4;
        } else {
            float4 b4 = *(const float4*)(B + (size_t)(bn + tn) * K + k0 + tk);
            Bs[tk + 0][tn] = b4.x; Bs[tk + 1][tn] = b4.y;
            Bs[tk + 2][tn] = b4.z; Bs[tk + 3][tn] = b4.w;
        }
        __syncthreads();

#pragma unroll
        for (int kk = 0; kk < BK; kk++) {
            float a[8], bv[8];
            *(float4*)&a[0]  = *(const float4*)&As[kk][ty * 4];
            *(float4*)&a[4]  = *(const float4*)&As[kk][64 + ty * 4];
            *(float4*)&bv[0] = *(const float4*)&Bs[kk][tx * 4];
            *(float4*)&bv[4] = *(const float4*)&Bs[kk][64 + tx * 4];
#pragma unroll
            for (int i = 0; i < 8; i++)
#pragma unroll
                for (int j = 0; j < 8; j++)
                    acc[i][j] += a[i] * bv[j];
        }
        __syncthreads();
    }

    // epilogue
#pragma unroll
    for (int i = 0; i < 8; i++) {
        int r = bm + ((i >> 2) * 64) + ty * 4 + (i & 3);
#pragma unroll
        for (int j = 0; j < 8; j++) {
            int c = bn + ((j >> 2) * 64) + tx * 4 + (j & 3);
            float v = acc[i][j];
            if (bias) v += bias[c];
            if (res)  v += res[(size_t)r * N + c];
            C[(size_t)r * N + c] = v;
        }
    }
}

// ---------------- attention: one block per (q, h, b) ----------------
__global__ __launch_bounds__(256)
void attn_kernel(const float* __restrict__ q, const float* __restrict__ k,
                 const float* __restrict__ v, float* __restrict__ o) {
    const int qi = blockIdx.x, h = blockIdx.y, b = blockIdx.z;
    const int tid = threadIdx.x;
    __shared__ float sc[Sc];
    __shared__ float qv[DHc];
    __shared__ float red[256];
    __shared__ float part[4][DHc];
    const float scale = 0.125f;  // 1/sqrt(64)

    const float* qrow = q + ((size_t)(b * Sc + qi) * Dc + h * DHc);
    if (tid < DHc) qv[tid] = qrow[tid];
    __syncthreads();

    const int nk = qi + 1;
    float lmax = -1e30f;
    for (int kk = tid; kk < nk; kk += 256) {
        const float* kr = k + ((size_t)(b * Sc + kk) * Dc + h * DHc);
        float dot = 0.f;
#pragma unroll
        for (int d = 0; d < DHc; d += 4) {
            float4 k4 = *(const float4*)(kr + d);
            dot += qv[d] * k4.x + qv[d + 1] * k4.y + qv[d + 2] * k4.z + qv[d + 3] * k4.w;
        }
        dot *= scale;
        sc[kk] = dot;
        lmax = fmaxf(lmax, dot);
    }
    red[tid] = lmax;
    __syncthreads();
    for (int st = 128; st > 0; st >>= 1) {
        if (tid < st) red[tid] = fmaxf(red[tid], red[tid + st]);
        __syncthreads();
    }
    const float m = red[0];
    __syncthreads();

    float lsum = 0.f;
    for (int kk = tid; kk < nk; kk += 256) {
        float e = expf(sc[kk] - m);
        sc[kk] = e;
        lsum += e;
    }
    red[tid] = lsum;
    __syncthreads();
    for (int st = 128; st > 0; st >>= 1) {
        if (tid < st) red[tid] += red[tid + st];
        __syncthreads();
    }
    const float inv = 1.0f / red[0];
    __syncthreads();

    const int d = tid & 63, g = tid >> 6;
    float acc = 0.f;
    for (int kk = g; kk < nk; kk += 4)
        acc += sc[kk] * v[(size_t)(b * Sc + kk) * Dc + h * DHc + d];
    part[g][d] = acc;
    __syncthreads();
    if (g == 0) {
        float r = (part[0][d] + part[1][d] + part[2][d] + part[3][d]) * inv;
        o[(size_t)(b * Sc + qi) * Dc + h * DHc + d] = r;
    }
}

// ---------------- launcher ----------------
extern "C" void kernel_launch(void* const* d_in, const int* in_sizes, int n_in,
                              void* d_out, int out_size) {
    const int*   ids     = (const int*)d_in[0];
    const float* tok     = (const float*)d_in[1];
    const float* pos     = (const float*)d_in[2];
    const float* Wq      = (const float*)d_in[3];
    const float* bq      = (const float*)d_in[4];
    const float* Wk      = (const float*)d_in[5];
    const float* bk      = (const float*)d_in[6];
    const float* Wv      = (const float*)d_in[7];
    const float* bv      = (const float*)d_in[8];
    const float* Wo      = (const float*)d_in[9];
    const float* bo      = (const float*)d_in[10];
    const float* ln1w    = (const float*)d_in[11];
    const float* ln1b    = (const float*)d_in[12];
    const float* ln2w    = (const float*)d_in[13];
    const float* ln2b    = (const float*)d_in[14];
    const float* Wup     = (const float*)d_in[15];
    const float* bup     = (const float*)d_in[16];
    const float* Wdown   = (const float*)d_in[17];
    const float* bdown   = (const float*)d_in[18];
    const float* fnw     = (const float*)d_in[19];
    const float* fnb     = (const float*)d_in[20];
    float* out = (float*)d_out;

    float *x, *h, *q, *k, *v, *o, *f;
    cudaGetSymbolAddress((void**)&x, g_x);
    cudaGetSymbolAddress((void**)&h, g_h);
    cudaGetSymbolAddress((void**)&q, g_q);
    cudaGetSymbolAddress((void**)&k, g_k);
    cudaGetSymbolAddress((void**)&v, g_v);
    cudaGetSymbolAddress((void**)&o, g_o);
    cudaGetSymbolAddress((void**)&f, g_f);

    embed_kernel<<<MR, 256>>>(ids, tok, pos, x);

    const dim3 gD(Dc / BN, MR / BM);    // N=1024
    const dim3 gF(Fc / BN, MR / BM);    // N=4096
    const dim3 gV(Vc / BN, MR / BM);    // N=32000
    const dim3 gA(Sc, Hc, Bc);

    for (int l = 0; l < Lc; l++) {
        ln_kernel<<<MR, 256>>>(x, ln1w + l * Dc, ln1b + l * Dc, h);
        gemm_kernel<<<gD, 256>>>(h, Wq + (size_t)l * Dc * Dc, bq + l * Dc, nullptr, q, MR, Dc, Dc, 0);
        gemm_kernel<<<gD, 256>>>(h, Wk + (size_t)l * Dc * Dc, bk + l * Dc, nullptr, k, MR, Dc, Dc, 0);
        gemm_kernel<<<gD, 256>>>(h, Wv + (size_t)l * Dc * Dc, bv + l * Dc, nullptr, v, MR, Dc, Dc, 0);
        attn_kernel<<<gA, 256>>>(q, k, v, o);
        gemm_kernel<<<gD, 256>>>(o, Wo + (size_t)l * Dc * Dc, bo + l * Dc, x, x, MR, Dc, Dc, 0);
        ln_kernel<<<MR, 256>>>(x, ln2w + l * Dc, ln2b + l * Dc, h);
        gemm_kernel<<<gF, 256>>>(h, Wup + (size_t)l * Dc * Fc, bup + l * Fc, nullptr, f, MR, Fc, Dc, 0);
        gelu_kernel<<<(MR * Fc + 255) / 256, 256>>>(f, MR * Fc);
        gemm_kernel<<<gD, 256>>>(f, Wdown + (size_t)l * Fc * Dc, bdown + l * Dc, x, x, MR, Dc, Fc, 0);
    }

    ln_kernel<<<MR, 256>>>(x, fnw, fnb, h);
    // logits = h @ token_emb^T   (NT)
    gemm_kernel<<<gV, 256>>>(h, tok, nullptr, nullptr, out, MR, Vc, Dc, 1);
}

// round 3
// speedup vs baseline: 3.9448x; 3.9448x over previous
#include <cuda_runtime.h>
#include <cuda_bf16.h>
#include <math.h>
#include <stdint.h>

#define Bc 2
#define Sc 2048
#define Dc 1024
#define Hc 16
#define Lc 6
#define Fc 4096
#define Vc 32000
#define DHc 64
#define MR (Bc*Sc)   // 4096 rows

// ---------------------------------------------------------------------------
// scratch (static device globals; no allocations allowed)
// ---------------------------------------------------------------------------
__device__ float g_x[MR*Dc];
__device__ float g_q[MR*Dc];
__device__ float g_k[MR*Dc];
__device__ float g_v[MR*Dc];
__device__ float g_f[MR*Fc];
__device__ __nv_bfloat16 g_ahi[MR*Fc];
__device__ __nv_bfloat16 g_alo[MR*Fc];
#define WPL 12582912   // elems per layer (4*D*D + D*F + F*D)
__device__ __nv_bfloat16 g_whi[Lc*WPL];
__device__ __nv_bfloat16 g_wlo[Lc*WPL];
__device__ __nv_bfloat16 g_thi[Vc*Dc];
__device__ __nv_bfloat16 g_tlo[Vc*Dc];

// ---------------------------------------------------------------------------
// helpers
// ---------------------------------------------------------------------------
__device__ __forceinline__ uint32_t s2u(const void* ptr) {
    uint32_t a;
    asm("{ .reg .u64 t; cvta.to.shared.u64 t, %1; cvt.u32.u64 %0, t; }"
        : "=r"(a) : "l"(ptr));
    return a;
}
__device__ __forceinline__ void cpasync16(uint32_t dst, const void* src) {
    asm volatile("cp.async.cg.shared.global [%0], [%1], 16;" :: "r"(dst), "l"(src));
}
__device__ __forceinline__ void ldm4(uint32_t* r, uint32_t addr) {
    asm volatile("ldmatrix.sync.aligned.m8n8.x4.shared.b16 {%0,%1,%2,%3}, [%4];"
                 : "=r"(r[0]), "=r"(r[1]), "=r"(r[2]), "=r"(r[3]) : "r"(addr));
}
__device__ __forceinline__ void mma_bf16(float* d, const uint32_t* a, const uint32_t* b) {
    asm volatile(
        "mma.sync.aligned.m16n8k16.row.col.f32.bf16.bf16.f32 "
        "{%0,%1,%2,%3}, {%4,%5,%6,%7}, {%8,%9}, {%0,%1,%2,%3};"
        : "+f"(d[0]), "+f"(d[1]), "+f"(d[2]), "+f"(d[3])
        : "r"(a[0]), "r"(a[1]), "r"(a[2]), "r"(a[3]), "r"(b[0]), "r"(b[1]));
}
__device__ __forceinline__ void split2(float v, __nv_bfloat16* h, __nv_bfloat16* l) {
    __nv_bfloat16 hh = __float2bfloat16(v);
    *h = hh;
    *l = __float2bfloat16(v - __bfloat162float(hh));
}

// ---------------------------------------------------------------------------
// bf16 split-precision MMA GEMM: C[M,N] = (Ah+Al)[M,K] @ (Bh+Bl)[N,K]^T (+bias,+res)
// Block 128x128, 8 warps (2x4), warp tile 64x32, K-chunk 32, double-buffered.
// smem tiles: 128 rows x 32 bf16, row pitch 80B (conflict-free ldmatrix).
// ---------------------------------------------------------------------------
#define CHK 32
#define PITCHB 80
#define TILE_B (128*PITCHB)     // 10240
#define STAGE_B (4*TILE_B)      // 40960
#define GEMM_SMEM (2*STAGE_B)   // 81920

__device__ __forceinline__ void load_stage(
    const __nv_bfloat16* __restrict__ Ahi, const __nv_bfloat16* __restrict__ Alo,
    const __nv_bfloat16* __restrict__ Bhi, const __nv_bfloat16* __restrict__ Blo,
    int bm, int bn, int K, int k0, uint32_t sbase, int s, int tid) {
    const __nv_bfloat16* srcs[4] = {
        Ahi + (size_t)bm * K + k0, Alo + (size_t)bm * K + k0,
        Bhi + (size_t)bn * K + k0, Blo + (size_t)bn * K + k0};
    uint32_t dbase = sbase + s * STAGE_B;
#pragma unroll
    for (int t = 0; t < 4; t++) {
#pragma unroll
        for (int u = 0; u < 2; u++) {
            int id = tid + u * 256;
            int row = id >> 2, cc = id & 3;
            const char* g = (const char*)(srcs[t] + (size_t)row * K) + cc * 16;
            cpasync16(dbase + t * TILE_B + row * PITCHB + cc * 16, g);
        }
    }
}

__global__ __launch_bounds__(256, 1)
void gemm_mma(const __nv_bfloat16* __restrict__ Ahi, const __nv_bfloat16* __restrict__ Alo,
              const __nv_bfloat16* __restrict__ Bhi, const __nv_bfloat16* __restrict__ Blo,
              const float* __restrict__ bias, const float* __restrict__ res,
              float* __restrict__ C, int M, int N, int K) {
    extern __shared__ char smem[];
    const uint32_t sbase = s2u(smem);
    const int tid = threadIdx.x;
    const int warp = tid >> 5, lane = tid & 31;
    const int bm = blockIdx.y * 128, bn = blockIdx.x * 128;
    const int wm = (warp >> 2) * 64, wn = (warp & 3) * 32;

    float acc[4][4][4];
#pragma unroll
    for (int i = 0; i < 4; i++)
#pragma unroll
        for (int j = 0; j < 4; j++)
#pragma unroll
            for (int q = 0; q < 4; q++) acc[i][j][q] = 0.f;

    const int nch = K / CHK;
    load_stage(Ahi, Alo, Bhi, Blo, bm, bn, K, 0, sbase, 0, tid);
    asm volatile("cp.async.commit_group;" ::: "memory");

    const int g = lane >> 3, r = lane & 7;
    // per-lane ldmatrix row/col offsets
    const int a_row = r + (g & 1) * 8;        // + mt*16 + wm
    const int a_cb  = (g >> 1) * 16;          // + kb
    const int b_row = (g >> 1) * 8 + r;       // + p*16 + wn
    const int b_cb  = (g & 1) * 16;           // + kb

    for (int c = 0; c < nch; c++) {
        if (c + 1 < nch) {
            load_stage(Ahi, Alo, Bhi, Blo, bm, bn, K, (c + 1) * CHK, sbase, (c + 1) & 1, tid);
            asm volatile("cp.async.commit_group;" ::: "memory");
            asm volatile("cp.async.wait_group 1;" ::: "memory");
        } else {
            asm volatile("cp.async.wait_group 0;" ::: "memory");
        }
        __syncthreads();

        uint32_t base = sbase + (c & 1) * STAGE_B;
#pragma unroll
        for (int ks = 0; ks < 2; ks++) {
            const int kb = ks * 32;
            uint32_t ah[4][4], al[4][4], bh[4][2], bl[4][2];
#pragma unroll
            for (int mt = 0; mt < 4; mt++) {
                uint32_t ad = base + (wm + mt * 16 + a_row) * PITCHB + kb + a_cb;
                ldm4(ah[mt], ad);
                ldm4(al[mt], ad + TILE_B);
            }
#pragma unroll
            for (int p = 0; p < 2; p++) {
                uint32_t bd = base + 2 * TILE_B + (wn + p * 16 + b_row) * PITCHB + kb + b_cb;
                uint32_t t4[4];
                ldm4(t4, bd);
                bh[2 * p][0] = t4[0]; bh[2 * p][1] = t4[1];
                bh[2 * p + 1][0] = t4[2]; bh[2 * p + 1][1] = t4[3];
                ldm4(t4, bd + TILE_B);
                bl[2 * p][0] = t4[0]; bl[2 * p][1] = t4[1];
                bl[2 * p + 1][0] = t4[2]; bl[2 * p + 1][1] = t4[3];
            }
#pragma unroll
            for (int mt = 0; mt < 4; mt++)
#pragma unroll
                for (int nt = 0; nt < 4; nt++) {
                    mma_bf16(acc[mt][nt], ah[mt], bh[nt]);
                    mma_bf16(acc[mt][nt], ah[mt], bl[nt]);
                    mma_bf16(acc[mt][nt], al[mt], bh[nt]);
                }
        }
        __syncthreads();
    }

    // epilogue
#pragma unroll
    for (int mt = 0; mt < 4; mt++) {
        int r0 = bm + wm + mt * 16 + (lane >> 2);
#pragma unroll
        for (int nt = 0; nt < 4; nt++) {
            int cc = bn + wn + nt * 8 + (lane & 3) * 2;
            float b0 = bias ? bias[cc] : 0.f, b1 = bias ? bias[cc + 1] : 0.f;
            float v0 = acc[mt][nt][0] + b0, v1 = acc[mt][nt][1] + b1;
            float v2 = acc[mt][nt][2] + b0, v3 = acc[mt][nt][3] + b1;
            if (res) {
                v0 += res[(size_t)r0 * N + cc];     v1 += res[(size_t)r0 * N + cc + 1];
                v2 += res[(size_t)(r0 + 8) * N + cc]; v3 += res[(size_t)(r0 + 8) * N + cc + 1];
            }
            *(float2*)&C[(size_t)r0 * N + cc] = make_float2(v0, v1);
            *(float2*)&C[(size_t)(r0 + 8) * N + cc] = make_float2(v2, v3);
        }
    }
}

// ---------------------------------------------------------------------------
// weight transpose + bf16 hi/lo split: W[K,N] fp32 -> out[N,K] bf16 (hi,lo)
// ---------------------------------------------------------------------------
__global__ void wtrans_split(const float* __restrict__ W,
                             __nv_bfloat16* __restrict__ hi,
                             __nv_bfloat16* __restrict__ lo, int K, int N) {
    __shared__ float t[32][33];
    int n0 = blockIdx.x * 32, k0 = blockIdx.y * 32;
    int tx = threadIdx.x, ty = threadIdx.y;  // 32x8
#pragma unroll
    for (int r = 0; r < 4; r++)
        t[ty + r * 8][tx] = W[(size_t)(k0 + ty + r * 8) * N + n0 + tx];
    __syncthreads();
#pragma unroll
    for (int r = 0; r < 4; r++) {
        int a = ty + r * 8;
        float v = t[tx][a];
        size_t o = (size_t)(n0 + a) * K + k0 + tx;
        split2(v, &hi[o], &lo[o]);
    }
}

__global__ void split_kernel(const float* __restrict__ in,
                             __nv_bfloat16* __restrict__ hi,
                             __nv_bfloat16* __restrict__ lo, int n) {
    int i = blockIdx.x * 256 + threadIdx.x;
    if (i < n) split2(in[i], &hi[i], &lo[i]);
}

// ---------------------------------------------------------------------------
// embed
// ---------------------------------------------------------------------------
__global__ void embed_kernel(const int* __restrict__ ids,
                             const float* __restrict__ tok,
                             const float* __restrict__ pos,
                             float* __restrict__ x) {
    int row = blockIdx.x;
    int s = row % Sc;
    int id = ids[row];
    const float* tr = tok + (size_t)id * Dc;
    const float* pr = pos + (size_t)s * Dc;
    float* xr = x + (size_t)row * Dc;
    for (int d = threadIdx.x; d < Dc; d += blockDim.x) xr[d] = tr[d] + pr[d];
}

// ---------------------------------------------------------------------------
// layernorm -> bf16 hi/lo
// ---------------------------------------------------------------------------
__global__ void ln_kernel(const float* __restrict__ x,
                          const float* __restrict__ w, const float* __restrict__ b,
                          __nv_bfloat16* __restrict__ yhi, __nv_bfloat16* __restrict__ ylo) {
    int row = blockIdx.x;
    const float* xr = x + (size_t)row * Dc;
    __shared__ float r1[256], r2[256];
    float s = 0.f, s2 = 0.f;
    for (int d = threadIdx.x; d < Dc; d += 256) {
        float v = xr[d];
        s += v; s2 += v * v;
    }
    r1[threadIdx.x] = s; r2[threadIdx.x] = s2;
    __syncthreads();
    for (int st = 128; st > 0; st >>= 1) {
        if (threadIdx.x < st) {
            r1[threadIdx.x] += r1[threadIdx.x + st];
            r2[threadIdx.x] += r2[threadIdx.x + st];
        }
        __syncthreads();
    }
    float mean = r1[0] * (1.0f / Dc);
    float var = r2[0] * (1.0f / Dc) - mean * mean;
    float rstd = rsqrtf(var + 1e-5f);
    for (int d = threadIdx.x; d < Dc; d += 256) {
        float v = (xr[d] - mean) * rstd * w[d] + b[d];
        size_t o = (size_t)row * Dc + d;
        split2(v, &yhi[o], &ylo[o]);
    }
}

// ---------------------------------------------------------------------------
// gelu -> bf16 hi/lo
// ---------------------------------------------------------------------------
__global__ void gelu_kernel(const float* __restrict__ f,
                            __nv_bfloat16* __restrict__ hi,
                            __nv_bfloat16* __restrict__ lo, int n) {
    int i = blockIdx.x * 256 + threadIdx.x;
    if (i < n) {
        float v = f[i];
        float ge = 0.5f * v * (1.0f + erff(v * 0.70710678118654752f));
        split2(ge, &hi[i], &lo[i]);
    }
}

// ---------------------------------------------------------------------------
// flash attention (fp32 SIMT, 64-row q-tiles) -> bf16 hi/lo output
// ---------------------------------------------------------------------------
#define ATTN_SMEM (4*64*65*4)  // 66560

__global__ __launch_bounds__(256)
void attn_kernel(const float* __restrict__ q, const float* __restrict__ k,
                 const float* __restrict__ v,
                 __nv_bfloat16* __restrict__ ohi, __nv_bfloat16* __restrict__ olo) {
    extern __shared__ float sm[];
    float* Qs = sm;
    float* Ks = sm + 64 * 65;
    float* Vs = sm + 2 * 64 * 65;
    float* Ps = sm + 3 * 64 * 65;
    const int qt = blockIdx.x, h = blockIdx.y, b = blockIdx.z;
    const int tid = threadIdx.x;
    const int tx = tid & 15, ty = tid >> 4;
    const int r0 = ty * 4, c0 = tx * 4;

#pragma unroll
    for (int rep = 0; rep < 4; rep++) {
        int idx = rep * 256 + tid;
        int rr = idx >> 4, f4 = (idx & 15) * 4;
        float4 val = *(const float4*)(q + ((size_t)(b * Sc + qt * 64 + rr) * Dc + h * 64 + f4));
        Qs[rr * 65 + f4 + 0] = val.x * 0.125f;
        Qs[rr * 65 + f4 + 1] = val.y * 0.125f;
        Qs[rr * 65 + f4 + 2] = val.z * 0.125f;
        Qs[rr * 65 + f4 + 3] = val.w * 0.125f;
    }

    float O[4][4];
#pragma unroll
    for (int i = 0; i < 4; i++)
#pragma unroll
        for (int j = 0; j < 4; j++) O[i][j] = 0.f;
    float m[4] = {-1e30f, -1e30f, -1e30f, -1e30f};
    float l[4] = {0.f, 0.f, 0.f, 0.f};

    for (int kt = 0; kt <= qt; kt++) {
        __syncthreads();
#pragma unroll
        for (int rep = 0; rep < 4; rep++) {
            int idx = rep * 256 + tid;
            int rr = idx >> 4, f4 = (idx & 15) * 4;
            size_t base = (size_t)(b * Sc + kt * 64 + rr) * Dc + h * 64 + f4;
            float4 kv = *(const float4*)(k + base);
            Ks[rr * 65 + f4 + 0] = kv.x; Ks[rr * 65 + f4 + 1] = kv.y;
            Ks[rr * 65 + f4 + 2] = kv.z; Ks[rr * 65 + f4 + 3] = kv.w;
            float4 vv = *(const float4*)(v + base);
            Vs[rr * 65 + f4 + 0] = vv.x; Vs[rr * 65 + f4 + 1] = vv.y;
            Vs[rr * 65 + f4 + 2] = vv.z; Vs[rr * 65 + f4 + 3] = vv.w;
        }
        __syncthreads();

        float s[4][4];
#pragma unroll
        for (int i = 0; i < 4; i++)
#pragma unroll
            for (int j = 0; j < 4; j++) s[i][j] = 0.f;
#pragma unroll 16
        for (int d = 0; d < 64; d++) {
            float a0 = Qs[(r0 + 0) * 65 + d], a1 = Qs[(r0 + 1) * 65 + d];
            float a2 = Qs[(r0 + 2) * 65 + d], a3 = Qs[(r0 + 3) * 65 + d];
            float b0 = Ks[(c0 + 0) * 65 + d], b1 = Ks[(c0 + 1) * 65 + d];
            float b2 = Ks[(c0 + 2) * 65 + d], b3 = Ks[(c0 + 3) * 65 + d];
            s[0][0] += a0 * b0; s[0][1] += a0 * b1; s[0][2] += a0 * b2; s[0][3] += a0 * b3;
            s[1][0] += a1 * b0; s[1][1] += a1 * b1; s[1][2] += a1 * b2; s[1][3] += a1 * b3;
            s[2][0] += a2 * b0; s[2][1] += a2 * b1; s[2][2] += a2 * b2; s[2][3] += a2 * b3;
            s[3][0] += a3 * b0; s[3][1] += a3 * b1; s[3][2] += a3 * b2; s[3][3] += a3 * b3;
        }
        if (kt == qt) {
#pragma unroll
            for (int i = 0; i < 4; i++)
#pragma unroll
                for (int j = 0; j < 4; j++)
                    if (c0 + j > r0 + i) s[i][j] = -1e30f;
        }
        float al[4];
#pragma unroll
        for (int i = 0; i < 4; i++) {
            float rm = fmaxf(fmaxf(s[i][0], s[i][1]), fmaxf(s[i][2], s[i][3]));
            rm = fmaxf(rm, __shfl_xor_sync(0xffffffff, rm, 1));
            rm = fmaxf(rm, __shfl_xor_sync(0xffffffff, rm, 2));
            rm = fmaxf(rm, __shfl_xor_sync(0xffffffff, rm, 4));
            rm = fmaxf(rm, __shfl_xor_sync(0xffffffff, rm, 8));
            float mn = fmaxf(m[i], rm);
            al[i] = __expf(m[i] - mn);
            m[i] = mn;
            float rs = 0.f;
#pragma unroll
            for (int j = 0; j < 4; j++) {
                s[i][j] = __expf(s[i][j] - mn);
                rs += s[i][j];
            }
            rs += __shfl_xor_sync(0xffffffff, rs, 1);
            rs += __shfl_xor_sync(0xffffffff, rs, 2);
            rs += __shfl_xor_sync(0xffffffff, rs, 4);
            rs += __shfl_xor_sync(0xffffffff, rs, 8);
            l[i] = l[i] * al[i] + rs;
#pragma unroll
            for (int j = 0; j < 4; j++) O[i][j] *= al[i];
        }
#pragma unroll
        for (int i = 0; i < 4; i++)
#pragma unroll
            for (int j = 0; j < 4; j++) Ps[(r0 + i) * 65 + c0 + j] = s[i][j];
        __syncthreads();
#pragma unroll 8
        for (int c = 0; c < 64; c++) {
            float p0 = Ps[(r0 + 0) * 65 + c], p1 = Ps[(r0 + 1) * 65 + c];
            float p2 = Ps[(r0 + 2) * 65 + c], p3 = Ps[(r0 + 3) * 65 + c];
            float v0 = Vs[c * 65 + c0 + 0], v1 = Vs[c * 65 + c0 + 1];
            float v2 = Vs[c * 65 + c0 + 2], v3 = Vs[c * 65 + c0 + 3];
            O[0][0] += p0 * v0; O[0][1] += p0 * v1; O[0][2] += p0 * v2; O[0][3] += p0 * v3;
            O[1][0] += p1 * v0; O[1][1] += p1 * v1; O[1][2] += p1 * v2; O[1][3] += p1 * v3;
            O[2][0] += p2 * v0; O[2][1] += p2 * v1; O[2][2] += p2 * v2; O[2][3] += p2 * v3;
            O[3][0] += p3 * v0; O[3][1] += p3 * v1; O[3][2] += p3 * v2; O[3][3] += p3 * v3;
        }
    }
#pragma unroll
    for (int i = 0; i < 4; i++) {
        float inv = 1.0f / l[i];
#pragma unroll
        for (int j = 0; j < 4; j++) {
            size_t o = (size_t)(b * Sc + qt * 64 + r0 + i) * Dc + h * 64 + c0 + j;
            split2(O[i][j] * inv, &ohi[o], &olo[o]);
        }
    }
}

// ---------------------------------------------------------------------------
// launcher
// ---------------------------------------------------------------------------
extern "C" void kernel_launch(void* const* d_in, const int* in_sizes, int n_in,
                              void* d_out, int out_size) {
    const int*   ids   = (const int*)d_in[0];
    const float* tok   = (const float*)d_in[1];
    const float* pos   = (const float*)d_in[2];
    const float* Wq    = (const float*)d_in[3];
    const float* bq    = (const float*)d_in[4];
    const float* Wk    = (const float*)d_in[5];
    const float* bk    = (const float*)d_in[6];
    const float* Wv    = (const float*)d_in[7];
    const float* bv    = (const float*)d_in[8];
    const float* Wo    = (const float*)d_in[9];
    const float* bo    = (const float*)d_in[10];
    const float* ln1w  = (const float*)d_in[11];
    const float* ln1b  = (const float*)d_in[12];
    const float* ln2w  = (const float*)d_in[13];
    const float* ln2b  = (const float*)d_in[14];
    const float* Wup   = (const float*)d_in[15];
    const float* bup   = (const float*)d_in[16];
    const float* Wdown = (const float*)d_in[17];
    const float* bdown = (const float*)d_in[18];
    const float* fnw   = (const float*)d_in[19];
    const float* fnb   = (const float*)d_in[20];
    float* out = (float*)d_out;

    float *x, *q, *k, *v, *f;
    __nv_bfloat16 *ahi, *alo, *whi, *wlo, *thi, *tlo;
    cudaGetSymbolAddress((void**)&x, g_x);
    cudaGetSymbolAddress((void**)&q, g_q);
    cudaGetSymbolAddress((void**)&k, g_k);
    cudaGetSymbolAddress((void**)&v, g_v);
    cudaGetSymbolAddress((void**)&f, g_f);
    cudaGetSymbolAddress((void**)&ahi, g_ahi);
    cudaGetSymbolAddress((void**)&alo, g_alo);
    cudaGetSymbolAddress((void**)&whi, g_whi);
    cudaGetSymbolAddress((void**)&wlo, g_wlo);
    cudaGetSymbolAddress((void**)&thi, g_thi);
    cudaGetSymbolAddress((void**)&tlo, g_tlo);

    cudaFuncSetAttribute(gemm_mma, cudaFuncAttributeMaxDynamicSharedMemorySize, GEMM_SMEM);
    cudaFuncSetAttribute(attn_kernel, cudaFuncAttributeMaxDynamicSharedMemorySize, ATTN_SMEM);

    const dim3 tb32(32, 8);
    const dim3 gDD(Dc / 32, Dc / 32);
    const dim3 gDF(Fc / 32, Dc / 32);
    const dim3 gFD(Dc / 32, Fc / 32);

    for (int l = 0; l < Lc; l++) {
        size_t lb = (size_t)l * WPL;
        wtrans_split<<<gDD, tb32>>>(Wq + (size_t)l * Dc * Dc, whi + lb,           wlo + lb,           Dc, Dc);
        wtrans_split<<<gDD, tb32>>>(Wk + (size_t)l * Dc * Dc, whi + lb + 1048576, wlo + lb + 1048576, Dc, Dc);
        wtrans_split<<<gDD, tb32>>>(Wv + (size_t)l * Dc * Dc, whi + lb + 2097152, wlo + lb + 2097152, Dc, Dc);
        wtrans_split<<<gDD, tb32>>>(Wo + (size_t)l * Dc * Dc, whi + lb + 3145728, wlo + lb + 3145728, Dc, Dc);
        wtrans_split<<<gDF, tb32>>>(Wup + (size_t)l * Dc * Fc, whi + lb + 4194304, wlo + lb + 4194304, Dc, Fc);
        wtrans_split<<<gFD, tb32>>>(Wdown + (size_t)l * Fc * Dc, whi + lb + 8388608, wlo + lb + 8388608, Fc, Dc);
    }
    split_kernel<<<(Vc * Dc + 255) / 256, 256>>>(tok, thi, tlo, Vc * Dc);

    embed_kernel<<<MR, 256>>>(ids, tok, pos, x);

    const dim3 gmD(Dc / 128, MR / 128);
    const dim3 gmF(Fc / 128, MR / 128);
    const dim3 gmV(Vc / 128, MR / 128);
    const dim3 gA(Sc / 64, Hc, Bc);

    for (int l = 0; l < Lc; l++) {
        size_t lb = (size_t)l * WPL;
        ln_kernel<<<MR, 256>>>(x, ln1w + l * Dc, ln1b + l * Dc, ahi, alo);
        gemm_mma<<<gmD, 256, GEMM_SMEM>>>(ahi, alo, whi + lb,           wlo + lb,           bq + l * Dc, nullptr, q, MR, Dc, Dc);
        gemm_mma<<<gmD, 256, GEMM_SMEM>>>(ahi, alo, whi + lb + 1048576, wlo + lb + 1048576, bk + l * Dc, nullptr, k, MR, Dc, Dc);
        gemm_mma<<<gmD, 256, GEMM_SMEM>>>(ahi, alo, whi + lb + 2097152, wlo + lb + 2097152, bv + l * Dc, nullptr, v, MR, Dc, Dc);
        attn_kernel<<<gA, 256, ATTN_SMEM>>>(q, k, v, ahi, alo);
        gemm_mma<<<gmD, 256, GEMM_SMEM>>>(ahi, alo, whi + lb + 3145728, wlo + lb + 3145728, bo + l * Dc, x, x, MR, Dc, Dc);
        ln_kernel<<<MR, 256>>>(x, ln2w + l * Dc, ln2b + l * Dc, ahi, alo);
        gemm_mma<<<gmF, 256, GEMM_SMEM>>>(ahi, alo, whi + lb + 4194304, wlo + lb + 4194304, bup + l * Fc, nullptr, f, MR, Fc, Dc);
        gelu_kernel<<<(MR * Fc + 255) / 256, 256>>>(f, ahi, alo, MR * Fc);
        gemm_mma<<<gmD, 256, GEMM_SMEM>>>(ahi, alo, whi + lb + 8388608, wlo + lb + 8388608, bdown + l * Dc, x, x, MR, Dc, Fc);
    }

    ln_kernel<<<MR, 256>>>(x, fnw, fnb, ahi, alo);
    gemm_mma<<<gmV, 256, GEMM_SMEM>>>(ahi, alo, thi, tlo, nullptr, nullptr, out, MR, Vc, Dc);
}

// round 4
// speedup vs baseline: 5.0239x; 1.2735x over previous
#include <cuda_runtime.h>
#include <cuda_bf16.h>
#include <math.h>
#include <stdint.h>

#define Bc 2
#define Sc 2048
#define Dc 1024
#define Hc 16
#define Lc 6
#define Fc 4096
#define Vc 32000
#define DHc 64
#define MR (Bc*Sc)   // 4096 rows

// ---------------------------------------------------------------------------
// scratch (static device globals; no allocations allowed)
// ---------------------------------------------------------------------------
__device__ float g_x[MR*Dc];
__device__ __nv_bfloat16 g_qkv[6*MR*Dc];   // qhi,qlo,khi,klo,vhi,vlo
__device__ float g_f[MR*Fc];
__device__ __nv_bfloat16 g_ahi[MR*Fc];
__device__ __nv_bfloat16 g_alo[MR*Fc];
#define WPL 12582912   // elems per layer (4*D*D + D*F + F*D)
__device__ __nv_bfloat16 g_whi[Lc*WPL];
__device__ __nv_bfloat16 g_wlo[Lc*WPL];
__device__ __nv_bfloat16 g_thi[Vc*Dc];
__device__ __nv_bfloat16 g_tlo[Vc*Dc];

// ---------------------------------------------------------------------------
// helpers
// ---------------------------------------------------------------------------
__device__ __forceinline__ uint32_t s2u(const void* ptr) {
    uint32_t a;
    asm("{ .reg .u64 t; cvta.to.shared.u64 t, %1; cvt.u32.u64 %0, t; }"
        : "=r"(a) : "l"(ptr));
    return a;
}
__device__ __forceinline__ void cpasync16(uint32_t dst, const void* src) {
    asm volatile("cp.async.cg.shared.global [%0], [%1], 16;" :: "r"(dst), "l"(src));
}
__device__ __forceinline__ void ldm4(uint32_t* r, uint32_t addr) {
    asm volatile("ldmatrix.sync.aligned.m8n8.x4.shared.b16 {%0,%1,%2,%3}, [%4];"
                 : "=r"(r[0]), "=r"(r[1]), "=r"(r[2]), "=r"(r[3]) : "r"(addr));
}
__device__ __forceinline__ void ldm4t(uint32_t* r, uint32_t addr) {
    asm volatile("ldmatrix.sync.aligned.m8n8.x4.trans.shared.b16 {%0,%1,%2,%3}, [%4];"
                 : "=r"(r[0]), "=r"(r[1]), "=r"(r[2]), "=r"(r[3]) : "r"(addr));
}
__device__ __forceinline__ void mma_bf16(float* d, const uint32_t* a, const uint32_t* b) {
    asm volatile(
        "mma.sync.aligned.m16n8k16.row.col.f32.bf16.bf16.f32 "
        "{%0,%1,%2,%3}, {%4,%5,%6,%7}, {%8,%9}, {%0,%1,%2,%3};"
        : "+f"(d[0]), "+f"(d[1]), "+f"(d[2]), "+f"(d[3])
        : "r"(a[0]), "r"(a[1]), "r"(a[2]), "r"(a[3]), "r"(b[0]), "r"(b[1]));
}
__device__ __forceinline__ void split2(float v, __nv_bfloat16* h, __nv_bfloat16* l) {
    __nv_bfloat16 hh = __float2bfloat16(v);
    *h = hh;
    *l = __float2bfloat16(v - __bfloat162float(hh));
}
// pack two floats into bf16x2 hi + bf16x2 lo
__device__ __forceinline__ void pk2(float x, float y, uint32_t& hi, uint32_t& lo) {
    __nv_bfloat16 xh = __float2bfloat16(x), yh = __float2bfloat16(y);
    __nv_bfloat16 xl = __float2bfloat16(x - __bfloat162float(xh));
    __nv_bfloat16 yl = __float2bfloat16(y - __bfloat162float(yh));
    hi = ((uint32_t)__bfloat16_as_ushort(yh) << 16) | __bfloat16_as_ushort(xh);
    lo = ((uint32_t)__bfloat16_as_ushort(yl) << 16) | __bfloat16_as_ushort(xl);
}
// fast 2^y on the FMA pipe (y <= 0), err ~2e-6
__device__ __forceinline__ float ex2(float y) {
    y = fmaxf(y, -126.f);
    float fn = y + 12582912.f;
    int n = __float_as_int(fn) - 0x4B400000;
    float r = y - (fn - 12582912.f);
    float p = 1.3333558e-3f;
    p = fmaf(p, r, 9.6181291e-3f);
    p = fmaf(p, r, 5.5504109e-2f);
    p = fmaf(p, r, 2.4022651e-1f);
    p = fmaf(p, r, 6.9314718e-1f);
    p = fmaf(p, r, 1.0f);
    return p * __int_as_float((n + 127) << 23);
}
__device__ __forceinline__ uint32_t swz(uint32_t off) {
    return off ^ ((off >> 3) & 0x70);
}

// ---------------------------------------------------------------------------
// bf16 split-precision MMA GEMM: C = (Ah+Al)[M,K] @ (Bh+Bl)[N,K]^T (+bias,+res)
// Output: fp32 C, or bf16 hi/lo pair (Chi/Clo).
// ---------------------------------------------------------------------------
#define CHK 32
#define PITCHB 80
#define TILE_B (128*PITCHB)
#define STAGE_B (4*TILE_B)
#define GEMM_SMEM (2*STAGE_B)

__device__ __forceinline__ void load_stage(
    const __nv_bfloat16* __restrict__ Ahi, const __nv_bfloat16* __restrict__ Alo,
    const __nv_bfloat16* __restrict__ Bhi, const __nv_bfloat16* __restrict__ Blo,
    int bm, int bn, int K, int k0, uint32_t sbase, int s, int tid) {
    const __nv_bfloat16* srcs[4] = {
        Ahi + (size_t)bm * K + k0, Alo + (size_t)bm * K + k0,
        Bhi + (size_t)bn * K + k0, Blo + (size_t)bn * K + k0};
    uint32_t dbase = sbase + s * STAGE_B;
#pragma unroll
    for (int t = 0; t < 4; t++) {
#pragma unroll
        for (int u = 0; u < 2; u++) {
            int id = tid + u * 256;
            int row = id >> 2, cc = id & 3;
            const char* g = (const char*)(srcs[t] + (size_t)row * K) + cc * 16;
            cpasync16(dbase + t * TILE_B + row * PITCHB + cc * 16, g);
        }
    }
}

__global__ __launch_bounds__(256, 1)
void gemm_mma(const __nv_bfloat16* __restrict__ Ahi, const __nv_bfloat16* __restrict__ Alo,
              const __nv_bfloat16* __restrict__ Bhi, const __nv_bfloat16* __restrict__ Blo,
              const float* __restrict__ bias, const float* __restrict__ res,
              float* __restrict__ C, __nv_bfloat16* __restrict__ Chi,
              __nv_bfloat16* __restrict__ Clo, int M, int N, int K) {
    extern __shared__ char smem[];
    const uint32_t sbase = s2u(smem);
    const int tid = threadIdx.x;
    const int warp = tid >> 5, lane = tid & 31;
    const int bm = blockIdx.y * 128, bn = blockIdx.x * 128;
    const int wm = (warp >> 2) * 64, wn = (warp & 3) * 32;

    float acc[4][4][4];
#pragma unroll
    for (int i = 0; i < 4; i++)
#pragma unroll
        for (int j = 0; j < 4; j++)
#pragma unroll
            for (int q = 0; q < 4; q++) acc[i][j][q] = 0.f;

    const int nch = K / CHK;
    load_stage(Ahi, Alo, Bhi, Blo, bm, bn, K, 0, sbase, 0, tid);
    asm volatile("cp.async.commit_group;" ::: "memory");

    const int g = lane >> 3, r = lane & 7;
    const int a_row = r + (g & 1) * 8;
    const int a_cb  = (g >> 1) * 16;
    const int b_row = (g >> 1) * 8 + r;
    const int b_cb  = (g & 1) * 16;

    for (int c = 0; c < nch; c++) {
        if (c + 1 < nch) {
            load_stage(Ahi, Alo, Bhi, Blo, bm, bn, K, (c + 1) * CHK, sbase, (c + 1) & 1, tid);
            asm volatile("cp.async.commit_group;" ::: "memory");
            asm volatile("cp.async.wait_group 1;" ::: "memory");
        } else {
            asm volatile("cp.async.wait_group 0;" ::: "memory");
        }
        __syncthreads();

        uint32_t base = sbase + (c & 1) * STAGE_B;
#pragma unroll
        for (int ks = 0; ks < 2; ks++) {
            const int kb = ks * 32;
            uint32_t ah[4][4], al[4][4], bh[4][2], bl[4][2];
#pragma unroll
            for (int mt = 0; mt < 4; mt++) {
                uint32_t ad = base + (wm + mt * 16 + a_row) * PITCHB + kb + a_cb;
                ldm4(ah[mt], ad);
                ldm4(al[mt], ad + TILE_B);
            }
#pragma unroll
            for (int p = 0; p < 2; p++) {
                uint32_t bd = base + 2 * TILE_B + (wn + p * 16 + b_row) * PITCHB + kb + b_cb;
                uint32_t t4[4];
                ldm4(t4, bd);
                bh[2 * p][0] = t4[0]; bh[2 * p][1] = t4[1];
                bh[2 * p + 1][0] = t4[2]; bh[2 * p + 1][1] = t4[3];
                ldm4(t4, bd + TILE_B);
                bl[2 * p][0] = t4[0]; bl[2 * p][1] = t4[1];
                bl[2 * p + 1][0] = t4[2]; bl[2 * p + 1][1] = t4[3];
            }
#pragma unroll
            for (int mt = 0; mt < 4; mt++)
#pragma unroll
                for (int nt = 0; nt < 4; nt++) {
                    mma_bf16(acc[mt][nt], ah[mt], bh[nt]);
                    mma_bf16(acc[mt][nt], ah[mt], bl[nt]);
                    mma_bf16(acc[mt][nt], al[mt], bh[nt]);
                }
        }
        __syncthreads();
    }

#pragma unroll
    for (int mt = 0; mt < 4; mt++) {
        int r0 = bm + wm + mt * 16 + (lane >> 2);
#pragma unroll
        for (int nt = 0; nt < 4; nt++) {
            int cc = bn + wn + nt * 8 + (lane & 3) * 2;
            float b0 = bias ? bias[cc] : 0.f, b1 = bias ? bias[cc + 1] : 0.f;
            float v0 = acc[mt][nt][0] + b0, v1 = acc[mt][nt][1] + b1;
            float v2 = acc[mt][nt][2] + b0, v3 = acc[mt][nt][3] + b1;
            if (Chi) {
                uint32_t h01, l01, h23, l23;
                pk2(v0, v1, h01, l01);
                pk2(v2, v3, h23, l23);
                *(uint32_t*)&Chi[(size_t)r0 * N + cc] = h01;
                *(uint32_t*)&Clo[(size_t)r0 * N + cc] = l01;
                *(uint32_t*)&Chi[(size_t)(r0 + 8) * N + cc] = h23;
                *(uint32_t*)&Clo[(size_t)(r0 + 8) * N + cc] = l23;
            } else {
                if (res) {
                    v0 += res[(size_t)r0 * N + cc];       v1 += res[(size_t)r0 * N + cc + 1];
                    v2 += res[(size_t)(r0 + 8) * N + cc]; v3 += res[(size_t)(r0 + 8) * N + cc + 1];
                }
                *(float2*)&C[(size_t)r0 * N + cc] = make_float2(v0, v1);
                *(float2*)&C[(size_t)(r0 + 8) * N + cc] = make_float2(v2, v3);
            }
        }
    }
}

// ---------------------------------------------------------------------------
// MMA flash attention: block = (qt 64 rows, h, b), 4 warps, 64-col k-tiles.
// Q/K/V and output all bf16 hi/lo. Scores/softmax fp32 (base-2 domain).
// ---------------------------------------------------------------------------
#define ATT_STAGE 32768  // Kh,Kl,Vh,Vl each 8KB (64 rows x 128B, SW128)
#define ATT_SMEM (2*ATT_STAGE)

__global__ __launch_bounds__(128, 2)
void attn_mma(const __nv_bfloat16* __restrict__ qhi, const __nv_bfloat16* __restrict__ qlo,
              const __nv_bfloat16* __restrict__ khi, const __nv_bfloat16* __restrict__ klo,
              const __nv_bfloat16* __restrict__ vhi, const __nv_bfloat16* __restrict__ vlo,
              __nv_bfloat16* __restrict__ ohi, __nv_bfloat16* __restrict__ olo) {
    extern __shared__ char sm[];
    const uint32_t sb = s2u(sm);
    const int qt = blockIdx.x, h = blockIdx.y, b = blockIdx.z;
    const int tid = threadIdx.x, warp = tid >> 5, lane = tid & 31;
    const int g = lane >> 3, r = lane & 7;
    const int a_row = r + (g & 1) * 8, a_cb = (g >> 1) * 16;
    const int b_row = (g >> 1) * 8 + r, b_cb = (g & 1) * 16;
    const size_t hoff = (size_t)h * 64;
    const size_t rowbase = (size_t)(b * Sc) * Dc;

    // ---- Q tile -> smem (stage0 reuse) -> register fragments
#pragma unroll
    for (int t = 0; t < 2; t++) {
        const __nv_bfloat16* src = (t ? qlo : qhi) + rowbase + (size_t)(qt * 64) * Dc + hoff;
#pragma unroll
        for (int u = 0; u < 4; u++) {
            int id = u * 128 + tid;
            int row = id >> 3, c16 = id & 7;
            uint4 val = *(const uint4*)((const char*)(src + (size_t)row * Dc) + c16 * 16);
            *(uint4*)(sm + t * 8192 + swz(row * 128 + c16 * 16)) = val;
        }
    }
    __syncthreads();
    uint32_t qh_[4][4], ql_[4][4];
#pragma unroll
    for (int ks = 0; ks < 4; ks++) {
        uint32_t ad = sb + swz((warp * 16 + a_row) * 128 + ks * 32 + a_cb);
        ldm4(qh_[ks], ad);
        ldm4(ql_[ks], ad + 8192);
    }
    __syncthreads();

    float O[8][4];
#pragma unroll
    for (int i = 0; i < 8; i++)
#pragma unroll
        for (int j = 0; j < 4; j++) O[i][j] = 0.f;
    float m2[2] = {-1e30f, -1e30f};
    float lsum[2] = {0.f, 0.f};

    // stage loader
    const __nv_bfloat16* srcs[4] = {khi, klo, vhi, vlo};
#define LOAD_KV(S, KT) do { \
        size_t base_ = rowbase + (size_t)((KT) * 64) * Dc + hoff; \
        uint32_t dst_ = sb + (S) * ATT_STAGE; \
        _Pragma("unroll") \
        for (int t = 0; t < 4; t++) { \
            _Pragma("unroll") \
            for (int u = 0; u < 4; u++) { \
                int id = u * 128 + tid; \
                int row = id >> 3, c16 = id & 7; \
                cpasync16(dst_ + t * 8192 + swz(row * 128 + c16 * 16), \
                          (const char*)(srcs[t] + base_ + (size_t)row * Dc) + c16 * 16); \
            } \
        } \
        asm volatile("cp.async.commit_group;" ::: "memory"); \
    } while (0)

    LOAD_KV(0, 0);

    for (int kt = 0; kt <= qt; kt++) {
        if (kt < qt) {
            LOAD_KV((kt + 1) & 1, kt + 1);
            asm volatile("cp.async.wait_group 1;" ::: "memory");
        } else {
            asm volatile("cp.async.wait_group 0;" ::: "memory");
        }
        __syncthreads();
        const uint32_t kb_ = sb + (kt & 1) * ATT_STAGE;

        // ---- S = Q K^T (split bf16, 3 terms)
        float S[8][4];
#pragma unroll
        for (int i = 0; i < 8; i++)
#pragma unroll
            for (int j = 0; j < 4; j++) S[i][j] = 0.f;
#pragma unroll
        for (int ks = 0; ks < 4; ks++) {
#pragma unroll
            for (int p = 0; p < 4; p++) {
                uint32_t t4h[4], t4l[4];
                uint32_t bd = kb_ + swz((p * 16 + b_row) * 128 + ks * 32 + b_cb);
                ldm4(t4h, bd);
                ldm4(t4l, bd + 8192);
                uint32_t bh0[2] = {t4h[0], t4h[1]}, bh1[2] = {t4h[2], t4h[3]};
                uint32_t bl0[2] = {t4l[0], t4l[1]}, bl1[2] = {t4l[2], t4l[3]};
                mma_bf16(S[2 * p],     qh_[ks], bh0);
                mma_bf16(S[2 * p],     qh_[ks], bl0);
                mma_bf16(S[2 * p],     ql_[ks], bh0);
                mma_bf16(S[2 * p + 1], qh_[ks], bh1);
                mma_bf16(S[2 * p + 1], qh_[ks], bl1);
                mma_bf16(S[2 * p + 1], ql_[ks], bh1);
            }
        }
        // scale into base-2 domain: * (1/8 * log2(e))
        const float SC = 0.18033688f;
#pragma unroll
        for (int i = 0; i < 8; i++)
#pragma unroll
            for (int j = 0; j < 4; j++) S[i][j] *= SC;
        // causal mask on diagonal tile
        if (kt == qt) {
            int rr = warp * 16 + (lane >> 2);
#pragma unroll
            for (int nt = 0; nt < 8; nt++) {
                int cc = nt * 8 + (lane & 3) * 2;
                if (cc     > rr)     S[nt][0] = -1e30f;
                if (cc + 1 > rr)     S[nt][1] = -1e30f;
                if (cc     > rr + 8) S[nt][2] = -1e30f;
                if (cc + 1 > rr + 8) S[nt][3] = -1e30f;
            }
        }
        // online softmax (base-2)
        float mx0 = -1e30f, mx1 = -1e30f;
#pragma unroll
        for (int nt = 0; nt < 8; nt++) {
            mx0 = fmaxf(mx0, fmaxf(S[nt][0], S[nt][1]));
            mx1 = fmaxf(mx1, fmaxf(S[nt][2], S[nt][3]));
        }
        mx0 = fmaxf(mx0, __shfl_xor_sync(0xffffffff, mx0, 1));
        mx0 = fmaxf(mx0, __shfl_xor_sync(0xffffffff, mx0, 2));
        mx1 = fmaxf(mx1, __shfl_xor_sync(0xffffffff, mx1, 1));
        mx1 = fmaxf(mx1, __shfl_xor_sync(0xffffffff, mx1, 2));
        float mn0 = fmaxf(m2[0], mx0), mn1 = fmaxf(m2[1], mx1);
        float al0 = ex2(m2[0] - mn0), al1 = ex2(m2[1] - mn1);
        m2[0] = mn0; m2[1] = mn1;
        float s0 = 0.f, s1 = 0.f;
#pragma unroll
        for (int nt = 0; nt < 8; nt++) {
            S[nt][0] = ex2(S[nt][0] - mn0); s0 += S[nt][0];
            S[nt][1] = ex2(S[nt][1] - mn0); s0 += S[nt][1];
            S[nt][2] = ex2(S[nt][2] - mn1); s1 += S[nt][2];
            S[nt][3] = ex2(S[nt][3] - mn1); s1 += S[nt][3];
        }
        s0 += __shfl_xor_sync(0xffffffff, s0, 1);
        s0 += __shfl_xor_sync(0xffffffff, s0, 2);
        s1 += __shfl_xor_sync(0xffffffff, s1, 1);
        s1 += __shfl_xor_sync(0xffffffff, s1, 2);
        lsum[0] = lsum[0] * al0 + s0;
        lsum[1] = lsum[1] * al1 + s1;
#pragma unroll
        for (int nt = 0; nt < 8; nt++) {
            O[nt][0] *= al0; O[nt][1] *= al0;
            O[nt][2] *= al1; O[nt][3] *= al1;
        }
        // ---- O += P V (split bf16, 3 terms)
        const uint32_t vb = kb_ + 16384;
#pragma unroll
        for (int ks = 0; ks < 4; ks++) {
            uint32_t pah[4], pal[4];
            pk2(S[2 * ks][0],     S[2 * ks][1],     pah[0], pal[0]);
            pk2(S[2 * ks][2],     S[2 * ks][3],     pah[1], pal[1]);
            pk2(S[2 * ks + 1][0], S[2 * ks + 1][1], pah[2], pal[2]);
            pk2(S[2 * ks + 1][2], S[2 * ks + 1][3], pah[3], pal[3]);
#pragma unroll
            for (int dg = 0; dg < 4; dg++) {
                uint32_t th[4], tl[4];
                uint32_t vd = vb + swz((ks * 16 + (lane & 15)) * 128 + dg * 32 + (lane >> 4) * 16);
                ldm4t(th, vd);
                ldm4t(tl, vd + 8192);
                uint32_t bh0[2] = {th[0], th[1]}, bh1[2] = {th[2], th[3]};
                uint32_t bl0[2] = {tl[0], tl[1]}, bl1[2] = {tl[2], tl[3]};
                mma_bf16(O[2 * dg],     pah, bh0);
                mma_bf16(O[2 * dg],     pah, bl0);
                mma_bf16(O[2 * dg],     pal, bh0);
                mma_bf16(O[2 * dg + 1], pah, bh1);
                mma_bf16(O[2 * dg + 1], pah, bl1);
                mma_bf16(O[2 * dg + 1], pal, bh1);
            }
        }
        __syncthreads();
    }

    // ---- write O/l as bf16 hi/lo
    float inv0 = 1.f / lsum[0], inv1 = 1.f / lsum[1];
    int r0 = qt * 64 + warp * 16 + (lane >> 2);
#pragma unroll
    for (int nt = 0; nt < 8; nt++) {
        int cc = nt * 8 + (lane & 3) * 2;
        size_t o0 = rowbase + (size_t)r0 * Dc + hoff + cc;
        size_t o1 = o0 + (size_t)8 * Dc;
        uint32_t h01, l01, h23, l23;
        pk2(O[nt][0] * inv0, O[nt][1] * inv0, h01, l01);
        pk2(O[nt][2] * inv1, O[nt][3] * inv1, h23, l23);
        *(uint32_t*)&ohi[o0] = h01; *(uint32_t*)&olo[o0] = l01;
        *(uint32_t*)&ohi[o1] = h23; *(uint32_t*)&olo[o1] = l23;
    }
}

// ---------------------------------------------------------------------------
// weight transpose + bf16 hi/lo split
// ---------------------------------------------------------------------------
__global__ void wtrans_split(const float* __restrict__ W,
                             __nv_bfloat16* __restrict__ hi,
                             __nv_bfloat16* __restrict__ lo, int K, int N) {
    __shared__ float t[32][33];
    int n0 = blockIdx.x * 32, k0 = blockIdx.y * 32;
    int tx = threadIdx.x, ty = threadIdx.y;
#pragma unroll
    for (int r = 0; r < 4; r++)
        t[ty + r * 8][tx] = W[(size_t)(k0 + ty + r * 8) * N + n0 + tx];
    __syncthreads();
#pragma unroll
    for (int r = 0; r < 4; r++) {
        int a = ty + r * 8;
        float v = t[tx][a];
        size_t o = (size_t)(n0 + a) * K + k0 + tx;
        split2(v, &hi[o], &lo[o]);
    }
}

__global__ void split_kernel(const float* __restrict__ in,
                             __nv_bfloat16* __restrict__ hi,
                             __nv_bfloat16* __restrict__ lo, int n) {
    int i = blockIdx.x * 256 + threadIdx.x;
    if (i < n) split2(in[i], &hi[i], &lo[i]);
}

__global__ void embed_kernel(const int* __restrict__ ids,
                             const float* __restrict__ tok,
                             const float* __restrict__ pos,
                             float* __restrict__ x) {
    int row = blockIdx.x;
    int s = row % Sc;
    int id = ids[row];
    const float* tr = tok + (size_t)id * Dc;
    const float* pr = pos + (size_t)s * Dc;
    float* xr = x + (size_t)row * Dc;
    for (int d = threadIdx.x; d < Dc; d += blockDim.x) xr[d] = tr[d] + pr[d];
}

__global__ void ln_kernel(const float* __restrict__ x,
                          const float* __restrict__ w, const float* __restrict__ b,
                          __nv_bfloat16* __restrict__ yhi, __nv_bfloat16* __restrict__ ylo) {
    int row = blockIdx.x;
    const float* xr = x + (size_t)row * Dc;
    __shared__ float r1[256], r2[256];
    float s = 0.f, s2 = 0.f;
    for (int d = threadIdx.x; d < Dc; d += 256) {
        float v = xr[d];
        s += v; s2 += v * v;
    }
    r1[threadIdx.x] = s; r2[threadIdx.x] = s2;
    __syncthreads();
    for (int st = 128; st > 0; st >>= 1) {
        if (threadIdx.x < st) {
            r1[threadIdx.x] += r1[threadIdx.x + st];
            r2[threadIdx.x] += r2[threadIdx.x + st];
        }
        __syncthreads();
    }
    float mean = r1[0] * (1.0f / Dc);
    float var = r2[0] * (1.0f / Dc) - mean * mean;
    float rstd = rsqrtf(var + 1e-5f);
    for (int d = threadIdx.x; d < Dc; d += 256) {
        float v = (xr[d] - mean) * rstd * w[d] + b[d];
        size_t o = (size_t)row * Dc + d;
        split2(v, &yhi[o], &ylo[o]);
    }
}

__global__ void gelu_kernel(const float* __restrict__ f,
                            __nv_bfloat16* __restrict__ hi,
                            __nv_bfloat16* __restrict__ lo, int n) {
    int i = blockIdx.x * 256 + threadIdx.x;
    if (i < n) {
        float v = f[i];
        float ge = 0.5f * v * (1.0f + erff(v * 0.70710678118654752f));
        split2(ge, &hi[i], &lo[i]);
    }
}

// ---------------------------------------------------------------------------
// launcher
// ---------------------------------------------------------------------------
extern "C" void kernel_launch(void* const* d_in, const int* in_sizes, int n_in,
                              void* d_out, int out_size) {
    const int*   ids   = (const int*)d_in[0];
    const float* tok   = (const float*)d_in[1];
    const float* pos   = (const float*)d_in[2];
    const float* Wq    = (const float*)d_in[3];
    const float* bq    = (const float*)d_in[4];
    const float* Wk    = (const float*)d_in[5];
    const float* bk    = (const float*)d_in[6];
    const float* Wv    = (const float*)d_in[7];
    const float* bv    = (const float*)d_in[8];
    const float* Wo    = (const float*)d_in[9];
    const float* bo    = (const float*)d_in[10];
    const float* ln1w  = (const float*)d_in[11];
    const float* ln1b  = (const float*)d_in[12];
    const float* ln2w  = (const float*)d_in[13];
    const float* ln2b  = (const float*)d_in[14];
    const float* Wup   = (const float*)d_in[15];
    const float* bup   = (const float*)d_in[16];
    const float* Wdown = (const float*)d_in[17];
    const float* bdown = (const float*)d_in[18];
    const float* fnw   = (const float*)d_in[19];
    const float* fnb   = (const float*)d_in[20];
    float* out = (float*)d_out;

    float *x, *f;
    __nv_bfloat16 *qkv, *ahi, *alo, *whi, *wlo, *thi, *tlo;
    cudaGetSymbolAddress((void**)&x, g_x);
    cudaGetSymbolAddress((void**)&f, g_f);
    cudaGetSymbolAddress((void**)&qkv, g_qkv);
    cudaGetSymbolAddress((void**)&ahi, g_ahi);
    cudaGetSymbolAddress((void**)&alo, g_alo);
    cudaGetSymbolAddress((void**)&whi, g_whi);
    cudaGetSymbolAddress((void**)&wlo, g_wlo);
    cudaGetSymbolAddress((void**)&thi, g_thi);
    cudaGetSymbolAddress((void**)&tlo, g_tlo);
    __nv_bfloat16 *qhi = qkv,             *qlo = qkv + (size_t)MR * Dc;
    __nv_bfloat16 *khi = qkv + 2ull*MR*Dc, *klo = qkv + 3ull*MR*Dc;
    __nv_bfloat16 *vhi = qkv + 4ull*MR*Dc, *vlo = qkv + 5ull*MR*Dc;

    cudaFuncSetAttribute(gemm_mma, cudaFuncAttributeMaxDynamicSharedMemorySize, GEMM_SMEM);
    cudaFuncSetAttribute(attn_mma, cudaFuncAttributeMaxDynamicSharedMemorySize, ATT_SMEM);

    const dim3 tb32(32, 8);
    const dim3 gDD(Dc / 32, Dc / 32);
    const dim3 gDF(Fc / 32, Dc / 32);
    const dim3 gFD(Dc / 32, Fc / 32);

    for (int l = 0; l < Lc; l++) {
        size_t lb = (size_t)l * WPL;
        wtrans_split<<<gDD, tb32>>>(Wq + (size_t)l * Dc * Dc, whi + lb,           wlo + lb,           Dc, Dc);
        wtrans_split<<<gDD, tb32>>>(Wk + (size_t)l * Dc * Dc, whi + lb + 1048576, wlo + lb + 1048576, Dc, Dc);
        wtrans_split<<<gDD, tb32>>>(Wv + (size_t)l * Dc * Dc, whi + lb + 2097152, wlo + lb + 2097152, Dc, Dc);
        wtrans_split<<<gDD, tb32>>>(Wo + (size_t)l * Dc * Dc, whi + lb + 3145728, wlo + lb + 3145728, Dc, Dc);
        wtrans_split<<<gDF, tb32>>>(Wup + (size_t)l * Dc * Fc, whi + lb + 4194304, wlo + lb + 4194304, Dc, Fc);
        wtrans_split<<<gFD, tb32>>>(Wdown + (size_t)l * Fc * Dc, whi + lb + 8388608, wlo + lb + 8388608, Fc, Dc);
    }
    split_kernel<<<(Vc * Dc + 255) / 256, 256>>>(tok, thi, tlo, Vc * Dc);

    embed_kernel<<<MR, 256>>>(ids, tok, pos, x);

    const dim3 gmD(Dc / 128, MR / 128);
    const dim3 gmF(Fc / 128, MR / 128);
    const dim3 gmV(Vc / 128, MR / 128);
    const dim3 gA(Sc / 64, Hc, Bc);

    for (int l = 0; l < Lc; l++) {
        size_t lb = (size_t)l * WPL;
        ln_kernel<<<MR, 256>>>(x, ln1w + l * Dc, ln1b + l * Dc, ahi, alo);
        gemm_mma<<<gmD, 256, GEMM_SMEM>>>(ahi, alo, whi + lb,           wlo + lb,           bq + l * Dc, nullptr, nullptr, qhi, qlo, MR, Dc, Dc);
        gemm_mma<<<gmD, 256, GEMM_SMEM>>>(ahi, alo, whi + lb + 1048576, wlo + lb + 1048576, bk + l * Dc, nullptr, nullptr, khi, klo, MR, Dc, Dc);
        gemm_mma<<<gmD, 256, GEMM_SMEM>>>(ahi, alo, whi + lb + 2097152, wlo + lb + 2097152, bv + l * Dc, nullptr, nullptr, vhi, vlo, MR, Dc, Dc);
        attn_mma<<<gA, 128, ATT_SMEM>>>(qhi, qlo, khi, klo, vhi, vlo, ahi, alo);
        gemm_mma<<<gmD, 256, GEMM_SMEM>>>(ahi, alo, whi + lb + 3145728, wlo + lb + 3145728, bo + l * Dc, x, x, nullptr, nullptr, MR, Dc, Dc);
        ln_kernel<<<MR, 256>>>(x, ln2w + l * Dc, ln2b + l * Dc, ahi, alo);
        gemm_mma<<<gmF, 256, GEMM_SMEM>>>(ahi, alo, whi + lb + 4194304, wlo + lb + 4194304, bup + l * Fc, nullptr, f, nullptr, nullptr, MR, Fc, Dc);
        gelu_kernel<<<(MR * Fc + 255) / 256, 256>>>(f, ahi, alo, MR * Fc);
        gemm_mma<<<gmD, 256, GEMM_SMEM>>>(ahi, alo, whi + lb + 8388608, wlo + lb + 8388608, bdown + l * Dc, x, x, nullptr, nullptr, MR, Dc, Fc);
    }

    ln_kernel<<<MR, 256>>>(x, fnw, fnb, ahi, alo);
    gemm_mma<<<gmV, 256, GEMM_SMEM>>>(ahi, alo, thi, tlo, nullptr, nullptr, out, nullptr, nullptr, MR, Vc, Dc);
}

// round 6
// speedup vs baseline: 6.9300x; 1.3794x over previous
#include <cuda_runtime.h>
#include <cuda_bf16.h>
#include <cuda_fp16.h>
#include <math.h>
#include <stdint.h>

#define Bc 2
#define Sc 2048
#define Dc 1024
#define Hc 16
#define Lc 6
#define Fc 4096
#define Vc 32000
#define DHc 64
#define MR (Bc*Sc)   // 4096 rows

// ---------------------------------------------------------------------------
// scratch (static device globals; no allocations allowed)
// ---------------------------------------------------------------------------
__device__ float g_x[MR*Dc];
__device__ __nv_bfloat16 g_qkv[6*MR*Dc];   // qhi,qlo,khi,klo,vhi,vlo
__device__ __nv_bfloat16 g_ahi[MR*Fc];
__device__ __nv_bfloat16 g_alo[MR*Fc];
__device__ __nv_bfloat16 g_bhi[MR*Fc];     // GELU(ffn-up) output hi
__device__ __nv_bfloat16 g_blo[MR*Fc];     // GELU(ffn-up) output lo
#define WPL 12582912   // elems per layer (4*D*D + D*F + F*D)
__device__ __nv_bfloat16 g_whi[Lc*WPL];
__device__ __nv_bfloat16 g_wlo[Lc*WPL];
__device__ __half g_thi[Vc*Dc];
__device__ __half g_tlo[Vc*Dc];
__device__ float g_bqkv[Lc*3*Dc];

// ---------------------------------------------------------------------------
// helpers
// ---------------------------------------------------------------------------
__device__ __forceinline__ uint32_t s2u(const void* ptr) {
    uint32_t a;
    asm("{ .reg .u64 t; cvta.to.shared.u64 t, %1; cvt.u32.u64 %0, t; }"
        : "=r"(a) : "l"(ptr));
    return a;
}
__device__ __forceinline__ void cpasync16(uint32_t dst, const void* src) {
    asm volatile("cp.async.cg.shared.global [%0], [%1], 16;" :: "r"(dst), "l"(src));
}
__device__ __forceinline__ void ldm4(uint32_t* r, uint32_t addr) {
    asm volatile("ldmatrix.sync.aligned.m8n8.x4.shared.b16 {%0,%1,%2,%3}, [%4];"
                 : "=r"(r[0]), "=r"(r[1]), "=r"(r[2]), "=r"(r[3]) : "r"(addr));
}
__device__ __forceinline__ void ldm4t(uint32_t* r, uint32_t addr) {
    asm volatile("ldmatrix.sync.aligned.m8n8.x4.trans.shared.b16 {%0,%1,%2,%3}, [%4];"
                 : "=r"(r[0]), "=r"(r[1]), "=r"(r[2]), "=r"(r[3]) : "r"(addr));
}
template<bool H>
__device__ __forceinline__ void mma16(float* d, const uint32_t* a, const uint32_t* b) {
    if (H)
        asm volatile(
            "mma.sync.aligned.m16n8k16.row.col.f32.f16.f16.f32 "
            "{%0,%1,%2,%3}, {%4,%5,%6,%7}, {%8,%9}, {%0,%1,%2,%3};"
            : "+f"(d[0]), "+f"(d[1]), "+f"(d[2]), "+f"(d[3])
            : "r"(a[0]), "r"(a[1]), "r"(a[2]), "r"(a[3]), "r"(b[0]), "r"(b[1]));
    else
        asm volatile(
            "mma.sync.aligned.m16n8k16.row.col.f32.bf16.bf16.f32 "
            "{%0,%1,%2,%3}, {%4,%5,%6,%7}, {%8,%9}, {%0,%1,%2,%3};"
            : "+f"(d[0]), "+f"(d[1]), "+f"(d[2]), "+f"(d[3])
            : "r"(a[0]), "r"(a[1]), "r"(a[2]), "r"(a[3]), "r"(b[0]), "r"(b[1]));
}
__device__ __forceinline__ void mma_bf16(float* d, const uint32_t* a, const uint32_t* b) {
    mma16<false>(d, a, b);
}
__device__ __forceinline__ void split2(float v, __nv_bfloat16* h, __nv_bfloat16* l) {
    __nv_bfloat16 hh = __float2bfloat16(v);
    *h = hh;
    *l = __float2bfloat16(v - __bfloat162float(hh));
}
__device__ __forceinline__ void split2h(float v, __half* h, __half* l) {
    __half hh = __float2half(v);
    *h = hh;
    *l = __float2half(v - __half2float(hh));
}
__device__ __forceinline__ void pk2(float x, float y, uint32_t& hi, uint32_t& lo) {
    __nv_bfloat16 xh = __float2bfloat16(x), yh = __float2bfloat16(y);
    __nv_bfloat16 xl = __float2bfloat16(x - __bfloat162float(xh));
    __nv_bfloat16 yl = __float2bfloat16(y - __bfloat162float(yh));
    hi = ((uint32_t)__bfloat16_as_ushort(yh) << 16) | __bfloat16_as_ushort(xh);
    lo = ((uint32_t)__bfloat16_as_ushort(yl) << 16) | __bfloat16_as_ushort(xl);
}
// fast 2^y on the FMA pipe (y <= 0), err ~2e-6
__device__ __forceinline__ float ex2(float y) {
    y = fmaxf(y, -126.f);
    float fn = y + 12582912.f;
    int n = __float_as_int(fn) - 0x4B400000;
    float r = y - (fn - 12582912.f);
    float p = 1.3333558e-3f;
    p = fmaf(p, r, 9.6181291e-3f);
    p = fmaf(p, r, 5.5504109e-2f);
    p = fmaf(p, r, 2.4022651e-1f);
    p = fmaf(p, r, 6.9314718e-1f);
    p = fmaf(p, r, 1.0f);
    return p * __int_as_float((n + 127) << 23);
}
__device__ __forceinline__ uint32_t swz(uint32_t off) {
    return off ^ ((off >> 3) & 0x70);
}
__device__ __forceinline__ float gelu_f(float v) {
    return 0.5f * v * (1.0f + erff(v * 0.70710678118654752f));
}

// ---------------------------------------------------------------------------
// split-precision MMA GEMM, K-chunk 64, SW128 smem, double-buffered.
// bf16 (3-term): C = (Ah+Al)@(Bh+Bl)^T ; fp16 (2-term): C = (Ah+Al)@Bh^T
// ---------------------------------------------------------------------------
#define T16 16384                  // one 128x64 16-bit tile (128B rows)
#define GEMM_SMEM (2*4*T16)        // 131072 max (bf16 variant)

template<int TILES>
__device__ __forceinline__ void load_stage64(
    const __nv_bfloat16* s0, const __nv_bfloat16* s1,
    const __nv_bfloat16* s2, const __nv_bfloat16* s3,
    int K, int k0, uint32_t dbase, int tid) {
    const __nv_bfloat16* srcs[4] = {s0, s1, s2, s3};
#pragma unroll
    for (int t = 0; t < TILES; t++) {
#pragma unroll
        for (int u = 0; u < 4; u++) {
            int id = u * 256 + tid;
            int row = id >> 3, c = id & 7;
            cpasync16(dbase + t * T16 + swz(row * 128 + c * 16),
                      srcs[t] + (size_t)row * K + k0 + c * 8);
        }
    }
}

template<bool FP16W, bool GELU>
__global__ __launch_bounds__(256, 1)
void gemm_t(const __nv_bfloat16* __restrict__ Ahi, const __nv_bfloat16* __restrict__ Alo,
            const __nv_bfloat16* __restrict__ Bhi, const __nv_bfloat16* __restrict__ Blo,
            const float* __restrict__ bias, const float* __restrict__ res,
            float* __restrict__ C, __nv_bfloat16* __restrict__ Chi,
            __nv_bfloat16* __restrict__ Clo, int M, int N, int K, int oseg) {
    constexpr int TILES = FP16W ? 3 : 4;
    constexpr int STAGE = TILES * T16;
    extern __shared__ char smem[];
    const uint32_t sbase = s2u(smem);
    const int tid = threadIdx.x;
    const int warp = tid >> 5, lane = tid & 31;
    const int bm = blockIdx.y * 128, bn = blockIdx.x * 128;
    const int wm = (warp >> 2) * 64, wn = (warp & 3) * 32;

    float acc[4][4][4];
#pragma unroll
    for (int i = 0; i < 4; i++)
#pragma unroll
        for (int j = 0; j < 4; j++)
#pragma unroll
            for (int q = 0; q < 4; q++) acc[i][j][q] = 0.f;

    const __nv_bfloat16* A0 = Ahi + (size_t)bm * K;
    const __nv_bfloat16* A1 = Alo + (size_t)bm * K;
    const __nv_bfloat16* B0 = Bhi + (size_t)bn * K;
    const __nv_bfloat16* B1 = FP16W ? nullptr : Blo + (size_t)bn * K;

    const int nch = K >> 6;
    load_stage64<TILES>(A0, A1, B0, B1, K, 0, sbase, tid);
    asm volatile("cp.async.commit_group;" ::: "memory");

    const int g = lane >> 3, r = lane & 7;
    const int a_row = r + (g & 1) * 8;
    const int a_cb  = (g >> 1) * 16;
    const int b_row = (g >> 1) * 8 + r;
    const int b_cb  = (g & 1) * 16;

    for (int c = 0; c < nch; c++) {
        if (c + 1 < nch) {
            load_stage64<TILES>(A0, A1, B0, B1, K, (c + 1) * 64, sbase + ((c + 1) & 1) * STAGE, tid);
            asm volatile("cp.async.commit_group;" ::: "memory");
            asm volatile("cp.async.wait_group 1;" ::: "memory");
        } else {
            asm volatile("cp.async.wait_group 0;" ::: "memory");
        }
        __syncthreads();

        uint32_t base = sbase + (c & 1) * STAGE;
#pragma unroll
        for (int ks = 0; ks < 4; ks++) {
            const int kb = ks * 32;
            uint32_t ah[4][4], al[4][4], bh[4][2], bl[4][2];
#pragma unroll
            for (int mt = 0; mt < 4; mt++) {
                uint32_t ad = base + swz((wm + mt * 16 + a_row) * 128 + kb + a_cb);
                ldm4(ah[mt], ad);
                ldm4(al[mt], ad + T16);
            }
#pragma unroll
            for (int p = 0; p < 2; p++) {
                uint32_t bd = base + 2 * T16 + swz((wn + p * 16 + b_row) * 128 + kb + b_cb);
                uint32_t t4[4];
                ldm4(t4, bd);
                bh[2 * p][0] = t4[0]; bh[2 * p][1] = t4[1];
                bh[2 * p + 1][0] = t4[2]; bh[2 * p + 1][1] = t4[3];
                if (!FP16W) {
                    ldm4(t4, bd + T16);
                    bl[2 * p][0] = t4[0]; bl[2 * p][1] = t4[1];
                    bl[2 * p + 1][0] = t4[2]; bl[2 * p + 1][1] = t4[3];
                }
            }
#pragma unroll
            for (int mt = 0; mt < 4; mt++)
#pragma unroll
                for (int nt = 0; nt < 4; nt++) {
                    mma16<FP16W>(acc[mt][nt], ah[mt], bh[nt]);
                    mma16<FP16W>(acc[mt][nt], al[mt], bh[nt]);
                    if (!FP16W) mma16<false>(acc[mt][nt], ah[mt], bl[nt]);
                }
        }
        __syncthreads();
    }

    // ---- epilogue
    __nv_bfloat16 *chi = Chi, *clo = Clo;
    int ost = N, bnl = bn;
    if (oseg) {
        int t = bn / oseg;
        bnl = bn - t * oseg;
        ost = oseg;
        chi = Chi + (size_t)(2 * t) * M * oseg;
        clo = Chi + (size_t)(2 * t + 1) * M * oseg;
    }
#pragma unroll
    for (int mt = 0; mt < 4; mt++) {
        int r0 = bm + wm + mt * 16 + (lane >> 2);
#pragma unroll
        for (int nt = 0; nt < 4; nt++) {
            int ccg = bn + wn + nt * 8 + (lane & 3) * 2;   // for bias
            int ccl = bnl + wn + nt * 8 + (lane & 3) * 2;  // for store
            float b0 = bias ? bias[ccg] : 0.f, b1 = bias ? bias[ccg + 1] : 0.f;
            float v0 = acc[mt][nt][0] + b0, v1 = acc[mt][nt][1] + b1;
            float v2 = acc[mt][nt][2] + b0, v3 = acc[mt][nt][3] + b1;
            if (GELU) {
                v0 = gelu_f(v0); v1 = gelu_f(v1);
                v2 = gelu_f(v2); v3 = gelu_f(v3);
            }
            if (chi) {
                uint32_t h01, l01, h23, l23;
                pk2(v0, v1, h01, l01);
                pk2(v2, v3, h23, l23);
                *(uint32_t*)&chi[(size_t)r0 * ost + ccl] = h01;
                *(uint32_t*)&clo[(size_t)r0 * ost + ccl] = l01;
                *(uint32_t*)&chi[(size_t)(r0 + 8) * ost + ccl] = h23;
                *(uint32_t*)&clo[(size_t)(r0 + 8) * ost + ccl] = l23;
            } else {
                if (res) {
                    v0 += res[(size_t)r0 * N + ccg];       v1 += res[(size_t)r0 * N + ccg + 1];
                    v2 += res[(size_t)(r0 + 8) * N + ccg]; v3 += res[(size_t)(r0 + 8) * N + ccg + 1];
                }
                *(float2*)&C[(size_t)r0 * N + ccg] = make_float2(v0, v1);
                *(float2*)&C[(size_t)(r0 + 8) * N + ccg] = make_float2(v2, v3);
            }
        }
    }
}

// ---------------------------------------------------------------------------
// MMA flash attention: block = (qt 64 rows, h, b), 4 warps, 64-col k-tiles.
// ---------------------------------------------------------------------------
#define ATT_STAGE 32768
#define ATT_SMEM (2*ATT_STAGE)

__global__ __launch_bounds__(128, 2)
void attn_mma(const __nv_bfloat16* __restrict__ qhi, const __nv_bfloat16* __restrict__ qlo,
              const __nv_bfloat16* __restrict__ khi, const __nv_bfloat16* __restrict__ klo,
              const __nv_bfloat16* __restrict__ vhi, const __nv_bfloat16* __restrict__ vlo,
              __nv_bfloat16* __restrict__ ohi, __nv_bfloat16* __restrict__ olo) {
    extern __shared__ char sm[];
    const uint32_t sb = s2u(sm);
    const int qt = blockIdx.x, h = blockIdx.y, b = blockIdx.z;
    const int tid = threadIdx.x, warp = tid >> 5, lane = tid & 31;
    const int g = lane >> 3, r = lane & 7;
    const int a_row = r + (g & 1) * 8, a_cb = (g >> 1) * 16;
    const int b_row = (g >> 1) * 8 + r, b_cb = (g & 1) * 16;
    const size_t hoff = (size_t)h * 64;
    const size_t rowbase = (size_t)(b * Sc) * Dc;

#pragma unroll
    for (int t = 0; t < 2; t++) {
        const __nv_bfloat16* src = (t ? qlo : qhi) + rowbase + (size_t)(qt * 64) * Dc + hoff;
#pragma unroll
        for (int u = 0; u < 4; u++) {
            int id = u * 128 + tid;
            int row = id >> 3, c16 = id & 7;
            uint4 val = *(const uint4*)((const char*)(src + (size_t)row * Dc) + c16 * 16);
            *(uint4*)(sm + t * 8192 + swz(row * 128 + c16 * 16)) = val;
        }
    }
    __syncthreads();
    uint32_t qh_[4][4], ql_[4][4];
#pragma unroll
    for (int ks = 0; ks < 4; ks++) {
        uint32_t ad = sb + swz((warp * 16 + a_row) * 128 + ks * 32 + a_cb);
        ldm4(qh_[ks], ad);
        ldm4(ql_[ks], ad + 8192);
    }
    __syncthreads();

    float O[8][4];
#pragma unroll
    for (int i = 0; i < 8; i++)
#pragma unroll
        for (int j = 0; j < 4; j++) O[i][j] = 0.f;
    float m2[2] = {-1e30f, -1e30f};
    float lsum[2] = {0.f, 0.f};

    const __nv_bfloat16* srcs[4] = {khi, klo, vhi, vlo};
#define LOAD_KV(S, KT) do { \
        size_t base_ = rowbase + (size_t)((KT) * 64) * Dc + hoff; \
        uint32_t dst_ = sb + (S) * ATT_STAGE; \
        _Pragma("unroll") \
        for (int t = 0; t < 4; t++) { \
            _Pragma("unroll") \
            for (int u = 0; u < 4; u++) { \
                int id = u * 128 + tid; \
                int row = id >> 3, c16 = id & 7; \
                cpasync16(dst_ + t * 8192 + swz(row * 128 + c16 * 16), \
                          (const char*)(srcs[t] + base_ + (size_t)row * Dc) + c16 * 16); \
            } \
        } \
        asm volatile("cp.async.commit_group;" ::: "memory"); \
    } while (0)

    LOAD_KV(0, 0);

    for (int kt = 0; kt <= qt; kt++) {
        if (kt < qt) {
            LOAD_KV((kt + 1) & 1, kt + 1);
            asm volatile("cp.async.wait_group 1;" ::: "memory");
        } else {
            asm volatile("cp.async.wait_group 0;" ::: "memory");
        }
        __syncthreads();
        const uint32_t kb_ = sb + (kt & 1) * ATT_STAGE;

        float S[8][4];
#pragma unroll
        for (int i = 0; i < 8; i++)
#pragma unroll
            for (int j = 0; j < 4; j++) S[i][j] = 0.f;
#pragma unroll
        for (int ks = 0; ks < 4; ks++) {
#pragma unroll
            for (int p = 0; p < 4; p++) {
                uint32_t t4h[4], t4l[4];
                uint32_t bd = kb_ + swz((p * 16 + b_row) * 128 + ks * 32 + b_cb);
                ldm4(t4h, bd);
                ldm4(t4l, bd + 8192);
                uint32_t bh0[2] = {t4h[0], t4h[1]}, bh1[2] = {t4h[2], t4h[3]};
                uint32_t bl0[2] = {t4l[0], t4l[1]}, bl1[2] = {t4l[2], t4l[3]};
                mma_bf16(S[2 * p],     qh_[ks], bh0);
                mma_bf16(S[2 * p],     qh_[ks], bl0);
                mma_bf16(S[2 * p],     ql_[ks], bh0);
                mma_bf16(S[2 * p + 1], qh_[ks], bh1);
                mma_bf16(S[2 * p + 1], qh_[ks], bl1);
                mma_bf16(S[2 * p + 1], ql_[ks], bh1);
            }
        }
        const float SC = 0.18033688f;
#pragma unroll
        for (int i = 0; i < 8; i++)
#pragma unroll
            for (int j = 0; j < 4; j++) S[i][j] *= SC;
        if (kt == qt) {
            int rr = warp * 16 + (lane >> 2);
#pragma unroll
            for (int nt = 0; nt < 8; nt++) {
                int cc = nt * 8 + (lane & 3) * 2;
                if (cc     > rr)     S[nt][0] = -1e30f;
                if (cc + 1 > rr)     S[nt][1] = -1e30f;
                if (cc     > rr + 8) S[nt][2] = -1e30f;
                if (cc + 1 > rr + 8) S[nt][3] = -1e30f;
            }
        }
        float mx0 = -1e30f, mx1 = -1e30f;
#pragma unroll
        for (int nt = 0; nt < 8; nt++) {
            mx0 = fmaxf(mx0, fmaxf(S[nt][0], S[nt][1]));
            mx1 = fmaxf(mx1, fmaxf(S[nt][2], S[nt][3]));
        }
        mx0 = fmaxf(mx0, __shfl_xor_sync(0xffffffff, mx0, 1));
        mx0 = fmaxf(mx0, __shfl_xor_sync(0xffffffff, mx0, 2));
        mx1 = fmaxf(mx1, __shfl_xor_sync(0xffffffff, mx1, 1));
        mx1 = fmaxf(mx1, __shfl_xor_sync(0xffffffff, mx1, 2));
        float mn0 = fmaxf(m2[0], mx0), mn1 = fmaxf(m2[1], mx1);
        float al0 = ex2(m2[0] - mn0), al1 = ex2(m2[1] - mn1);
        m2[0] = mn0; m2[1] = mn1;
        float s0 = 0.f, s1 = 0.f;
#pragma unroll
        for (int nt = 0; nt < 8; nt++) {
            S[nt][0] = ex2(S[nt][0] - mn0); s0 += S[nt][0];
            S[nt][1] = ex2(S[nt][1] - mn0); s0 += S[nt][1];
            S[nt][2] = ex2(S[nt][2] - mn1); s1 += S[nt][2];
            S[nt][3] = ex2(S[nt][3] - mn1); s1 += S[nt][3];
        }
        s0 += __shfl_xor_sync(0xffffffff, s0, 1);
        s0 += __shfl_xor_sync(0xffffffff, s0, 2);
        s1 += __shfl_xor_sync(0xffffffff, s1, 1);
        s1 += __shfl_xor_sync(0xffffffff, s1, 2);
        lsum[0] = lsum[0] * al0 + s0;
        lsum[1] = lsum[1] * al1 + s1;
#pragma unroll
        for (int nt = 0; nt < 8; nt++) {
            O[nt][0] *= al0; O[nt][1] *= al0;
            O[nt][2] *= al1; O[nt][3] *= al1;
        }
        const uint32_t vb = kb_ + 16384;
#pragma unroll
        for (int ks = 0; ks < 4; ks++) {
            uint32_t pah[4], pal[4];
            pk2(S[2 * ks][0],     S[2 * ks][1],     pah[0], pal[0]);
            pk2(S[2 * ks][2],     S[2 * ks][3],     pah[1], pal[1]);
            pk2(S[2 * ks + 1][0], S[2 * ks + 1][1], pah[2], pal[2]);
            pk2(S[2 * ks + 1][2], S[2 * ks + 1][3], pah[3], pal[3]);
#pragma unroll
            for (int dg = 0; dg < 4; dg++) {
                uint32_t th[4], tl[4];
                uint32_t vd = vb + swz((ks * 16 + (lane & 15)) * 128 + dg * 32 + (lane >> 4) * 16);
                ldm4t(th, vd);
                ldm4t(tl, vd + 8192);
                uint32_t bh0[2] = {th[0], th[1]}, bh1[2] = {th[2], th[3]};
                uint32_t bl0[2] = {tl[0], tl[1]}, bl1[2] = {tl[2], tl[3]};
                mma_bf16(O[2 * dg],     pah, bh0);
                mma_bf16(O[2 * dg],     pah, bl0);
                mma_bf16(O[2 * dg],     pal, bh0);
                mma_bf16(O[2 * dg + 1], pah, bh1);
                mma_bf16(O[2 * dg + 1], pah, bl1);
                mma_bf16(O[2 * dg + 1], pal, bh1);
            }
        }
        __syncthreads();
    }

    float inv0 = 1.f / lsum[0], inv1 = 1.f / lsum[1];
    int r0 = qt * 64 + warp * 16 + (lane >> 2);
#pragma unroll
    for (int nt = 0; nt < 8; nt++) {
        int cc = nt * 8 + (lane & 3) * 2;
        size_t o0 = rowbase + (size_t)r0 * Dc + hoff + cc;
        size_t o1 = o0 + (size_t)8 * Dc;
        uint32_t h01, l01, h23, l23;
        pk2(O[nt][0] * inv0, O[nt][1] * inv0, h01, l01);
        pk2(O[nt][2] * inv1, O[nt][3] * inv1, h23, l23);
        *(uint32_t*)&ohi[o0] = h01; *(uint32_t*)&olo[o0] = l01;
        *(uint32_t*)&ohi[o1] = h23; *(uint32_t*)&olo[o1] = l23;
    }
}

// ---------------------------------------------------------------------------
// prep kernels
// ---------------------------------------------------------------------------
__global__ void wtrans_split(const float* __restrict__ W,
                             __nv_bfloat16* __restrict__ hi,
                             __nv_bfloat16* __restrict__ lo, int K, int N) {
    __shared__ float t[32][33];
    int n0 = blockIdx.x * 32, k0 = blockIdx.y * 32;
    int tx = threadIdx.x, ty = threadIdx.y;
#pragma unroll
    for (int r = 0; r < 4; r++)
        t[ty + r * 8][tx] = W[(size_t)(k0 + ty + r * 8) * N + n0 + tx];
    __syncthreads();
#pragma unroll
    for (int r = 0; r < 4; r++) {
        int a = ty + r * 8;
        float v = t[tx][a];
        size_t o = (size_t)(n0 + a) * K + k0 + tx;
        split2(v, &hi[o], &lo[o]);
    }
}

__global__ void split_kernel_h(const float* __restrict__ in,
                               __half* __restrict__ hi,
                               __half* __restrict__ lo, int n) {
    int i = blockIdx.x * 256 + threadIdx.x;
    if (i < n) split2h(in[i], &hi[i], &lo[i]);
}

__global__ void pack_bqkv(const float* __restrict__ bq, const float* __restrict__ bk,
                          const float* __restrict__ bv, float* __restrict__ dst) {
    int i = blockIdx.x * 256 + threadIdx.x;
    if (i < Lc * 3 * Dc) {
        int l = i / (3 * Dc), c = i % (3 * Dc);
        const float* src = c < Dc ? bq : (c < 2 * Dc ? bk : bv);
        dst[i] = src[l * Dc + (c & (Dc - 1))];
    }
}

__global__ void embed_kernel(const int* __restrict__ ids,
                             const float* __restrict__ tok,
                             const float* __restrict__ pos,
                             float* __restrict__ x) {
    int row = blockIdx.x;
    int s = row % Sc;
    int id = ids[row];
    const float* tr = tok + (size_t)id * Dc;
    const float* pr = pos + (size_t)s * Dc;
    float* xr = x + (size_t)row * Dc;
    for (int d = threadIdx.x; d < Dc; d += blockDim.x) xr[d] = tr[d] + pr[d];
}

template<bool HOUT>
__global__ void ln_kernel(const float* __restrict__ x,
                          const float* __restrict__ w, const float* __restrict__ b,
                          void* __restrict__ yhi, void* __restrict__ ylo) {
    int row = blockIdx.x;
    const float* xr = x + (size_t)row * Dc;
    __shared__ float r1[256], r2[256];
    float s = 0.f, s2 = 0.f;
    for (int d = threadIdx.x; d < Dc; d += 256) {
        float v = xr[d];
        s += v; s2 += v * v;
    }
    r1[threadIdx.x] = s; r2[threadIdx.x] = s2;
    __syncthreads();
    for (int st = 128; st > 0; st >>= 1) {
        if (threadIdx.x < st) {
            r1[threadIdx.x] += r1[threadIdx.x + st];
            r2[threadIdx.x] += r2[threadIdx.x + st];
        }
        __syncthreads();
    }
    float mean = r1[0] * (1.0f / Dc);
    float var = r2[0] * (1.0f / Dc) - mean * mean;
    float rstd = rsqrtf(var + 1e-5f);
    for (int d = threadIdx.x; d < Dc; d += 256) {
        float v = (xr[d] - mean) * rstd * w[d] + b[d];
        size_t o = (size_t)row * Dc + d;
        if (HOUT) split2h(v, (__half*)yhi + o, (__half*)ylo + o);
        else      split2(v, (__nv_bfloat16*)yhi + o, (__nv_bfloat16*)ylo + o);
    }
}

// ---------------------------------------------------------------------------
// launcher
// ---------------------------------------------------------------------------
extern "C" void kernel_launch(void* const* d_in, const int* in_sizes, int n_in,
                              void* d_out, int out_size) {
    const int*   ids   = (const int*)d_in[0];
    const float* tok   = (const float*)d_in[1];
    const float* pos   = (const float*)d_in[2];
    const float* Wq    = (const float*)d_in[3];
    const float* bq    = (const float*)d_in[4];
    const float* Wk    = (const float*)d_in[5];
    const float* bk    = (const float*)d_in[6];
    const float* Wv    = (const float*)d_in[7];
    const float* bv    = (const float*)d_in[8];
    const float* Wo    = (const float*)d_in[9];
    const float* bo    = (const float*)d_in[10];
    const float* ln1w  = (const float*)d_in[11];
    const float* ln1b  = (const float*)d_in[12];
    const float* ln2w  = (const float*)d_in[13];
    const float* ln2b  = (const float*)d_in[14];
    const float* Wup   = (const float*)d_in[15];
    const float* bup   = (const float*)d_in[16];
    const float* Wdown = (const float*)d_in[17];
    const float* bdown = (const float*)d_in[18];
    const float* fnw   = (const float*)d_in[19];
    const float* fnb   = (const float*)d_in[20];
    float* out = (float*)d_out;

    float *x, *bqkv;
    __nv_bfloat16 *qkv, *ahi, *alo, *bhi, *blo, *whi, *wlo;
    __half *thi, *tlo;
    cudaGetSymbolAddress((void**)&x, g_x);
    cudaGetSymbolAddress((void**)&qkv, g_qkv);
    cudaGetSymbolAddress((void**)&ahi, g_ahi);
    cudaGetSymbolAddress((void**)&alo, g_alo);
    cudaGetSymbolAddress((void**)&bhi, g_bhi);
    cudaGetSymbolAddress((void**)&blo, g_blo);
    cudaGetSymbolAddress((void**)&whi, g_whi);
    cudaGetSymbolAddress((void**)&wlo, g_wlo);
    cudaGetSymbolAddress((void**)&thi, g_thi);
    cudaGetSymbolAddress((void**)&tlo, g_tlo);
    cudaGetSymbolAddress((void**)&bqkv, g_bqkv);
    __nv_bfloat16 *qhi = qkv,              *qlo = qkv + (size_t)MR * Dc;
    __nv_bfloat16 *khi = qkv + 2ull*MR*Dc, *klo = qkv + 3ull*MR*Dc;
    __nv_bfloat16 *vhi = qkv + 4ull*MR*Dc, *vlo = qkv + 5ull*MR*Dc;

    cudaFuncSetAttribute(gemm_t<false,false>, cudaFuncAttributeMaxDynamicSharedMemorySize, GEMM_SMEM);
    cudaFuncSetAttribute(gemm_t<false,true>,  cudaFuncAttributeMaxDynamicSharedMemorySize, GEMM_SMEM);
    cudaFuncSetAttribute(gemm_t<true,false>,  cudaFuncAttributeMaxDynamicSharedMemorySize, GEMM_SMEM);
    cudaFuncSetAttribute(attn_mma, cudaFuncAttributeMaxDynamicSharedMemorySize, ATT_SMEM);

    const dim3 tb32(32, 8);
    const dim3 gDD(Dc / 32, Dc / 32);
    const dim3 gDF(Fc / 32, Dc / 32);
    const dim3 gFD(Dc / 32, Fc / 32);

    for (int l = 0; l < Lc; l++) {
        size_t lb = (size_t)l * WPL;
        wtrans_split<<<gDD, tb32>>>(Wq + (size_t)l * Dc * Dc, whi + lb,           wlo + lb,           Dc, Dc);
        wtrans_split<<<gDD, tb32>>>(Wk + (size_t)l * Dc * Dc, whi + lb + 1048576, wlo + lb + 1048576, Dc, Dc);
        wtrans_split<<<gDD, tb32>>>(Wv + (size_t)l * Dc * Dc, whi + lb + 2097152, wlo + lb + 2097152, Dc, Dc);
        wtrans_split<<<gDD, tb32>>>(Wo + (size_t)l * Dc * Dc, whi + lb + 3145728, wlo + lb + 3145728, Dc, Dc);
        wtrans_split<<<gDF, tb32>>>(Wup + (size_t)l * Dc * Fc, whi + lb + 4194304, wlo + lb + 4194304, Dc, Fc);
        wtrans_split<<<gFD, tb32>>>(Wdown + (size_t)l * Fc * Dc, whi + lb + 8388608, wlo + lb + 8388608, Fc, Dc);
    }
    split_kernel_h<<<(Vc * Dc + 255) / 256, 256>>>(tok, thi, tlo, Vc * Dc);
    pack_bqkv<<<(Lc * 3 * Dc + 255) / 256, 256>>>(bq, bk, bv, bqkv);

    embed_kernel<<<MR, 256>>>(ids, tok, pos, x);

    const dim3 gmQKV(3 * Dc / 128, MR / 128);   // 24 x 32
    const dim3 gmD(Dc / 128, MR / 128);         // 8 x 32
    const dim3 gmF(Fc / 128, MR / 128);         // 32 x 32
    const dim3 gmV(Vc / 128, MR / 128);         // 250 x 32
    const dim3 gA(Sc / 64, Hc, Bc);

    for (int l = 0; l < Lc; l++) {
        size_t lb = (size_t)l * WPL;
        ln_kernel<false><<<MR, 256>>>(x, ln1w + l * Dc, ln1b + l * Dc, ahi, alo);
        gemm_t<false,false><<<gmQKV, 256, GEMM_SMEM>>>(
            ahi, alo, whi + lb, wlo + lb, bqkv + l * 3 * Dc, nullptr,
            nullptr, qkv, nullptr, MR, 3 * Dc, Dc, Dc);
        attn_mma<<<gA, 128, ATT_SMEM>>>(qhi, qlo, khi, klo, vhi, vlo, ahi, alo);
        gemm_t<false,false><<<gmD, 256, GEMM_SMEM>>>(
            ahi, alo, whi + lb + 3145728, wlo + lb + 3145728, bo + l * Dc, x,
            x, nullptr, nullptr, MR, Dc, Dc, 0);
        ln_kernel<false><<<MR, 256>>>(x, ln2w + l * Dc, ln2b + l * Dc, ahi, alo);
        gemm_t<false,true><<<gmF, 256, GEMM_SMEM>>>(
            ahi, alo, whi + lb + 4194304, wlo + lb + 4194304, bup + l * Fc, nullptr,
            nullptr, bhi, blo, MR, Fc, Dc, 0);
        gemm_t<false,false><<<gmD, 256, GEMM_SMEM>>>(
            bhi, blo, whi + lb + 8388608, wlo + lb + 8388608, bdown + l * Dc, x,
            x, nullptr, nullptr, MR, Dc, Fc, 0);
    }

    ln_kernel<true><<<MR, 256>>>(x, fnw, fnb, ahi, alo);
    gemm_t<true,false><<<gmV, 256, GEMM_SMEM>>>(
        (const __nv_bfloat16*)ahi, (const __nv_bfloat16*)alo,
        (const __nv_bfloat16*)thi, (const __nv_bfloat16*)tlo,
        nullptr, nullptr, out, nullptr, nullptr, MR, Vc, Dc, 0);
}

// round 8
// speedup vs baseline: 7.7660x; 1.1206x over previous
#include <cuda_runtime.h>
#include <cuda_bf16.h>
#include <cuda_fp16.h>
#include <math.h>
#include <stdint.h>

#define Bc 2
#define Sc 2048
#define Dc 1024
#define Hc 16
#define Lc 6
#define Fc 4096
#define Vc 32000
#define DHc 64
#define MR (Bc*Sc)   // 4096 rows

// ---------------------------------------------------------------------------
// scratch (static device globals; no allocations allowed)
// ---------------------------------------------------------------------------
__device__ float g_x[MR*Dc];
__device__ __nv_bfloat16 g_qkv[6*MR*Dc];   // qhi,qlo,khi,klo,vhi,vlo (bf16)
__device__ __nv_bfloat16 g_ahi[MR*Fc];     // activation hi (bf16 or fp16 bits)
__device__ __nv_bfloat16 g_alo[MR*Fc];
__device__ __nv_bfloat16 g_bhi[MR*Fc];     // GELU(ffn-up) output hi (fp16 bits)
__device__ __nv_bfloat16 g_blo[MR*Fc];
#define WPL 12582912   // elems per layer (4*D*D + D*F + F*D)
__device__ __nv_bfloat16 g_whi[Lc*WPL];    // attn weights bf16; FFN weights fp16 bits
__device__ __nv_bfloat16 g_wlo[Lc*WPL];
__device__ __half g_thi[Vc*Dc];
__device__ __half g_tlo[Vc*Dc];
__device__ float g_bqkv[Lc*3*Dc];

// ---------------------------------------------------------------------------
// helpers
// ---------------------------------------------------------------------------
__device__ __forceinline__ uint32_t s2u(const void* ptr) {
    uint32_t a;
    asm("{ .reg .u64 t; cvta.to.shared.u64 t, %1; cvt.u32.u64 %0, t; }"
        : "=r"(a) : "l"(ptr));
    return a;
}
__device__ __forceinline__ void cpasync16(uint32_t dst, const void* src) {
    asm volatile("cp.async.cg.shared.global [%0], [%1], 16;" :: "r"(dst), "l"(src));
}
__device__ __forceinline__ void ldm4(uint32_t* r, uint32_t addr) {
    asm volatile("ldmatrix.sync.aligned.m8n8.x4.shared.b16 {%0,%1,%2,%3}, [%4];"
                 : "=r"(r[0]), "=r"(r[1]), "=r"(r[2]), "=r"(r[3]) : "r"(addr));
}
__device__ __forceinline__ void ldm4t(uint32_t* r, uint32_t addr) {
    asm volatile("ldmatrix.sync.aligned.m8n8.x4.trans.shared.b16 {%0,%1,%2,%3}, [%4];"
                 : "=r"(r[0]), "=r"(r[1]), "=r"(r[2]), "=r"(r[3]) : "r"(addr));
}
template<bool H>
__device__ __forceinline__ void mma16(float* d, const uint32_t* a, const uint32_t* b) {
    if (H)
        asm volatile(
            "mma.sync.aligned.m16n8k16.row.col.f32.f16.f16.f32 "
            "{%0,%1,%2,%3}, {%4,%5,%6,%7}, {%8,%9}, {%0,%1,%2,%3};"
            : "+f"(d[0]), "+f"(d[1]), "+f"(d[2]), "+f"(d[3])
            : "r"(a[0]), "r"(a[1]), "r"(a[2]), "r"(a[3]), "r"(b[0]), "r"(b[1]));
    else
        asm volatile(
            "mma.sync.aligned.m16n8k16.row.col.f32.bf16.bf16.f32 "
            "{%0,%1,%2,%3}, {%4,%5,%6,%7}, {%8,%9}, {%0,%1,%2,%3};"
            : "+f"(d[0]), "+f"(d[1]), "+f"(d[2]), "+f"(d[3])
            : "r"(a[0]), "r"(a[1]), "r"(a[2]), "r"(a[3]), "r"(b[0]), "r"(b[1]));
}
__device__ __forceinline__ void mma_bf16(float* d, const uint32_t* a, const uint32_t* b) {
    mma16<false>(d, a, b);
}
__device__ __forceinline__ void split2(float v, __nv_bfloat16* h, __nv_bfloat16* l) {
    __nv_bfloat16 hh = __float2bfloat16(v);
    *h = hh;
    *l = __float2bfloat16(v - __bfloat162float(hh));
}
__device__ __forceinline__ void split2h(float v, __half* h, __half* l) {
    __half hh = __float2half(v);
    *h = hh;
    *l = __float2half(v - __half2float(hh));
}
__device__ __forceinline__ void pk2(float x, float y, uint32_t& hi, uint32_t& lo) {
    __nv_bfloat16 xh = __float2bfloat16(x), yh = __float2bfloat16(y);
    __nv_bfloat16 xl = __float2bfloat16(x - __bfloat162float(xh));
    __nv_bfloat16 yl = __float2bfloat16(y - __bfloat162float(yh));
    hi = ((uint32_t)__bfloat16_as_ushort(yh) << 16) | __bfloat16_as_ushort(xh);
    lo = ((uint32_t)__bfloat16_as_ushort(yl) << 16) | __bfloat16_as_ushort(xl);
}
__device__ __forceinline__ void pk2h(float x, float y, uint32_t& hi, uint32_t& lo) {
    __half xh = __float2half(x), yh = __float2half(y);
    __half xl = __float2half(x - __half2float(xh));
    __half yl = __float2half(y - __half2float(yh));
    hi = ((uint32_t)__half_as_ushort(yh) << 16) | __half_as_ushort(xh);
    lo = ((uint32_t)__half_as_ushort(yl) << 16) | __half_as_ushort(xl);
}
// fast 2^y on the FMA pipe (y <= 0), err ~2e-6
__device__ __forceinline__ float ex2(float y) {
    y = fmaxf(y, -126.f);
    float fn = y + 12582912.f;
    int n = __float_as_int(fn) - 0x4B400000;
    float r = y - (fn - 12582912.f);
    float p = 1.3333558e-3f;
    p = fmaf(p, r, 9.6181291e-3f);
    p = fmaf(p, r, 5.5504109e-2f);
    p = fmaf(p, r, 2.4022651e-1f);
    p = fmaf(p, r, 6.9314718e-1f);
    p = fmaf(p, r, 1.0f);
    return p * __int_as_float((n + 127) << 23);
}
__device__ __forceinline__ uint32_t swz(uint32_t off) {
    return off ^ ((off >> 3) & 0x70);
}
__device__ __forceinline__ float gelu_f(float v) {
    return 0.5f * v * (1.0f + erff(v * 0.70710678118654752f));
}

// ---------------------------------------------------------------------------
// split-precision MMA GEMM, K-chunk 64, SW128 smem, 3-stage pipeline
// (single __syncthreads per chunk).
// bf16 (3-term): C = (Ah+Al)@(Bh+Bl)^T ; fp16 (2-term): C = (Ah+Al)@Bh^T
// ---------------------------------------------------------------------------
#define T16 16384                       // one 128x64 16-bit tile (128B rows)
#define SMEM_BF (3*4*T16)               // 196608
#define SMEM_FP (3*3*T16)               // 147456

template<int TILES>
__device__ __forceinline__ void load_stage64(
    const __nv_bfloat16* s0, const __nv_bfloat16* s1,
    const __nv_bfloat16* s2, const __nv_bfloat16* s3,
    int K, int k0, uint32_t dbase, int tid) {
    const __nv_bfloat16* srcs[4] = {s0, s1, s2, s3};
#pragma unroll
    for (int t = 0; t < TILES; t++) {
#pragma unroll
        for (int u = 0; u < 4; u++) {
            int id = u * 256 + tid;
            int row = id >> 3, c = id & 7;
            cpasync16(dbase + t * T16 + swz(row * 128 + c * 16),
                      srcs[t] + (size_t)row * K + k0 + c * 8);
        }
    }
}

template<bool FP16W, bool GELU, bool OUT16>
__global__ __launch_bounds__(256, 1)
void gemm_t(const __nv_bfloat16* __restrict__ Ahi, const __nv_bfloat16* __restrict__ Alo,
            const __nv_bfloat16* __restrict__ Bhi, const __nv_bfloat16* __restrict__ Blo,
            const float* __restrict__ bias, const float* __restrict__ res,
            float* __restrict__ C, __nv_bfloat16* __restrict__ Chi,
            __nv_bfloat16* __restrict__ Clo, int M, int N, int K, int oseg) {
    constexpr int TILES = FP16W ? 3 : 4;
    constexpr int STAGE = TILES * T16;
    extern __shared__ char smem[];
    const uint32_t sbase = s2u(smem);
    const int tid = threadIdx.x;
    const int warp = tid >> 5, lane = tid & 31;
    const int bm = blockIdx.y * 128, bn = blockIdx.x * 128;
    const int wm = (warp >> 2) * 64, wn = (warp & 3) * 32;

    float acc[4][4][4];
#pragma unroll
    for (int i = 0; i < 4; i++)
#pragma unroll
        for (int j = 0; j < 4; j++)
#pragma unroll
            for (int q = 0; q < 4; q++) acc[i][j][q] = 0.f;

    const __nv_bfloat16* A0 = Ahi + (size_t)bm * K;
    const __nv_bfloat16* A1 = Alo + (size_t)bm * K;
    const __nv_bfloat16* B0 = Bhi + (size_t)bn * K;
    const __nv_bfloat16* B1 = FP16W ? nullptr : Blo + (size_t)bn * K;

    const int nch = K >> 6;
    // prologue: chunks 0 and 1 into stages 0, 1
    load_stage64<TILES>(A0, A1, B0, B1, K, 0, sbase, tid);
    asm volatile("cp.async.commit_group;" ::: "memory");
    if (nch > 1) {
        load_stage64<TILES>(A0, A1, B0, B1, K, 64, sbase + STAGE, tid);
        asm volatile("cp.async.commit_group;" ::: "memory");
    }

    const int g = lane >> 3, r = lane & 7;
    const int a_row = r + (g & 1) * 8;
    const int a_cb  = (g >> 1) * 16;
    const int b_row = (g >> 1) * 8 + r;
    const int b_cb  = (g & 1) * 16;

    for (int c = 0; c < nch; c++) {
        if (c == nch - 1) asm volatile("cp.async.wait_group 0;" ::: "memory");
        else              asm volatile("cp.async.wait_group 1;" ::: "memory");
        __syncthreads();   // single barrier per chunk: data-ready + stage-free

        uint32_t base = sbase + (c % 3) * STAGE;
#pragma unroll
        for (int ks = 0; ks < 4; ks++) {
            const int kb = ks * 32;
            uint32_t ah[4][4], al[4][4], bh[4][2], bl[4][2];
#pragma unroll
            for (int mt = 0; mt < 4; mt++) {
                uint32_t ad = base + swz((wm + mt * 16 + a_row) * 128 + kb + a_cb);
                ldm4(ah[mt], ad);
                ldm4(al[mt], ad + T16);
            }
#pragma unroll
            for (int p = 0; p < 2; p++) {
                uint32_t bd = base + 2 * T16 + swz((wn + p * 16 + b_row) * 128 + kb + b_cb);
                uint32_t t4[4];
                ldm4(t4, bd);
                bh[2 * p][0] = t4[0]; bh[2 * p][1] = t4[1];
                bh[2 * p + 1][0] = t4[2]; bh[2 * p + 1][1] = t4[3];
                if (!FP16W) {
                    ldm4(t4, bd + T16);
                    bl[2 * p][0] = t4[0]; bl[2 * p][1] = t4[1];
                    bl[2 * p + 1][0] = t4[2]; bl[2 * p + 1][1] = t4[3];
                }
            }
#pragma unroll
            for (int mt = 0; mt < 4; mt++)
#pragma unroll
                for (int nt = 0; nt < 4; nt++) {
                    mma16<FP16W>(acc[mt][nt], ah[mt], bh[nt]);
                    mma16<FP16W>(acc[mt][nt], al[mt], bh[nt]);
                    if (!FP16W) mma16<false>(acc[mt][nt], ah[mt], bl[nt]);
                }
        }
        // prefetch chunk c+2 into stage (c+2)%3 (held chunk c-1, fully consumed
        // before this iteration's barrier)
        if (c + 2 < nch) {
            load_stage64<TILES>(A0, A1, B0, B1, K, (c + 2) * 64,
                                sbase + ((c + 2) % 3) * STAGE, tid);
            asm volatile("cp.async.commit_group;" ::: "memory");
        }
    }

    // ---- epilogue
    __nv_bfloat16 *chi = Chi, *clo = Clo;
    int ost = N, bnl = bn;
    if (oseg) {
        int t = bn / oseg;
        bnl = bn - t * oseg;
        ost = oseg;
        chi = Chi + (size_t)(2 * t) * M * oseg;
        clo = Chi + (size_t)(2 * t + 1) * M * oseg;
    }
#pragma unroll
    for (int mt = 0; mt < 4; mt++) {
        int r0 = bm + wm + mt * 16 + (lane >> 2);
#pragma unroll
        for (int nt = 0; nt < 4; nt++) {
            int ccg = bn + wn + nt * 8 + (lane & 3) * 2;   // for bias
            int ccl = bnl + wn + nt * 8 + (lane & 3) * 2;  // for store
            float b0 = bias ? bias[ccg] : 0.f, b1 = bias ? bias[ccg + 1] : 0.f;
            float v0 = acc[mt][nt][0] + b0, v1 = acc[mt][nt][1] + b1;
            float v2 = acc[mt][nt][2] + b0, v3 = acc[mt][nt][3] + b1;
            if (GELU) {
                v0 = gelu_f(v0); v1 = gelu_f(v1);
                v2 = gelu_f(v2); v3 = gelu_f(v3);
            }
            if (chi) {
                uint32_t h01, l01, h23, l23;
                if (OUT16) { pk2h(v0, v1, h01, l01); pk2h(v2, v3, h23, l23); }
                else       { pk2(v0, v1, h01, l01);  pk2(v2, v3, h23, l23); }
                *(uint32_t*)&chi[(size_t)r0 * ost + ccl] = h01;
                *(uint32_t*)&clo[(size_t)r0 * ost + ccl] = l01;
                *(uint32_t*)&chi[(size_t)(r0 + 8) * ost + ccl] = h23;
                *(uint32_t*)&clo[(size_t)(r0 + 8) * ost + ccl] = l23;
            } else {
                if (res) {
                    v0 += res[(size_t)r0 * N + ccg];       v1 += res[(size_t)r0 * N + ccg + 1];
                    v2 += res[(size_t)(r0 + 8) * N + ccg]; v3 += res[(size_t)(r0 + 8) * N + ccg + 1];
                }
                *(float2*)&C[(size_t)r0 * N + ccg] = make_float2(v0, v1);
                *(float2*)&C[(size_t)(r0 + 8) * N + ccg] = make_float2(v2, v3);
            }
        }
    }
}

// ---------------------------------------------------------------------------
// MMA flash attention: block = (qt 64 rows, h, b), 4 warps, 64-col k-tiles.
// ---------------------------------------------------------------------------
#define ATT_STAGE 32768
#define ATT_SMEM (2*ATT_STAGE)

__global__ __launch_bounds__(128, 2)
void attn_mma(const __nv_bfloat16* __restrict__ qhi, const __nv_bfloat16* __restrict__ qlo,
              const __nv_bfloat16* __restrict__ khi, const __nv_bfloat16* __restrict__ klo,
              const __nv_bfloat16* __restrict__ vhi, const __nv_bfloat16* __restrict__ vlo,
              __nv_bfloat16* __restrict__ ohi, __nv_bfloat16* __restrict__ olo) {
    extern __shared__ char sm[];
    const uint32_t sb = s2u(sm);
    const int qt = blockIdx.x, h = blockIdx.y, b = blockIdx.z;
    const int tid = threadIdx.x, warp = tid >> 5, lane = tid & 31;
    const int g = lane >> 3, r = lane & 7;
    const int a_row = r + (g & 1) * 8, a_cb = (g >> 1) * 16;
    const int b_row = (g >> 1) * 8 + r, b_cb = (g & 1) * 16;
    const size_t hoff = (size_t)h * 64;
    const size_t rowbase = (size_t)(b * Sc) * Dc;

#pragma unroll
    for (int t = 0; t < 2; t++) {
        const __nv_bfloat16* src = (t ? qlo : qhi) + rowbase + (size_t)(qt * 64) * Dc + hoff;
#pragma unroll
        for (int u = 0; u < 4; u++) {
            int id = u * 128 + tid;
            int row = id >> 3, c16 = id & 7;
            uint4 val = *(const uint4*)((const char*)(src + (size_t)row * Dc) + c16 * 16);
            *(uint4*)(sm + t * 8192 + swz(row * 128 + c16 * 16)) = val;
        }
    }
    __syncthreads();
    uint32_t qh_[4][4], ql_[4][4];
#pragma unroll
    for (int ks = 0; ks < 4; ks++) {
        uint32_t ad = sb + swz((warp * 16 + a_row) * 128 + ks * 32 + a_cb);
        ldm4(qh_[ks], ad);
        ldm4(ql_[ks], ad + 8192);
    }
    __syncthreads();

    float O[8][4];
#pragma unroll
    for (int i = 0; i < 8; i++)
#pragma unroll
        for (int j = 0; j < 4; j++) O[i][j] = 0.f;
    float m2[2] = {-1e30f, -1e30f};
    float lsum[2] = {0.f, 0.f};

    const __nv_bfloat16* srcs[4] = {khi, klo, vhi, vlo};
#define LOAD_KV(S, KT) do { \
        size_t base_ = rowbase + (size_t)((KT) * 64) * Dc + hoff; \
        uint32_t dst_ = sb + (S) * ATT_STAGE; \
        _Pragma("unroll") \
        for (int t = 0; t < 4; t++) { \
            _Pragma("unroll") \
            for (int u = 0; u < 4; u++) { \
                int id = u * 128 + tid; \
                int row = id >> 3, c16 = id & 7; \
                cpasync16(dst_ + t * 8192 + swz(row * 128 + c16 * 16), \
                          (const char*)(srcs[t] + base_ + (size_t)row * Dc) + c16 * 16); \
            } \
        } \
        asm volatile("cp.async.commit_group;" ::: "memory"); \
    } while (0)

    LOAD_KV(0, 0);

    for (int kt = 0; kt <= qt; kt++) {
        if (kt < qt) {
            LOAD_KV((kt + 1) & 1, kt + 1);
            asm volatile("cp.async.wait_group 1;" ::: "memory");
        } else {
            asm volatile("cp.async.wait_group 0;" ::: "memory");
        }
        __syncthreads();
        const uint32_t kb_ = sb + (kt & 1) * ATT_STAGE;

        float S[8][4];
#pragma unroll
        for (int i = 0; i < 8; i++)
#pragma unroll
            for (int j = 0; j < 4; j++) S[i][j] = 0.f;
#pragma unroll
        for (int ks = 0; ks < 4; ks++) {
#pragma unroll
            for (int p = 0; p < 4; p++) {
                uint32_t t4h[4], t4l[4];
                uint32_t bd = kb_ + swz((p * 16 + b_row) * 128 + ks * 32 + b_cb);
                ldm4(t4h, bd);
                ldm4(t4l, bd + 8192);
                uint32_t bh0[2] = {t4h[0], t4h[1]}, bh1[2] = {t4h[2], t4h[3]};
                uint32_t bl0[2] = {t4l[0], t4l[1]}, bl1[2] = {t4l[2], t4l[3]};
                mma_bf16(S[2 * p],     qh_[ks], bh0);
                mma_bf16(S[2 * p],     qh_[ks], bl0);
                mma_bf16(S[2 * p],     ql_[ks], bh0);
                mma_bf16(S[2 * p + 1], qh_[ks], bh1);
                mma_bf16(S[2 * p + 1], qh_[ks], bl1);
                mma_bf16(S[2 * p + 1], ql_[ks], bh1);
            }
        }
        const float SC = 0.18033688f;
#pragma unroll
        for (int i = 0; i < 8; i++)
#pragma unroll
            for (int j = 0; j < 4; j++) S[i][j] *= SC;
        if (kt == qt) {
            int rr = warp * 16 + (lane >> 2);
#pragma unroll
            for (int nt = 0; nt < 8; nt++) {
                int cc = nt * 8 + (lane & 3) * 2;
                if (cc     > rr)     S[nt][0] = -1e30f;
                if (cc + 1 > rr)     S[nt][1] = -1e30f;
                if (cc     > rr + 8) S[nt][2] = -1e30f;
                if (cc + 1 > rr + 8) S[nt][3] = -1e30f;
            }
        }
        float mx0 = -1e30f, mx1 = -1e30f;
#pragma unroll
        for (int nt = 0; nt < 8; nt++) {
            mx0 = fmaxf(mx0, fmaxf(S[nt][0], S[nt][1]));
            mx1 = fmaxf(mx1, fmaxf(S[nt][2], S[nt][3]));
        }
        mx0 = fmaxf(mx0, __shfl_xor_sync(0xffffffff, mx0, 1));
        mx0 = fmaxf(mx0, __shfl_xor_sync(0xffffffff, mx0, 2));
        mx1 = fmaxf(mx1, __shfl_xor_sync(0xffffffff, mx1, 1));
        mx1 = fmaxf(mx1, __shfl_xor_sync(0xffffffff, mx1, 2));
        float mn0 = fmaxf(m2[0], mx0), mn1 = fmaxf(m2[1], mx1);
        float al0 = ex2(m2[0] - mn0), al1 = ex2(m2[1] - mn1);
        m2[0] = mn0; m2[1] = mn1;
        float s0 = 0.f, s1 = 0.f;
#pragma unroll
        for (int nt = 0; nt < 8; nt++) {
            S[nt][0] = ex2(S[nt][0] - mn0); s0 += S[nt][0];
            S[nt][1] = ex2(S[nt][1] - mn0); s0 += S[nt][1];
            S[nt][2] = ex2(S[nt][2] - mn1); s1 += S[nt][2];
            S[nt][3] = ex2(S[nt][3] - mn1); s1 += S[nt][3];
        }
        s0 += __shfl_xor_sync(0xffffffff, s0, 1);
        s0 += __shfl_xor_sync(0xffffffff, s0, 2);
        s1 += __shfl_xor_sync(0xffffffff, s1, 1);
        s1 += __shfl_xor_sync(0xffffffff, s1, 2);
        lsum[0] = lsum[0] * al0 + s0;
        lsum[1] = lsum[1] * al1 + s1;
#pragma unroll
        for (int nt = 0; nt < 8; nt++) {
            O[nt][0] *= al0; O[nt][1] *= al0;
            O[nt][2] *= al1; O[nt][3] *= al1;
        }
        const uint32_t vb = kb_ + 16384;
#pragma unroll
        for (int ks = 0; ks < 4; ks++) {
            uint32_t pah[4], pal[4];
            pk2(S[2 * ks][0],     S[2 * ks][1],     pah[0], pal[0]);
            pk2(S[2 * ks][2],     S[2 * ks][3],     pah[1], pal[1]);
            pk2(S[2 * ks + 1][0], S[2 * ks + 1][1], pah[2], pal[2]);
            pk2(S[2 * ks + 1][2], S[2 * ks + 1][3], pah[3], pal[3]);
#pragma unroll
            for (int dg = 0; dg < 4; dg++) {
                uint32_t th[4], tl[4];
                uint32_t vd = vb + swz((ks * 16 + (lane & 15)) * 128 + dg * 32 + (lane >> 4) * 16);
                ldm4t(th, vd);
                ldm4t(tl, vd + 8192);
                uint32_t bh0[2] = {th[0], th[1]}, bh1[2] = {th[2], th[3]};
                uint32_t bl0[2] = {tl[0], tl[1]}, bl1[2] = {tl[2], tl[3]};
                mma_bf16(O[2 * dg],     pah, bh0);
                mma_bf16(O[2 * dg],     pah, bl0);
                mma_bf16(O[2 * dg],     pal, bh0);
                mma_bf16(O[2 * dg + 1], pah, bh1);
                mma_bf16(O[2 * dg + 1], pah, bl1);
                mma_bf16(O[2 * dg + 1], pal, bh1);
            }
        }
        __syncthreads();
    }

    float inv0 = 1.f / lsum[0], inv1 = 1.f / lsum[1];
    int r0 = qt * 64 + warp * 16 + (lane >> 2);
#pragma unroll
    for (int nt = 0; nt < 8; nt++) {
        int cc = nt * 8 + (lane & 3) * 2;
        size_t o0 = rowbase + (size_t)r0 * Dc + hoff + cc;
        size_t o1 = o0 + (size_t)8 * Dc;
        uint32_t h01, l01, h23, l23;
        pk2(O[nt][0] * inv0, O[nt][1] * inv0, h01, l01);
        pk2(O[nt][2] * inv1, O[nt][3] * inv1, h23, l23);
        *(uint32_t*)&ohi[o0] = h01; *(uint32_t*)&olo[o0] = l01;
        *(uint32_t*)&ohi[o1] = h23; *(uint32_t*)&olo[o1] = l23;
    }
}

// ---------------------------------------------------------------------------
// prep kernels
// ---------------------------------------------------------------------------
template<bool H>
__global__ void wtrans_split(const float* __restrict__ W,
                             void* __restrict__ hi_, void* __restrict__ lo_,
                             int K, int N) {
    __shared__ float t[32][33];
    int n0 = blockIdx.x * 32, k0 = blockIdx.y * 32;
    int tx = threadIdx.x, ty = threadIdx.y;
#pragma unroll
    for (int r = 0; r < 4; r++)
        t[ty + r * 8][tx] = W[(size_t)(k0 + ty + r * 8) * N + n0 + tx];
    __syncthreads();
#pragma unroll
    for (int r = 0; r < 4; r++) {
        int a = ty + r * 8;
        float v = t[tx][a];
        size_t o = (size_t)(n0 + a) * K + k0 + tx;
        if (H) split2h(v, (__half*)hi_ + o, (__half*)lo_ + o);
        else   split2(v, (__nv_bfloat16*)hi_ + o, (__nv_bfloat16*)lo_ + o);
    }
}

__global__ void split_kernel_h(const float* __restrict__ in,
                               __half* __restrict__ hi,
                               __half* __restrict__ lo, int n) {
    int i = blockIdx.x * 256 + threadIdx.x;
    if (i < n) split2h(in[i], &hi[i], &lo[i]);
}

__global__ void pack_bqkv(const float* __restrict__ bq, const float* __restrict__ bk,
                          const float* __restrict__ bv, float* __restrict__ dst) {
    int i = blockIdx.x * 256 + threadIdx.x;
    if (i < Lc * 3 * Dc) {
        int l = i / (3 * Dc), c = i % (3 * Dc);
        const float* src = c < Dc ? bq : (c < 2 * Dc ? bk : bv);
        dst[i] = src[l * Dc + (c & (Dc - 1))];
    }
}

__global__ void embed_kernel(const int* __restrict__ ids,
                             const float* __restrict__ tok,
                             const float* __restrict__ pos,
                             float* __restrict__ x) {
    int row = blockIdx.x;
    int s = row % Sc;
    int id = ids[row];
    const float* tr = tok + (size_t)id * Dc;
    const float* pr = pos + (size_t)s * Dc;
    float* xr = x + (size_t)row * Dc;
    for (int d = threadIdx.x; d < Dc; d += blockDim.x) xr[d] = tr[d] + pr[d];
}

template<bool HOUT>
__global__ void ln_kernel(const float* __restrict__ x,
                          const float* __restrict__ w, const float* __restrict__ b,
                          void* __restrict__ yhi, void* __restrict__ ylo) {
    int row = blockIdx.x;
    const float* xr = x + (size_t)row * Dc;
    __shared__ float r1[256], r2[256];
    float s = 0.f, s2 = 0.f;
    for (int d = threadIdx.x; d < Dc; d += 256) {
        float v = xr[d];
        s += v; s2 += v * v;
    }
    r1[threadIdx.x] = s; r2[threadIdx.x] = s2;
    __syncthreads();
    for (int st = 128; st > 0; st >>= 1) {
        if (threadIdx.x < st) {
            r1[threadIdx.x] += r1[threadIdx.x + st];
            r2[threadIdx.x] += r2[threadIdx.x + st];
        }
        __syncthreads();
    }
    float mean = r1[0] * (1.0f / Dc);
    float var = r2[0] * (1.0f / Dc) - mean * mean;
    float rstd = rsqrtf(var + 1e-5f);
    for (int d = threadIdx.x; d < Dc; d += 256) {
        float v = (xr[d] - mean) * rstd * w[d] + b[d];
        size_t o = (size_t)row * Dc + d;
        if (HOUT) split2h(v, (__half*)yhi + o, (__half*)ylo + o);
        else      split2(v, (__nv_bfloat16*)yhi + o, (__nv_bfloat16*)ylo + o);
    }
}

// ---------------------------------------------------------------------------
// launcher
// ---------------------------------------------------------------------------
extern "C" void kernel_launch(void* const* d_in, const int* in_sizes, int n_in,
                              void* d_out, int out_size) {
    const int*   ids   = (const int*)d_in[0];
    const float* tok   = (const float*)d_in[1];
    const float* pos   = (const float*)d_in[2];
    const float* Wq    = (const float*)d_in[3];
    const float* bq    = (const float*)d_in[4];
    const float* Wk    = (const float*)d_in[5];
    const float* bk    = (const float*)d_in[6];
    const float* Wv    = (const float*)d_in[7];
    const float* bv    = (const float*)d_in[8];
    const float* Wo    = (const float*)d_in[9];
    const float* bo    = (const float*)d_in[10];
    const float* ln1w  = (const float*)d_in[11];
    const float* ln1b  = (const float*)d_in[12];
    const float* ln2w  = (const float*)d_in[13];
    const float* ln2b  = (const float*)d_in[14];
    const float* Wup   = (const float*)d_in[15];
    const float* bup   = (const float*)d_in[16];
    const float* Wdown = (const float*)d_in[17];
    const float* bdown = (const float*)d_in[18];
    const float* fnw   = (const float*)d_in[19];
    const float* fnb   = (const float*)d_in[20];
    float* out = (float*)d_out;

    float *x, *bqkv;
    __nv_bfloat16 *qkv, *ahi, *alo, *bhi, *blo, *whi, *wlo;
    __half *thi, *tlo;
    cudaGetSymbolAddress((void**)&x, g_x);
    cudaGetSymbolAddress((void**)&qkv, g_qkv);
    cudaGetSymbolAddress((void**)&ahi, g_ahi);
    cudaGetSymbolAddress((void**)&alo, g_alo);
    cudaGetSymbolAddress((void**)&bhi, g_bhi);
    cudaGetSymbolAddress((void**)&blo, g_blo);
    cudaGetSymbolAddress((void**)&whi, g_whi);
    cudaGetSymbolAddress((void**)&wlo, g_wlo);
    cudaGetSymbolAddress((void**)&thi, g_thi);
    cudaGetSymbolAddress((void**)&tlo, g_tlo);
    cudaGetSymbolAddress((void**)&bqkv, g_bqkv);
    __nv_bfloat16 *qhi = qkv,              *qlo = qkv + (size_t)MR * Dc;
    __nv_bfloat16 *khi = qkv + 2ull*MR*Dc, *klo = qkv + 3ull*MR*Dc;
    __nv_bfloat16 *vhi = qkv + 4ull*MR*Dc, *vlo = qkv + 5ull*MR*Dc;

    cudaFuncSetAttribute(gemm_t<false,false,false>, cudaFuncAttributeMaxDynamicSharedMemorySize, SMEM_BF);
    cudaFuncSetAttribute(gemm_t<true,true,true>,    cudaFuncAttributeMaxDynamicSharedMemorySize, SMEM_FP);
    cudaFuncSetAttribute(gemm_t<true,false,false>,  cudaFuncAttributeMaxDynamicSharedMemorySize, SMEM_FP);
    cudaFuncSetAttribute(attn_mma, cudaFuncAttributeMaxDynamicSharedMemorySize, ATT_SMEM);

    const dim3 tb32(32, 8);
    const dim3 gDD(Dc / 32, Dc / 32);
    const dim3 gDF(Fc / 32, Dc / 32);
    const dim3 gFD(Dc / 32, Fc / 32);

    for (int l = 0; l < Lc; l++) {
        size_t lb = (size_t)l * WPL;
        wtrans_split<false><<<gDD, tb32>>>(Wq + (size_t)l * Dc * Dc, whi + lb,           wlo + lb,           Dc, Dc);
        wtrans_split<false><<<gDD, tb32>>>(Wk + (size_t)l * Dc * Dc, whi + lb + 1048576, wlo + lb + 1048576, Dc, Dc);
        wtrans_split<false><<<gDD, tb32>>>(Wv + (size_t)l * Dc * Dc, whi + lb + 2097152, wlo + lb + 2097152, Dc, Dc);
        wtrans_split<false><<<gDD, tb32>>>(Wo + (size_t)l * Dc * Dc, whi + lb + 3145728, wlo + lb + 3145728, Dc, Dc);
        wtrans_split<true><<<gDF, tb32>>>(Wup + (size_t)l * Dc * Fc, whi + lb + 4194304, wlo + lb + 4194304, Dc, Fc);
        wtrans_split<true><<<gFD, tb32>>>(Wdown + (size_t)l * Fc * Dc, whi + lb + 8388608, wlo + lb + 8388608, Fc, Dc);
    }
    split_kernel_h<<<(Vc * Dc + 255) / 256, 256>>>(tok, thi, tlo, Vc * Dc);
    pack_bqkv<<<(Lc * 3 * Dc + 255) / 256, 256>>>(bq, bk, bv, bqkv);

    embed_kernel<<<MR, 256>>>(ids, tok, pos, x);

    const dim3 gmQKV(3 * Dc / 128, MR / 128);   // 24 x 32
    const dim3 gmD(Dc / 128, MR / 128);         // 8 x 32
    const dim3 gmF(Fc / 128, MR / 128);         // 32 x 32
    const dim3 gmV(Vc / 128, MR / 128);         // 250 x 32
    const dim3 gA(Sc / 64, Hc, Bc);

    for (int l = 0; l < Lc; l++) {
        size_t lb = (size_t)l * WPL;
        ln_kernel<false><<<MR, 256>>>(x, ln1w + l * Dc, ln1b + l * Dc, ahi, alo);
        gemm_t<false,false,false><<<gmQKV, 256, SMEM_BF>>>(
            ahi, alo, whi + lb, wlo + lb, bqkv + l * 3 * Dc, nullptr,
            nullptr, qkv, nullptr, MR, 3 * Dc, Dc, Dc);
        attn_mma<<<gA, 128, ATT_SMEM>>>(qhi, qlo, khi, klo, vhi, vlo, ahi, alo);
        gemm_t<false,false,false><<<gmD, 256, SMEM_BF>>>(
            ahi, alo, whi + lb + 3145728, wlo + lb + 3145728, bo + l * Dc, x,
            x, nullptr, nullptr, MR, Dc, Dc, 0);
        ln_kernel<true><<<MR, 256>>>(x, ln2w + l * Dc, ln2b + l * Dc, ahi, alo);
        gemm_t<true,true,true><<<gmF, 256, SMEM_FP>>>(
            ahi, alo, whi + lb + 4194304, nullptr, bup + l * Fc, nullptr,
            nullptr, bhi, blo, MR, Fc, Dc, 0);
        gemm_t<true,false,false><<<gmD, 256, SMEM_FP>>>(
            bhi, blo, whi + lb + 8388608, nullptr, bdown + l * Dc, x,
            x, nullptr, nullptr, MR, Dc, Fc, 0);
    }

    ln_kernel<true><<<MR, 256>>>(x, fnw, fnb, ahi, alo);
    gemm_t<true,false,false><<<gmV, 256, SMEM_FP>>>(
        ahi, alo, (const __nv_bfloat16*)thi, nullptr,
        nullptr, nullptr, out, nullptr, nullptr, MR, Vc, Dc, 0);
}

// round 9
// speedup vs baseline: 7.9200x; 1.0198x over previous
#include <cuda_runtime.h>
#include <cuda_bf16.h>
#include <cuda_fp16.h>
#include <math.h>
#include <stdint.h>

#define Bc 2
#define Sc 2048
#define Dc 1024
#define Hc 16
#define Lc 6
#define Fc 4096
#define Vc 32000
#define DHc 64
#define MR (Bc*Sc)   // 4096 rows

// ---------------------------------------------------------------------------
// scratch (static device globals; no allocations allowed)
// ---------------------------------------------------------------------------
__device__ float g_x[MR*Dc];
__device__ __nv_bfloat16 g_qkv[6*MR*Dc];   // qhi,qlo,khi,klo,vhi,vlo (bf16)
__device__ __nv_bfloat16 g_ahi[MR*Fc];
__device__ __nv_bfloat16 g_alo[MR*Fc];
__device__ __nv_bfloat16 g_bhi[MR*Fc];     // GELU(ffn-up) output (fp16 bits)
__device__ __nv_bfloat16 g_blo[MR*Fc];
#define WPL 12582912   // elems per layer (4*D*D + D*F + F*D)
__device__ __nv_bfloat16 g_whi[Lc*WPL];    // attn weights bf16; FFN weights fp16 bits
__device__ __nv_bfloat16 g_wlo[Lc*WPL];
__device__ __half g_thi[Vc*Dc];
__device__ __half g_tlo[Vc*Dc];

// ---------------------------------------------------------------------------
// helpers
// ---------------------------------------------------------------------------
__device__ __forceinline__ uint32_t s2u(const void* ptr) {
    uint32_t a;
    asm("{ .reg .u64 t; cvta.to.shared.u64 t, %1; cvt.u32.u64 %0, t; }"
        : "=r"(a) : "l"(ptr));
    return a;
}
__device__ __forceinline__ void cpasync16(uint32_t dst, const void* src) {
    asm volatile("cp.async.cg.shared.global [%0], [%1], 16;" :: "r"(dst), "l"(src));
}
__device__ __forceinline__ void ldm4(uint32_t* r, uint32_t addr) {
    asm volatile("ldmatrix.sync.aligned.m8n8.x4.shared.b16 {%0,%1,%2,%3}, [%4];"
                 : "=r"(r[0]), "=r"(r[1]), "=r"(r[2]), "=r"(r[3]) : "r"(addr));
}
__device__ __forceinline__ void ldm4t(uint32_t* r, uint32_t addr) {
    asm volatile("ldmatrix.sync.aligned.m8n8.x4.trans.shared.b16 {%0,%1,%2,%3}, [%4];"
                 : "=r"(r[0]), "=r"(r[1]), "=r"(r[2]), "=r"(r[3]) : "r"(addr));
}
template<bool H>
__device__ __forceinline__ void mma16(float* d, const uint32_t* a, const uint32_t* b) {
    if (H)
        asm volatile(
            "mma.sync.aligned.m16n8k16.row.col.f32.f16.f16.f32 "
            "{%0,%1,%2,%3}, {%4,%5,%6,%7}, {%8,%9}, {%0,%1,%2,%3};"
            : "+f"(d[0]), "+f"(d[1]), "+f"(d[2]), "+f"(d[3])
            : "r"(a[0]), "r"(a[1]), "r"(a[2]), "r"(a[3]), "r"(b[0]), "r"(b[1]));
    else
        asm volatile(
            "mma.sync.aligned.m16n8k16.row.col.f32.bf16.bf16.f32 "
            "{%0,%1,%2,%3}, {%4,%5,%6,%7}, {%8,%9}, {%0,%1,%2,%3};"
            : "+f"(d[0]), "+f"(d[1]), "+f"(d[2]), "+f"(d[3])
            : "r"(a[0]), "r"(a[1]), "r"(a[2]), "r"(a[3]), "r"(b[0]), "r"(b[1]));
}
__device__ __forceinline__ void mma_bf16(float* d, const uint32_t* a, const uint32_t* b) {
    mma16<false>(d, a, b);
}
__device__ __forceinline__ void split2(float v, __nv_bfloat16* h, __nv_bfloat16* l) {
    __nv_bfloat16 hh = __float2bfloat16(v);
    *h = hh;
    *l = __float2bfloat16(v - __bfloat162float(hh));
}
__device__ __forceinline__ void split2h(float v, __half* h, __half* l) {
    __half hh = __float2half(v);
    *h = hh;
    *l = __float2half(v - __half2float(hh));
}
__device__ __forceinline__ void pk2(float x, float y, uint32_t& hi, uint32_t& lo) {
    __nv_bfloat16 xh = __float2bfloat16(x), yh = __float2bfloat16(y);
    __nv_bfloat16 xl = __float2bfloat16(x - __bfloat162float(xh));
    __nv_bfloat16 yl = __float2bfloat16(y - __bfloat162float(yh));
    hi = ((uint32_t)__bfloat16_as_ushort(yh) << 16) | __bfloat16_as_ushort(xh);
    lo = ((uint32_t)__bfloat16_as_ushort(yl) << 16) | __bfloat16_as_ushort(xl);
}
__device__ __forceinline__ void pk2h(float x, float y, uint32_t& hi, uint32_t& lo) {
    __half xh = __float2half(x), yh = __float2half(y);
    __half xl = __float2half(x - __half2float(xh));
    __half yl = __float2half(y - __half2float(yh));
    hi = ((uint32_t)__half_as_ushort(yh) << 16) | __half_as_ushort(xh);
    lo = ((uint32_t)__half_as_ushort(yl) << 16) | __half_as_ushort(xl);
}
// fast 2^y on the FMA pipe (y <= 0), err ~2e-6
__device__ __forceinline__ float ex2(float y) {
    y = fmaxf(y, -126.f);
    float fn = y + 12582912.f;
    int n = __float_as_int(fn) - 0x4B400000;
    float r = y - (fn - 12582912.f);
    float p = 1.3333558e-3f;
    p = fmaf(p, r, 9.6181291e-3f);
    p = fmaf(p, r, 5.5504109e-2f);
    p = fmaf(p, r, 2.4022651e-1f);
    p = fmaf(p, r, 6.9314718e-1f);
    p = fmaf(p, r, 1.0f);
    return p * __int_as_float((n + 127) << 23);
}
__device__ __forceinline__ uint32_t swz(uint32_t off) {
    return off ^ ((off >> 3) & 0x70);
}
__device__ __forceinline__ float gelu_f(float v) {
    return 0.5f * v * (1.0f + erff(v * 0.70710678118654752f));
}

// ---------------------------------------------------------------------------
// split-precision MMA GEMM, K-chunk 64, SW128 smem, 3-stage pipeline,
// templated warp-N width (WN=32 -> block 128x128; WN=64 -> block 128x256).
// bf16 (3-term): C = (Ah+Al)@(Bh+Bl)^T ; fp16 (2-term): C = (Ah+Al)@Bh^T
// ---------------------------------------------------------------------------
#define T16 16384                       // one 128x64 16-bit tile (128B rows)

template<int NB, int BROWS>
__device__ __forceinline__ void load_stageG(
    const __nv_bfloat16* A0, const __nv_bfloat16* A1,
    const __nv_bfloat16* B0, const __nv_bfloat16* B1,
    int K, int k0, uint32_t dbase, int tid) {
#pragma unroll
    for (int t = 0; t < 2; t++) {
        const __nv_bfloat16* s = t ? A1 : A0;
#pragma unroll
        for (int u = 0; u < 4; u++) {
            int id = u * 256 + tid;
            int row = id >> 3, c = id & 7;
            cpasync16(dbase + t * T16 + swz(row * 128 + c * 16),
                      s + (size_t)row * K + k0 + c * 8);
        }
    }
#pragma unroll
    for (int t = 0; t < NB; t++) {
        const __nv_bfloat16* s = t ? B1 : B0;
#pragma unroll
        for (int u = 0; u < BROWS / 32; u++) {
            int id = u * 256 + tid;
            int row = id >> 3, c = id & 7;
            cpasync16(dbase + 2 * T16 + t * (BROWS * 128) + swz(row * 128 + c * 16),
                      s + (size_t)row * K + k0 + c * 8);
        }
    }
}

template<bool FP16W, bool GELU, bool OUT16, int WN>
__global__ __launch_bounds__(256, 1)
void gemm_t(const __nv_bfloat16* __restrict__ Ahi, const __nv_bfloat16* __restrict__ Alo,
            const __nv_bfloat16* __restrict__ Bhi, const __nv_bfloat16* __restrict__ Blo,
            const float* __restrict__ bias, const float* __restrict__ bias2,
            const float* __restrict__ bias3, const float* __restrict__ res,
            float* __restrict__ C, __nv_bfloat16* __restrict__ Chi,
            __nv_bfloat16* __restrict__ Clo, int M, int N, int K, int oseg) {
    constexpr int NB = FP16W ? 1 : 2;       // B tiles (hi only vs hi+lo)
    constexpr int BROWS = 4 * WN;           // B tile rows = block N width
    constexpr int NTT = WN / 8;             // n microtiles per warp
    constexpr int STAGE = (256 + NB * BROWS) * 128;
    extern __shared__ char smem[];
    const uint32_t sbase = s2u(smem);
    const int tid = threadIdx.x;
    const int warp = tid >> 5, lane = tid & 31;
    const int bm = blockIdx.y * 128, bn = blockIdx.x * BROWS;
    const int wm = (warp >> 2) * 64, wn = (warp & 3) * WN;

    float acc[4][NTT][4];
#pragma unroll
    for (int i = 0; i < 4; i++)
#pragma unroll
        for (int j = 0; j < NTT; j++)
#pragma unroll
            for (int q = 0; q < 4; q++) acc[i][j][q] = 0.f;

    const __nv_bfloat16* A0 = Ahi + (size_t)bm * K;
    const __nv_bfloat16* A1 = Alo + (size_t)bm * K;
    const __nv_bfloat16* B0 = Bhi + (size_t)bn * K;
    const __nv_bfloat16* B1 = FP16W ? nullptr : Blo + (size_t)bn * K;

    const int nch = K >> 6;
    load_stageG<NB, BROWS>(A0, A1, B0, B1, K, 0, sbase, tid);
    asm volatile("cp.async.commit_group;" ::: "memory");
    if (nch > 1) {
        load_stageG<NB, BROWS>(A0, A1, B0, B1, K, 64, sbase + STAGE, tid);
        asm volatile("cp.async.commit_group;" ::: "memory");
    }

    const int g = lane >> 3, r = lane & 7;
    const int a_row = r + (g & 1) * 8;
    const int a_cb  = (g >> 1) * 16;
    const int b_row = (g >> 1) * 8 + r;
    const int b_cb  = (g & 1) * 16;

    for (int c = 0; c < nch; c++) {
        if (c == nch - 1) asm volatile("cp.async.wait_group 0;" ::: "memory");
        else              asm volatile("cp.async.wait_group 1;" ::: "memory");
        __syncthreads();   // single barrier per chunk

        uint32_t base = sbase + (c % 3) * STAGE;
#pragma unroll
        for (int ks = 0; ks < 4; ks++) {
            const int kb = ks * 32;
            uint32_t ah[4][4], al[4][4], bh[NTT][2], bl[NTT][2];
#pragma unroll
            for (int mt = 0; mt < 4; mt++) {
                uint32_t ad = base + swz((wm + mt * 16 + a_row) * 128 + kb + a_cb);
                ldm4(ah[mt], ad);
                ldm4(al[mt], ad + T16);
            }
#pragma unroll
            for (int p = 0; p < WN / 16; p++) {
                uint32_t bd = base + 2 * T16 + swz((wn + p * 16 + b_row) * 128 + kb + b_cb);
                uint32_t t4[4];
                ldm4(t4, bd);
                bh[2 * p][0] = t4[0]; bh[2 * p][1] = t4[1];
                bh[2 * p + 1][0] = t4[2]; bh[2 * p + 1][1] = t4[3];
                if (!FP16W) {
                    ldm4(t4, bd + BROWS * 128);
                    bl[2 * p][0] = t4[0]; bl[2 * p][1] = t4[1];
                    bl[2 * p + 1][0] = t4[2]; bl[2 * p + 1][1] = t4[3];
                }
            }
#pragma unroll
            for (int mt = 0; mt < 4; mt++)
#pragma unroll
                for (int nt = 0; nt < NTT; nt++) {
                    mma16<FP16W>(acc[mt][nt], ah[mt], bh[nt]);
                    mma16<FP16W>(acc[mt][nt], al[mt], bh[nt]);
                    if (!FP16W) mma16<false>(acc[mt][nt], ah[mt], bl[nt]);
                }
        }
        if (c + 2 < nch) {
            load_stageG<NB, BROWS>(A0, A1, B0, B1, K, (c + 2) * 64,
                                   sbase + ((c + 2) % 3) * STAGE, tid);
            asm volatile("cp.async.commit_group;" ::: "memory");
        }
    }

    // ---- epilogue
    __nv_bfloat16 *chi = Chi, *clo = Clo;
    int ost = N, bnl = bn;
    if (oseg) {
        int t = bn / oseg;
        bnl = bn - t * oseg;
        ost = oseg;
        chi = Chi + (size_t)(2 * t) * M * oseg;
        clo = Chi + (size_t)(2 * t + 1) * M * oseg;
    }
#pragma unroll
    for (int mt = 0; mt < 4; mt++) {
        int r0 = bm + wm + mt * 16 + (lane >> 2);
#pragma unroll
        for (int nt = 0; nt < NTT; nt++) {
            int ccg = bn + wn + nt * 8 + (lane & 3) * 2;   // global col
            int ccl = bnl + wn + nt * 8 + (lane & 3) * 2;  // store col
            const float* bsel = bias;
            int bidx = ccg;
            if (bias2) {            // QKV: 3 bias arrays of Dc each
                if (ccg >= 2 * Dc)      bsel = bias3;
                else if (ccg >= Dc)     bsel = bias2;
                bidx = ccg & (Dc - 1);
            }
            float b0 = bsel ? bsel[bidx] : 0.f, b1 = bsel ? bsel[bidx + 1] : 0.f;
            float v0 = acc[mt][nt][0] + b0, v1 = acc[mt][nt][1] + b1;
            float v2 = acc[mt][nt][2] + b0, v3 = acc[mt][nt][3] + b1;
            if (GELU) {
                v0 = gelu_f(v0); v1 = gelu_f(v1);
                v2 = gelu_f(v2); v3 = gelu_f(v3);
            }
            if (chi) {
                uint32_t h01, l01, h23, l23;
                if (OUT16) { pk2h(v0, v1, h01, l01); pk2h(v2, v3, h23, l23); }
                else       { pk2(v0, v1, h01, l01);  pk2(v2, v3, h23, l23); }
                *(uint32_t*)&chi[(size_t)r0 * ost + ccl] = h01;
                *(uint32_t*)&clo[(size_t)r0 * ost + ccl] = l01;
                *(uint32_t*)&chi[(size_t)(r0 + 8) * ost + ccl] = h23;
                *(uint32_t*)&clo[(size_t)(r0 + 8) * ost + ccl] = l23;
            } else {
                if (res) {
                    v0 += res[(size_t)r0 * N + ccg];       v1 += res[(size_t)r0 * N + ccg + 1];
                    v2 += res[(size_t)(r0 + 8) * N + ccg]; v3 += res[(size_t)(r0 + 8) * N + ccg + 1];
                }
                *(float2*)&C[(size_t)r0 * N + ccg] = make_float2(v0, v1);
                *(float2*)&C[(size_t)(r0 + 8) * N + ccg] = make_float2(v2, v3);
            }
        }
    }
}

#define SMEM_BF32 (3*(256+2*128)*128)   // 196608
#define SMEM_FP32 (3*(256+128)*128)     // 147456
#define SMEM_FP64 (3*(256+256)*128)     // 196608

// ---------------------------------------------------------------------------
// MMA flash attention: block = (qt 64 rows, h, b), 4 warps, 64-col k-tiles.
// ---------------------------------------------------------------------------
#define ATT_STAGE 32768
#define ATT_SMEM (2*ATT_STAGE)

__global__ __launch_bounds__(128, 2)
void attn_mma(const __nv_bfloat16* __restrict__ qhi, const __nv_bfloat16* __restrict__ qlo,
              const __nv_bfloat16* __restrict__ khi, const __nv_bfloat16* __restrict__ klo,
              const __nv_bfloat16* __restrict__ vhi, const __nv_bfloat16* __restrict__ vlo,
              __nv_bfloat16* __restrict__ ohi, __nv_bfloat16* __restrict__ olo) {
    extern __shared__ char sm[];
    const uint32_t sb = s2u(sm);
    const int qt = blockIdx.x, h = blockIdx.y, b = blockIdx.z;
    const int tid = threadIdx.x, warp = tid >> 5, lane = tid & 31;
    const int g = lane >> 3, r = lane & 7;
    const int a_row = r + (g & 1) * 8, a_cb = (g >> 1) * 16;
    const int b_row = (g >> 1) * 8 + r, b_cb = (g & 1) * 16;
    const size_t hoff = (size_t)h * 64;
    const size_t rowbase = (size_t)(b * Sc) * Dc;

#pragma unroll
    for (int t = 0; t < 2; t++) {
        const __nv_bfloat16* src = (t ? qlo : qhi) + rowbase + (size_t)(qt * 64) * Dc + hoff;
#pragma unroll
        for (int u = 0; u < 4; u++) {
            int id = u * 128 + tid;
            int row = id >> 3, c16 = id & 7;
            uint4 val = *(const uint4*)((const char*)(src + (size_t)row * Dc) + c16 * 16);
            *(uint4*)(sm + t * 8192 + swz(row * 128 + c16 * 16)) = val;
        }
    }
    __syncthreads();
    uint32_t qh_[4][4], ql_[4][4];
#pragma unroll
    for (int ks = 0; ks < 4; ks++) {
        uint32_t ad = sb + swz((warp * 16 + a_row) * 128 + ks * 32 + a_cb);
        ldm4(qh_[ks], ad);
        ldm4(ql_[ks], ad + 8192);
    }
    __syncthreads();

    float O[8][4];
#pragma unroll
    for (int i = 0; i < 8; i++)
#pragma unroll
        for (int j = 0; j < 4; j++) O[i][j] = 0.f;
    float m2[2] = {-1e30f, -1e30f};
    float lsum[2] = {0.f, 0.f};

    const __nv_bfloat16* srcs[4] = {khi, klo, vhi, vlo};
#define LOAD_KV(S, KT) do { \
        size_t base_ = rowbase + (size_t)((KT) * 64) * Dc + hoff; \
        uint32_t dst_ = sb + (S) * ATT_STAGE; \
        _Pragma("unroll") \
        for (int t = 0; t < 4; t++) { \
            _Pragma("unroll") \
            for (int u = 0; u < 4; u++) { \
                int id = u * 128 + tid; \
                int row = id >> 3, c16 = id & 7; \
                cpasync16(dst_ + t * 8192 + swz(row * 128 + c16 * 16), \
                          (const char*)(srcs[t] + base_ + (size_t)row * Dc) + c16 * 16); \
            } \
        } \
        asm volatile("cp.async.commit_group;" ::: "memory"); \
    } while (0)

    LOAD_KV(0, 0);

    for (int kt = 0; kt <= qt; kt++) {
        if (kt < qt) {
            LOAD_KV((kt + 1) & 1, kt + 1);
            asm volatile("cp.async.wait_group 1;" ::: "memory");
        } else {
            asm volatile("cp.async.wait_group 0;" ::: "memory");
        }
        __syncthreads();
        const uint32_t kb_ = sb + (kt & 1) * ATT_STAGE;

        float S[8][4];
#pragma unroll
        for (int i = 0; i < 8; i++)
#pragma unroll
            for (int j = 0; j < 4; j++) S[i][j] = 0.f;
#pragma unroll
        for (int ks = 0; ks < 4; ks++) {
#pragma unroll
            for (int p = 0; p < 4; p++) {
                uint32_t t4h[4], t4l[4];
                uint32_t bd = kb_ + swz((p * 16 + b_row) * 128 + ks * 32 + b_cb);
                ldm4(t4h, bd);
                ldm4(t4l, bd + 8192);
                uint32_t bh0[2] = {t4h[0], t4h[1]}, bh1[2] = {t4h[2], t4h[3]};
                uint32_t bl0[2] = {t4l[0], t4l[1]}, bl1[2] = {t4l[2], t4l[3]};
                mma_bf16(S[2 * p],     qh_[ks], bh0);
                mma_bf16(S[2 * p],     qh_[ks], bl0);
                mma_bf16(S[2 * p],     ql_[ks], bh0);
                mma_bf16(S[2 * p + 1], qh_[ks], bh1);
                mma_bf16(S[2 * p + 1], qh_[ks], bl1);
                mma_bf16(S[2 * p + 1], ql_[ks], bh1);
            }
        }
        const float SC = 0.18033688f;
#pragma unroll
        for (int i = 0; i < 8; i++)
#pragma unroll
            for (int j = 0; j < 4; j++) S[i][j] *= SC;
        if (kt == qt) {
            int rr = warp * 16 + (lane >> 2);
#pragma unroll
            for (int nt = 0; nt < 8; nt++) {
                int cc = nt * 8 + (lane & 3) * 2;
                if (cc     > rr)     S[nt][0] = -1e30f;
                if (cc + 1 > rr)     S[nt][1] = -1e30f;
                if (cc     > rr + 8) S[nt][2] = -1e30f;
                if (cc + 1 > rr + 8) S[nt][3] = -1e30f;
            }
        }
        float mx0 = -1e30f, mx1 = -1e30f;
#pragma unroll
        for (int nt = 0; nt < 8; nt++) {
            mx0 = fmaxf(mx0, fmaxf(S[nt][0], S[nt][1]));
            mx1 = fmaxf(mx1, fmaxf(S[nt][2], S[nt][3]));
        }
        mx0 = fmaxf(mx0, __shfl_xor_sync(0xffffffff, mx0, 1));
        mx0 = fmaxf(mx0, __shfl_xor_sync(0xffffffff, mx0, 2));
        mx1 = fmaxf(mx1, __shfl_xor_sync(0xffffffff, mx1, 1));
        mx1 = fmaxf(mx1, __shfl_xor_sync(0xffffffff, mx1, 2));
        float mn0 = fmaxf(m2[0], mx0), mn1 = fmaxf(m2[1], mx1);
        float al0 = ex2(m2[0] - mn0), al1 = ex2(m2[1] - mn1);
        m2[0] = mn0; m2[1] = mn1;
        float s0 = 0.f, s1 = 0.f;
#pragma unroll
        for (int nt = 0; nt < 8; nt++) {
            S[nt][0] = ex2(S[nt][0] - mn0); s0 += S[nt][0];
            S[nt][1] = ex2(S[nt][1] - mn0); s0 += S[nt][1];
            S[nt][2] = ex2(S[nt][2] - mn1); s1 += S[nt][2];
            S[nt][3] = ex2(S[nt][3] - mn1); s1 += S[nt][3];
        }
        s0 += __shfl_xor_sync(0xffffffff, s0, 1);
        s0 += __shfl_xor_sync(0xffffffff, s0, 2);
        s1 += __shfl_xor_sync(0xffffffff, s1, 1);
        s1 += __shfl_xor_sync(0xffffffff, s1, 2);
        lsum[0] = lsum[0] * al0 + s0;
        lsum[1] = lsum[1] * al1 + s1;
#pragma unroll
        for (int nt = 0; nt < 8; nt++) {
            O[nt][0] *= al0; O[nt][1] *= al0;
            O[nt][2] *= al1; O[nt][3] *= al1;
        }
        const uint32_t vb = kb_ + 16384;
#pragma unroll
        for (int ks = 0; ks < 4; ks++) {
            uint32_t pah[4], pal[4];
            pk2(S[2 * ks][0],     S[2 * ks][1],     pah[0], pal[0]);
            pk2(S[2 * ks][2],     S[2 * ks][3],     pah[1], pal[1]);
            pk2(S[2 * ks + 1][0], S[2 * ks + 1][1], pah[2], pal[2]);
            pk2(S[2 * ks + 1][2], S[2 * ks + 1][3], pah[3], pal[3]);
#pragma unroll
            for (int dg = 0; dg < 4; dg++) {
                uint32_t th[4], tl[4];
                uint32_t vd = vb + swz((ks * 16 + (lane & 15)) * 128 + dg * 32 + (lane >> 4) * 16);
                ldm4t(th, vd);
                ldm4t(tl, vd + 8192);
                uint32_t bh0[2] = {th[0], th[1]}, bh1[2] = {th[2], th[3]};
                uint32_t bl0[2] = {tl[0], tl[1]}, bl1[2] = {tl[2], tl[3]};
                mma_bf16(O[2 * dg],     pah, bh0);
                mma_bf16(O[2 * dg],     pah, bl0);
                mma_bf16(O[2 * dg],     pal, bh0);
                mma_bf16(O[2 * dg + 1], pah, bh1);
                mma_bf16(O[2 * dg + 1], pah, bl1);
                mma_bf16(O[2 * dg + 1], pal, bh1);
            }
        }
        __syncthreads();
    }

    float inv0 = 1.f / lsum[0], inv1 = 1.f / lsum[1];
    int r0 = qt * 64 + warp * 16 + (lane >> 2);
#pragma unroll
    for (int nt = 0; nt < 8; nt++) {
        int cc = nt * 8 + (lane & 3) * 2;
        size_t o0 = rowbase + (size_t)r0 * Dc + hoff + cc;
        size_t o1 = o0 + (size_t)8 * Dc;
        uint32_t h01, l01, h23, l23;
        pk2(O[nt][0] * inv0, O[nt][1] * inv0, h01, l01);
        pk2(O[nt][2] * inv1, O[nt][3] * inv1, h23, l23);
        *(uint32_t*)&ohi[o0] = h01; *(uint32_t*)&olo[o0] = l01;
        *(uint32_t*)&ohi[o1] = h23; *(uint32_t*)&olo[o1] = l23;
    }
}

// ---------------------------------------------------------------------------
// prep kernels
// ---------------------------------------------------------------------------
template<bool H>
__global__ void wtrans_split(const float* __restrict__ W,
                             void* __restrict__ hi_, void* __restrict__ lo_,
                             int K, int N) {
    __shared__ float t[32][33];
    int n0 = blockIdx.x * 32, k0 = blockIdx.y * 32;
    int tx = threadIdx.x, ty = threadIdx.y;
#pragma unroll
    for (int r = 0; r < 4; r++)
        t[ty + r * 8][tx] = W[(size_t)(k0 + ty + r * 8) * N + n0 + tx];
    __syncthreads();
#pragma unroll
    for (int r = 0; r < 4; r++) {
        int a = ty + r * 8;
        float v = t[tx][a];
        size_t o = (size_t)(n0 + a) * K + k0 + tx;
        if (H) split2h(v, (__half*)hi_ + o, (__half*)lo_ + o);
        else   split2(v, (__nv_bfloat16*)hi_ + o, (__nv_bfloat16*)lo_ + o);
    }
}

__global__ void split_kernel_h(const float* __restrict__ in,
                               __half* __restrict__ hi,
                               __half* __restrict__ lo, int n) {
    int i = blockIdx.x * 256 + threadIdx.x;
    if (i < n) split2h(in[i], &hi[i], &lo[i]);
}

__global__ void embed_kernel(const int* __restrict__ ids,
                             const float* __restrict__ tok,
                             const float* __restrict__ pos,
                             float* __restrict__ x) {
    int row = blockIdx.x;
    int s = row % Sc;
    int id = ids[row];
    const float* tr = tok + (size_t)id * Dc;
    const float* pr = pos + (size_t)s * Dc;
    float* xr = x + (size_t)row * Dc;
    for (int d = threadIdx.x; d < Dc; d += blockDim.x) xr[d] = tr[d] + pr[d];
}

template<bool HOUT>
__global__ void ln_kernel(const float* __restrict__ x,
                          const float* __restrict__ w, const float* __restrict__ b,
                          void* __restrict__ yhi, void* __restrict__ ylo) {
    int row = blockIdx.x;
    const float* xr = x + (size_t)row * Dc;
    __shared__ float r1[256], r2[256];
    float s = 0.f, s2 = 0.f;
    for (int d = threadIdx.x; d < Dc; d += 256) {
        float v = xr[d];
        s += v; s2 += v * v;
    }
    r1[threadIdx.x] = s; r2[threadIdx.x] = s2;
    __syncthreads();
    for (int st = 128; st > 0; st >>= 1) {
        if (threadIdx.x < st) {
            r1[threadIdx.x] += r1[threadIdx.x + st];
            r2[threadIdx.x] += r2[threadIdx.x + st];
        }
        __syncthreads();
    }
    float mean = r1[0] * (1.0f / Dc);
    float var = r2[0] * (1.0f / Dc) - mean * mean;
    float rstd = rsqrtf(var + 1e-5f);
    for (int d = threadIdx.x; d < Dc; d += 256) {
        float v = (xr[d] - mean) * rstd * w[d] + b[d];
        size_t o = (size_t)row * Dc + d;
        if (HOUT) split2h(v, (__half*)yhi + o, (__half*)ylo + o);
        else      split2(v, (__nv_bfloat16*)yhi + o, (__nv_bfloat16*)ylo + o);
    }
}

// ---------------------------------------------------------------------------
// launcher
// ---------------------------------------------------------------------------
extern "C" void kernel_launch(void* const* d_in, const int* in_sizes, int n_in,
                              void* d_out, int out_size) {
    const int*   ids   = (const int*)d_in[0];
    const float* tok   = (const float*)d_in[1];
    const float* pos   = (const float*)d_in[2];
    const float* Wq    = (const float*)d_in[3];
    const float* bq    = (const float*)d_in[4];
    const float* Wk    = (const float*)d_in[5];
    const float* bk    = (const float*)d_in[6];
    const float* Wv    = (const float*)d_in[7];
    const float* bv    = (const float*)d_in[8];
    const float* Wo    = (const float*)d_in[9];
    const float* bo    = (const float*)d_in[10];
    const float* ln1w  = (const float*)d_in[11];
    const float* ln1b  = (const float*)d_in[12];
    const float* ln2w  = (const float*)d_in[13];
    const float* ln2b  = (const float*)d_in[14];
    const float* Wup   = (const float*)d_in[15];
    const float* bup   = (const float*)d_in[16];
    const float* Wdown = (const float*)d_in[17];
    const float* bdown = (const float*)d_in[18];
    const float* fnw   = (const float*)d_in[19];
    const float* fnb   = (const float*)d_in[20];
    float* out = (float*)d_out;

    float *x;
    __nv_bfloat16 *qkv, *ahi, *alo, *bhi, *blo, *whi, *wlo;
    __half *thi, *tlo;
    cudaGetSymbolAddress((void**)&x, g_x);
    cudaGetSymbolAddress((void**)&qkv, g_qkv);
    cudaGetSymbolAddress((void**)&ahi, g_ahi);
    cudaGetSymbolAddress((void**)&alo, g_alo);
    cudaGetSymbolAddress((void**)&bhi, g_bhi);
    cudaGetSymbolAddress((void**)&blo, g_blo);
    cudaGetSymbolAddress((void**)&whi, g_whi);
    cudaGetSymbolAddress((void**)&wlo, g_wlo);
    cudaGetSymbolAddress((void**)&thi, g_thi);
    cudaGetSymbolAddress((void**)&tlo, g_tlo);
    __nv_bfloat16 *qhi = qkv,              *qlo = qkv + (size_t)MR * Dc;
    __nv_bfloat16 *khi = qkv + 2ull*MR*Dc, *klo = qkv + 3ull*MR*Dc;
    __nv_bfloat16 *vhi = qkv + 4ull*MR*Dc, *vlo = qkv + 5ull*MR*Dc;

    cudaFuncSetAttribute(gemm_t<false,false,false,32>, cudaFuncAttributeMaxDynamicSharedMemorySize, SMEM_BF32);
    cudaFuncSetAttribute(gemm_t<true,true,true,32>,    cudaFuncAttributeMaxDynamicSharedMemorySize, SMEM_FP32);
    cudaFuncSetAttribute(gemm_t<true,false,false,64>,  cudaFuncAttributeMaxDynamicSharedMemorySize, SMEM_FP64);
    cudaFuncSetAttribute(attn_mma, cudaFuncAttributeMaxDynamicSharedMemorySize, ATT_SMEM);

    const dim3 tb32(32, 8);
    const dim3 gDD(Dc / 32, Dc / 32);
    const dim3 gDF(Fc / 32, Dc / 32);
    const dim3 gFD(Dc / 32, Fc / 32);

    const dim3 gmQKV(3 * Dc / 128, MR / 128);   // 24 x 32
    const dim3 gmD(Dc / 128, MR / 128);         // 8 x 32
    const dim3 gmF(Fc / 128, MR / 128);         // 32 x 32
    const dim3 gmD2(Dc / 256, MR / 128);        // 4 x 32  (WN=64)
    const dim3 gmV2(Vc / 256, MR / 128);        // 125 x 32 (WN=64)
    const dim3 gA(Sc / 64, Hc, Bc);

    // --- launches 1-5: minimal prep for layer-0 QKV, so the QKV GEMM is
    //     launch #6 (ncu -s 5 -c 1 captures it) ---
    embed_kernel<<<MR, 256>>>(ids, tok, pos, x);                                   // 1
    wtrans_split<false><<<gDD, tb32>>>(Wq, whi, wlo, Dc, Dc);                      // 2
    wtrans_split<false><<<gDD, tb32>>>(Wk, whi + 1048576, wlo + 1048576, Dc, Dc);  // 3
    wtrans_split<false><<<gDD, tb32>>>(Wv, whi + 2097152, wlo + 2097152, Dc, Dc);  // 4
    ln_kernel<false><<<MR, 256>>>(x, ln1w, ln1b, ahi, alo);                        // 5
    gemm_t<false,false,false,32><<<gmQKV, 256, SMEM_BF32>>>(                       // 6 <- profiled
        ahi, alo, whi, wlo, bq, bk, bv, nullptr,
        nullptr, qkv, nullptr, MR, 3 * Dc, Dc, Dc);

    // remaining weight conversion
    wtrans_split<false><<<gDD, tb32>>>(Wo, whi + 3145728, wlo + 3145728, Dc, Dc);
    wtrans_split<true><<<gDF, tb32>>>(Wup, whi + 4194304, wlo + 4194304, Dc, Fc);
    wtrans_split<true><<<gFD, tb32>>>(Wdown, whi + 8388608, wlo + 8388608, Fc, Dc);
    for (int l = 1; l < Lc; l++) {
        size_t lb = (size_t)l * WPL;
        wtrans_split<false><<<gDD, tb32>>>(Wq + (size_t)l * Dc * Dc, whi + lb,           wlo + lb,           Dc, Dc);
        wtrans_split<false><<<gDD, tb32>>>(Wk + (size_t)l * Dc * Dc, whi + lb + 1048576, wlo + lb + 1048576, Dc, Dc);
        wtrans_split<false><<<gDD, tb32>>>(Wv + (size_t)l * Dc * Dc, whi + lb + 2097152, wlo + lb + 2097152, Dc, Dc);
        wtrans_split<false><<<gDD, tb32>>>(Wo + (size_t)l * Dc * Dc, whi + lb + 3145728, wlo + lb + 3145728, Dc, Dc);
        wtrans_split<true><<<gDF, tb32>>>(Wup + (size_t)l * Dc * Fc, whi + lb + 4194304, wlo + lb + 4194304, Dc, Fc);
        wtrans_split<true><<<gFD, tb32>>>(Wdown + (size_t)l * Fc * Dc, whi + lb + 8388608, wlo + lb + 8388608, Fc, Dc);
    }
    split_kernel_h<<<(Vc * Dc + 255) / 256, 256>>>(tok, thi, tlo, Vc * Dc);

    for (int l = 0; l < Lc; l++) {
        size_t lb = (size_t)l * WPL;
        if (l > 0) {
            ln_kernel<false><<<MR, 256>>>(x, ln1w + l * Dc, ln1b + l * Dc, ahi, alo);
            gemm_t<false,false,false,32><<<gmQKV, 256, SMEM_BF32>>>(
                ahi, alo, whi + lb, wlo + lb, bq + l * Dc, bk + l * Dc, bv + l * Dc, nullptr,
                nullptr, qkv, nullptr, MR, 3 * Dc, Dc, Dc);
        }
        attn_mma<<<gA, 128, ATT_SMEM>>>(qhi, qlo, khi, klo, vhi, vlo, ahi, alo);
        gemm_t<false,false,false,32><<<gmD, 256, SMEM_BF32>>>(
            ahi, alo, whi + lb + 3145728, wlo + lb + 3145728, bo + l * Dc, nullptr, nullptr, x,
            x, nullptr, nullptr, MR, Dc, Dc, 0);
        ln_kernel<true><<<MR, 256>>>(x, ln2w + l * Dc, ln2b + l * Dc, ahi, alo);
        gemm_t<true,true,true,32><<<gmF, 256, SMEM_FP32>>>(
            ahi, alo, whi + lb + 4194304, nullptr, bup + l * Fc, nullptr, nullptr, nullptr,
            nullptr, bhi, blo, MR, Fc, Dc, 0);
        gemm_t<true,false,false,64><<<gmD2, 256, SMEM_FP64>>>(
            bhi, blo, whi + lb + 8388608, nullptr, bdown + l * Dc, nullptr, nullptr, x,
            x, nullptr, nullptr, MR, Dc, Fc, 0);
    }

    ln_kernel<true><<<MR, 256>>>(x, fnw, fnb, ahi, alo);
    gemm_t<true,false,false,64><<<gmV2, 256, SMEM_FP64>>>(
        ahi, alo, (const __nv_bfloat16*)thi, nullptr,
        nullptr, nullptr, nullptr, nullptr, out, nullptr, nullptr, MR, Vc, Dc, 0);
}

// round 11
// speedup vs baseline: 8.3968x; 1.0602x over previous
#include <cuda_runtime.h>
#include <cuda_bf16.h>
#include <cuda_fp16.h>
#include <math.h>
#include <stdint.h>

#define Bc 2
#define Sc 2048
#define Dc 1024
#define Hc 16
#define Lc 6
#define Fc 4096
#define Vc 32000
#define DHc 64
#define MR (Bc*Sc)   // 4096 rows

// ---------------------------------------------------------------------------
// scratch (static device globals; no allocations allowed)
// 16-bit buffers are untyped bit-containers (bf16* alias, may hold fp16 bits)
// ---------------------------------------------------------------------------
__device__ float g_x[MR*Dc];
__device__ __nv_bfloat16 g_qkv[6*MR*Dc];   // qhi,qlo,khi,klo,vhi,vlo (fp16 bits)
__device__ __nv_bfloat16 g_ahi[MR*Fc];
__device__ __nv_bfloat16 g_alo[MR*Fc];
__device__ __nv_bfloat16 g_bhi[MR*Fc];
__device__ __nv_bfloat16 g_blo[MR*Fc];
#define WPL 12582912   // elems per layer (4*D*D + D*F + F*D)
__device__ __nv_bfloat16 g_whi[Lc*WPL];    // all weights fp16 bits now
__device__ __nv_bfloat16 g_wlo[Lc*WPL];
__device__ __half g_thi[Vc*Dc];
__device__ __half g_tlo[Vc*Dc];

// ---------------------------------------------------------------------------
// helpers
// ---------------------------------------------------------------------------
__device__ __forceinline__ uint32_t s2u(const void* ptr) {
    uint32_t a;
    asm("{ .reg .u64 t; cvta.to.shared.u64 t, %1; cvt.u32.u64 %0, t; }"
        : "=r"(a) : "l"(ptr));
    return a;
}
__device__ __forceinline__ void cpasync16(uint32_t dst, const void* src) {
    asm volatile("cp.async.cg.shared.global [%0], [%1], 16;" :: "r"(dst), "l"(src));
}
__device__ __forceinline__ void ldm4(uint32_t* r, uint32_t addr) {
    asm volatile("ldmatrix.sync.aligned.m8n8.x4.shared.b16 {%0,%1,%2,%3}, [%4];"
                 : "=r"(r[0]), "=r"(r[1]), "=r"(r[2]), "=r"(r[3]) : "r"(addr));
}
__device__ __forceinline__ void ldm4t(uint32_t* r, uint32_t addr) {
    asm volatile("ldmatrix.sync.aligned.m8n8.x4.trans.shared.b16 {%0,%1,%2,%3}, [%4];"
                 : "=r"(r[0]), "=r"(r[1]), "=r"(r[2]), "=r"(r[3]) : "r"(addr));
}
template<bool H>
__device__ __forceinline__ void mma16(float* d, const uint32_t* a, const uint32_t* b) {
    if (H)
        asm volatile(
            "mma.sync.aligned.m16n8k16.row.col.f32.f16.f16.f32 "
            "{%0,%1,%2,%3}, {%4,%5,%6,%7}, {%8,%9}, {%0,%1,%2,%3};"
            : "+f"(d[0]), "+f"(d[1]), "+f"(d[2]), "+f"(d[3])
            : "r"(a[0]), "r"(a[1]), "r"(a[2]), "r"(a[3]), "r"(b[0]), "r"(b[1]));
    else
        asm volatile(
            "mma.sync.aligned.m16n8k16.row.col.f32.bf16.bf16.f32 "
            "{%0,%1,%2,%3}, {%4,%5,%6,%7}, {%8,%9}, {%0,%1,%2,%3};"
            : "+f"(d[0]), "+f"(d[1]), "+f"(d[2]), "+f"(d[3])
            : "r"(a[0]), "r"(a[1]), "r"(a[2]), "r"(a[3]), "r"(b[0]), "r"(b[1]));
}
__device__ __forceinline__ void split2(float v, __nv_bfloat16* h, __nv_bfloat16* l) {
    __nv_bfloat16 hh = __float2bfloat16(v);
    *h = hh;
    *l = __float2bfloat16(v - __bfloat162float(hh));
}
__device__ __forceinline__ void split2h(float v, __half* h, __half* l) {
    __half hh = __float2half(v);
    *h = hh;
    *l = __float2half(v - __half2float(hh));
}
__device__ __forceinline__ void pk2(float x, float y, uint32_t& hi, uint32_t& lo) {
    __nv_bfloat16 xh = __float2bfloat16(x), yh = __float2bfloat16(y);
    __nv_bfloat16 xl = __float2bfloat16(x - __bfloat162float(xh));
    __nv_bfloat16 yl = __float2bfloat16(y - __bfloat162float(yh));
    hi = ((uint32_t)__bfloat16_as_ushort(yh) << 16) | __bfloat16_as_ushort(xh);
    lo = ((uint32_t)__bfloat16_as_ushort(yl) << 16) | __bfloat16_as_ushort(xl);
}
__device__ __forceinline__ void pk2h(float x, float y, uint32_t& hi, uint32_t& lo) {
    __half xh = __float2half(x), yh = __float2half(y);
    __half xl = __float2half(x - __half2float(xh));
    __half yl = __float2half(y - __half2float(yh));
    hi = ((uint32_t)__half_as_ushort(yh) << 16) | __half_as_ushort(xh);
    lo = ((uint32_t)__half_as_ushort(yl) << 16) | __half_as_ushort(xl);
}
// fast 2^y on the FMA pipe (y <= 0), err ~2e-6
__device__ __forceinline__ float ex2(float y) {
    y = fmaxf(y, -126.f);
    float fn = y + 12582912.f;
    int n = __float_as_int(fn) - 0x4B400000;
    float r = y - (fn - 12582912.f);
    float p = 1.3333558e-3f;
    p = fmaf(p, r, 9.6181291e-3f);
    p = fmaf(p, r, 5.5504109e-2f);
    p = fmaf(p, r, 2.4022651e-1f);
    p = fmaf(p, r, 6.9314718e-1f);
    p = fmaf(p, r, 1.0f);
    return p * __int_as_float((n + 127) << 23);
}
__device__ __forceinline__ uint32_t swz(uint32_t off) {
    return off ^ ((off >> 3) & 0x70);
}
__device__ __forceinline__ float gelu_f(float v) {
    return 0.5f * v * (1.0f + erff(v * 0.70710678118654752f));
}

// ---------------------------------------------------------------------------
// split-precision MMA GEMM, K-chunk 64, SW128 smem, 3-stage pipeline,
// templated warp-N width (WN=32 -> block 128x128; WN=64 -> block 128x256).
// bf16 (3-term): C = (Ah+Al)@(Bh+Bl)^T ; fp16 (2-term): C = (Ah+Al)@Bh^T
// ---------------------------------------------------------------------------
#define T16 16384                       // one 128x64 16-bit tile (128B rows)

template<int NB, int BROWS>
__device__ __forceinline__ void load_stageG(
    const __nv_bfloat16* A0, const __nv_bfloat16* A1,
    const __nv_bfloat16* B0, const __nv_bfloat16* B1,
    int K, int k0, uint32_t dbase, int tid) {
#pragma unroll
    for (int t = 0; t < 2; t++) {
        const __nv_bfloat16* s = t ? A1 : A0;
#pragma unroll
        for (int u = 0; u < 4; u++) {
            int id = u * 256 + tid;
            int row = id >> 3, c = id & 7;
            cpasync16(dbase + t * T16 + swz(row * 128 + c * 16),
                      s + (size_t)row * K + k0 + c * 8);
        }
    }
#pragma unroll
    for (int t = 0; t < NB; t++) {
        const __nv_bfloat16* s = t ? B1 : B0;
#pragma unroll
        for (int u = 0; u < BROWS / 32; u++) {
            int id = u * 256 + tid;
            int row = id >> 3, c = id & 7;
            cpasync16(dbase + 2 * T16 + t * (BROWS * 128) + swz(row * 128 + c * 16),
                      s + (size_t)row * K + k0 + c * 8);
        }
    }
}

template<bool FP16W, bool GELU, bool OUT16, int WN>
__global__ __launch_bounds__(256, 1)
void gemm_t(const __nv_bfloat16* __restrict__ Ahi, const __nv_bfloat16* __restrict__ Alo,
            const __nv_bfloat16* __restrict__ Bhi, const __nv_bfloat16* __restrict__ Blo,
            const float* __restrict__ bias, const float* __restrict__ bias2,
            const float* __restrict__ bias3, const float* __restrict__ res,
            float* __restrict__ C, __nv_bfloat16* __restrict__ Chi,
            __nv_bfloat16* __restrict__ Clo, int M, int N, int K, int oseg) {
    constexpr int NB = FP16W ? 1 : 2;
    constexpr int BROWS = 4 * WN;
    constexpr int NTT = WN / 8;
    constexpr int STAGE = (256 + NB * BROWS) * 128;
    extern __shared__ char smem[];
    const uint32_t sbase = s2u(smem);
    const int tid = threadIdx.x;
    const int warp = tid >> 5, lane = tid & 31;
    const int bm = blockIdx.y * 128, bn = blockIdx.x * BROWS;
    const int wm = (warp >> 2) * 64, wn = (warp & 3) * WN;

    float acc[4][NTT][4];
#pragma unroll
    for (int i = 0; i < 4; i++)
#pragma unroll
        for (int j = 0; j < NTT; j++)
#pragma unroll
            for (int q = 0; q < 4; q++) acc[i][j][q] = 0.f;

    const __nv_bfloat16* A0 = Ahi + (size_t)bm * K;
    const __nv_bfloat16* A1 = Alo + (size_t)bm * K;
    const __nv_bfloat16* B0 = Bhi + (size_t)bn * K;
    const __nv_bfloat16* B1 = FP16W ? nullptr : Blo + (size_t)bn * K;

    const int nch = K >> 6;
    load_stageG<NB, BROWS>(A0, A1, B0, B1, K, 0, sbase, tid);
    asm volatile("cp.async.commit_group;" ::: "memory");
    if (nch > 1) {
        load_stageG<NB, BROWS>(A0, A1, B0, B1, K, 64, sbase + STAGE, tid);
        asm volatile("cp.async.commit_group;" ::: "memory");
    }

    const int g = lane >> 3, r = lane & 7;
    const int a_row = r + (g & 1) * 8;
    const int a_cb  = (g >> 1) * 16;
    const int b_row = (g >> 1) * 8 + r;
    const int b_cb  = (g & 1) * 16;

    for (int c = 0; c < nch; c++) {
        if (c == nch - 1) asm volatile("cp.async.wait_group 0;" ::: "memory");
        else              asm volatile("cp.async.wait_group 1;" ::: "memory");
        __syncthreads();

        uint32_t base = sbase + (c % 3) * STAGE;
#pragma unroll
        for (int ks = 0; ks < 4; ks++) {
            const int kb = ks * 32;
            uint32_t ah[4][4], al[4][4], bh[NTT][2], bl[NTT][2];
#pragma unroll
            for (int mt = 0; mt < 4; mt++) {
                uint32_t ad = base + swz((wm + mt * 16 + a_row) * 128 + kb + a_cb);
                ldm4(ah[mt], ad);
                ldm4(al[mt], ad + T16);
            }
#pragma unroll
            for (int p = 0; p < WN / 16; p++) {
                uint32_t bd = base + 2 * T16 + swz((wn + p * 16 + b_row) * 128 + kb + b_cb);
                uint32_t t4[4];
                ldm4(t4, bd);
                bh[2 * p][0] = t4[0]; bh[2 * p][1] = t4[1];
                bh[2 * p + 1][0] = t4[2]; bh[2 * p + 1][1] = t4[3];
                if (!FP16W) {
                    ldm4(t4, bd + BROWS * 128);
                    bl[2 * p][0] = t4[0]; bl[2 * p][1] = t4[1];
                    bl[2 * p + 1][0] = t4[2]; bl[2 * p + 1][1] = t4[3];
                }
            }
#pragma unroll
            for (int mt = 0; mt < 4; mt++)
#pragma unroll
                for (int nt = 0; nt < NTT; nt++) {
                    mma16<FP16W>(acc[mt][nt], ah[mt], bh[nt]);
                    mma16<FP16W>(acc[mt][nt], al[mt], bh[nt]);
                    if (!FP16W) mma16<false>(acc[mt][nt], ah[mt], bl[nt]);
                }
        }
        if (c + 2 < nch) {
            load_stageG<NB, BROWS>(A0, A1, B0, B1, K, (c + 2) * 64,
                                   sbase + ((c + 2) % 3) * STAGE, tid);
            asm volatile("cp.async.commit_group;" ::: "memory");
        }
    }

    // ---- epilogue
    __nv_bfloat16 *chi = Chi, *clo = Clo;
    int ost = N, bnl = bn;
    if (oseg) {
        int t = bn / oseg;
        bnl = bn - t * oseg;
        ost = oseg;
        chi = Chi + (size_t)(2 * t) * M * oseg;
        clo = Chi + (size_t)(2 * t + 1) * M * oseg;
    }
#pragma unroll
    for (int mt = 0; mt < 4; mt++) {
        int r0 = bm + wm + mt * 16 + (lane >> 2);
#pragma unroll
        for (int nt = 0; nt < NTT; nt++) {
            int ccg = bn + wn + nt * 8 + (lane & 3) * 2;
            int ccl = bnl + wn + nt * 8 + (lane & 3) * 2;
            const float* bsel = bias;
            int bidx = ccg;
            if (bias2) {
                if (ccg >= 2 * Dc)      bsel = bias3;
                else if (ccg >= Dc)     bsel = bias2;
                bidx = ccg & (Dc - 1);
            }
            float b0 = bsel ? bsel[bidx] : 0.f, b1 = bsel ? bsel[bidx + 1] : 0.f;
            float v0 = acc[mt][nt][0] + b0, v1 = acc[mt][nt][1] + b1;
            float v2 = acc[mt][nt][2] + b0, v3 = acc[mt][nt][3] + b1;
            if (GELU) {
                v0 = gelu_f(v0); v1 = gelu_f(v1);
                v2 = gelu_f(v2); v3 = gelu_f(v3);
            }
            if (chi) {
                uint32_t h01, l01, h23, l23;
                if (OUT16) { pk2h(v0, v1, h01, l01); pk2h(v2, v3, h23, l23); }
                else       { pk2(v0, v1, h01, l01);  pk2(v2, v3, h23, l23); }
                *(uint32_t*)&chi[(size_t)r0 * ost + ccl] = h01;
                *(uint32_t*)&clo[(size_t)r0 * ost + ccl] = l01;
                *(uint32_t*)&chi[(size_t)(r0 + 8) * ost + ccl] = h23;
                *(uint32_t*)&clo[(size_t)(r0 + 8) * ost + ccl] = l23;
            } else {
                if (res) {
                    v0 += res[(size_t)r0 * N + ccg];       v1 += res[(size_t)r0 * N + ccg + 1];
                    v2 += res[(size_t)(r0 + 8) * N + ccg]; v3 += res[(size_t)(r0 + 8) * N + ccg + 1];
                }
                *(float2*)&C[(size_t)r0 * N + ccg] = make_float2(v0, v1);
                *(float2*)&C[(size_t)(r0 + 8) * N + ccg] = make_float2(v2, v3);
            }
        }
    }
}

#define SMEM_FP32 (3*(256+128)*128)     // 147456
#define SMEM_FP64 (3*(256+256)*128)     // 196608

// ---------------------------------------------------------------------------
// MMA flash attention (fp16 arithmetic, 3-term exact-split inputs):
// block = (qt 64 rows, h, b), 4 warps, 64-col k-tiles.
// ---------------------------------------------------------------------------
#define ATT_STAGE 32768
#define ATT_SMEM (2*ATT_STAGE)

__global__ __launch_bounds__(128, 2)
void attn_mma(const __nv_bfloat16* __restrict__ qhi, const __nv_bfloat16* __restrict__ qlo,
              const __nv_bfloat16* __restrict__ khi, const __nv_bfloat16* __restrict__ klo,
              const __nv_bfloat16* __restrict__ vhi, const __nv_bfloat16* __restrict__ vlo,
              __nv_bfloat16* __restrict__ ohi, __nv_bfloat16* __restrict__ olo) {
    extern __shared__ char sm[];
    const uint32_t sb = s2u(sm);
    const int qt = blockIdx.x, h = blockIdx.y, b = blockIdx.z;
    const int tid = threadIdx.x, warp = tid >> 5, lane = tid & 31;
    const int g = lane >> 3, r = lane & 7;
    const int a_row = r + (g & 1) * 8, a_cb = (g >> 1) * 16;
    const int b_row = (g >> 1) * 8 + r, b_cb = (g & 1) * 16;
    const size_t hoff = (size_t)h * 64;
    const size_t rowbase = (size_t)(b * Sc) * Dc;

#pragma unroll
    for (int t = 0; t < 2; t++) {
        const __nv_bfloat16* src = (t ? qlo : qhi) + rowbase + (size_t)(qt * 64) * Dc + hoff;
#pragma unroll
        for (int u = 0; u < 4; u++) {
            int id = u * 128 + tid;
            int row = id >> 3, c16 = id & 7;
            uint4 val = *(const uint4*)((const char*)(src + (size_t)row * Dc) + c16 * 16);
            *(uint4*)(sm + t * 8192 + swz(row * 128 + c16 * 16)) = val;
        }
    }
    __syncthreads();
    uint32_t qh_[4][4], ql_[4][4];
#pragma unroll
    for (int ks = 0; ks < 4; ks++) {
        uint32_t ad = sb + swz((warp * 16 + a_row) * 128 + ks * 32 + a_cb);
        ldm4(qh_[ks], ad);
        ldm4(ql_[ks], ad + 8192);
    }
    __syncthreads();

    float O[8][4];
#pragma unroll
    for (int i = 0; i < 8; i++)
#pragma unroll
        for (int j = 0; j < 4; j++) O[i][j] = 0.f;
    float m2[2] = {-1e30f, -1e30f};
    float lsum[2] = {0.f, 0.f};

    const __nv_bfloat16* srcs[4] = {khi, klo, vhi, vlo};
#define LOAD_KV(S, KT) do { \
        size_t base_ = rowbase + (size_t)((KT) * 64) * Dc + hoff; \
        uint32_t dst_ = sb + (S) * ATT_STAGE; \
        _Pragma("unroll") \
        for (int t = 0; t < 4; t++) { \
            _Pragma("unroll") \
            for (int u = 0; u < 4; u++) { \
                int id = u * 128 + tid; \
                int row = id >> 3, c16 = id & 7; \
                cpasync16(dst_ + t * 8192 + swz(row * 128 + c16 * 16), \
                          (const char*)(srcs[t] + base_ + (size_t)row * Dc) + c16 * 16); \
            } \
        } \
        asm volatile("cp.async.commit_group;" ::: "memory"); \
    } while (0)

    LOAD_KV(0, 0);

    for (int kt = 0; kt <= qt; kt++) {
        if (kt < qt) {
            LOAD_KV((kt + 1) & 1, kt + 1);
            asm volatile("cp.async.wait_group 1;" ::: "memory");
        } else {
            asm volatile("cp.async.wait_group 0;" ::: "memory");
        }
        __syncthreads();
        const uint32_t kb_ = sb + (kt & 1) * ATT_STAGE;

        float S[8][4];
#pragma unroll
        for (int i = 0; i < 8; i++)
#pragma unroll
            for (int j = 0; j < 4; j++) S[i][j] = 0.f;
#pragma unroll
        for (int ks = 0; ks < 4; ks++) {
#pragma unroll
            for (int p = 0; p < 4; p++) {
                uint32_t t4h[4], t4l[4];
                uint32_t bd = kb_ + swz((p * 16 + b_row) * 128 + ks * 32 + b_cb);
                ldm4(t4h, bd);
                ldm4(t4l, bd + 8192);
                uint32_t bh0[2] = {t4h[0], t4h[1]}, bh1[2] = {t4h[2], t4h[3]};
                uint32_t bl0[2] = {t4l[0], t4l[1]}, bl1[2] = {t4l[2], t4l[3]};
                mma16<true>(S[2 * p],     qh_[ks], bh0);
                mma16<true>(S[2 * p],     qh_[ks], bl0);
                mma16<true>(S[2 * p],     ql_[ks], bh0);
                mma16<true>(S[2 * p + 1], qh_[ks], bh1);
                mma16<true>(S[2 * p + 1], qh_[ks], bl1);
                mma16<true>(S[2 * p + 1], ql_[ks], bh1);
            }
        }
        const float SC = 0.18033688f;
#pragma unroll
        for (int i = 0; i < 8; i++)
#pragma unroll
            for (int j = 0; j < 4; j++) S[i][j] *= SC;
        if (kt == qt) {
            int rr = warp * 16 + (lane >> 2);
#pragma unroll
            for (int nt = 0; nt < 8; nt++) {
                int cc = nt * 8 + (lane & 3) * 2;
                if (cc     > rr)     S[nt][0] = -1e30f;
                if (cc + 1 > rr)     S[nt][1] = -1e30f;
                if (cc     > rr + 8) S[nt][2] = -1e30f;
                if (cc + 1 > rr + 8) S[nt][3] = -1e30f;
            }
        }
        float mx0 = -1e30f, mx1 = -1e30f;
#pragma unroll
        for (int nt = 0; nt < 8; nt++) {
            mx0 = fmaxf(mx0, fmaxf(S[nt][0], S[nt][1]));
            mx1 = fmaxf(mx1, fmaxf(S[nt][2], S[nt][3]));
        }
        mx0 = fmaxf(mx0, __shfl_xor_sync(0xffffffff, mx0, 1));
        mx0 = fmaxf(mx0, __shfl_xor_sync(0xffffffff, mx0, 2));
        mx1 = fmaxf(mx1, __shfl_xor_sync(0xffffffff, mx1, 1));
        mx1 = fmaxf(mx1, __shfl_xor_sync(0xffffffff, mx1, 2));
        float mn0 = fmaxf(m2[0], mx0), mn1 = fmaxf(m2[1], mx1);
        float al0 = ex2(m2[0] - mn0), al1 = ex2(m2[1] - mn1);
        m2[0] = mn0; m2[1] = mn1;
        float s0 = 0.f, s1 = 0.f;
#pragma unroll
        for (int nt = 0; nt < 8; nt++) {
            S[nt][0] = ex2(S[nt][0] - mn0); s0 += S[nt][0];
            S[nt][1] = ex2(S[nt][1] - mn0); s0 += S[nt][1];
            S[nt][2] = ex2(S[nt][2] - mn1); s1 += S[nt][2];
            S[nt][3] = ex2(S[nt][3] - mn1); s1 += S[nt][3];
        }
        s0 += __shfl_xor_sync(0xffffffff, s0, 1);
        s0 += __shfl_xor_sync(0xffffffff, s0, 2);
        s1 += __shfl_xor_sync(0xffffffff, s1, 1);
        s1 += __shfl_xor_sync(0xffffffff, s1, 2);
        lsum[0] = lsum[0] * al0 + s0;
        lsum[1] = lsum[1] * al1 + s1;
#pragma unroll
        for (int nt = 0; nt < 8; nt++) {
            O[nt][0] *= al0; O[nt][1] *= al0;
            O[nt][2] *= al1; O[nt][3] *= al1;
        }
        const uint32_t vb = kb_ + 16384;
#pragma unroll
        for (int ks = 0; ks < 4; ks++) {
            uint32_t pah[4], pal[4];
            pk2h(S[2 * ks][0],     S[2 * ks][1],     pah[0], pal[0]);
            pk2h(S[2 * ks][2],     S[2 * ks][3],     pah[1], pal[1]);
            pk2h(S[2 * ks + 1][0], S[2 * ks + 1][1], pah[2], pal[2]);
            pk2h(S[2 * ks + 1][2], S[2 * ks + 1][3], pah[3], pal[3]);
#pragma unroll
            for (int dg = 0; dg < 4; dg++) {
                uint32_t th[4], tl[4];
                uint32_t vd = vb + swz((ks * 16 + (lane & 15)) * 128 + dg * 32 + (lane >> 4) * 16);
                ldm4t(th, vd);
                ldm4t(tl, vd + 8192);
                uint32_t bh0[2] = {th[0], th[1]}, bh1[2] = {th[2], th[3]};
                uint32_t bl0[2] = {tl[0], tl[1]}, bl1[2] = {tl[2], tl[3]};
                mma16<true>(O[2 * dg],     pah, bh0);
                mma16<true>(O[2 * dg],     pah, bl0);
                mma16<true>(O[2 * dg],     pal, bh0);
                mma16<true>(O[2 * dg + 1], pah, bh1);
                mma16<true>(O[2 * dg + 1], pah, bl1);
                mma16<true>(O[2 * dg + 1], pal, bh1);
            }
        }
        __syncthreads();
    }

    float inv0 = 1.f / lsum[0], inv1 = 1.f / lsum[1];
    int r0 = qt * 64 + warp * 16 + (lane >> 2);
#pragma unroll
    for (int nt = 0; nt < 8; nt++) {
        int cc = nt * 8 + (lane & 3) * 2;
        size_t o0 = rowbase + (size_t)r0 * Dc + hoff + cc;
        size_t o1 = o0 + (size_t)8 * Dc;
        uint32_t h01, l01, h23, l23;
        pk2h(O[nt][0] * inv0, O[nt][1] * inv0, h01, l01);
        pk2h(O[nt][2] * inv1, O[nt][3] * inv1, h23, l23);
        *(uint32_t*)&ohi[o0] = h01; *(uint32_t*)&olo[o0] = l01;
        *(uint32_t*)&ohi[o1] = h23; *(uint32_t*)&olo[o1] = l23;
    }
}

// ---------------------------------------------------------------------------
// prep kernels
// ---------------------------------------------------------------------------
template<bool H>
__global__ void wtrans_split(const float* __restrict__ W,
                             void* __restrict__ hi_, void* __restrict__ lo_,
                             int K, int N) {
    __shared__ float t[32][33];
    int n0 = blockIdx.x * 32, k0 = blockIdx.y * 32;
    int tx = threadIdx.x, ty = threadIdx.y;
#pragma unroll
    for (int r = 0; r < 4; r++)
        t[ty + r * 8][tx] = W[(size_t)(k0 + ty + r * 8) * N + n0 + tx];
    __syncthreads();
#pragma unroll
    for (int r = 0; r < 4; r++) {
        int a = ty + r * 8;
        float v = t[tx][a];
        size_t o = (size_t)(n0 + a) * K + k0 + tx;
        if (H) split2h(v, (__half*)hi_ + o, (__half*)lo_ + o);
        else   split2(v, (__nv_bfloat16*)hi_ + o, (__nv_bfloat16*)lo_ + o);
    }
}

__global__ void split_kernel_h(const float* __restrict__ in,
                               __half* __restrict__ hi,
                               __half* __restrict__ lo, int n) {
    int i = blockIdx.x * 256 + threadIdx.x;
    if (i < n) split2h(in[i], &hi[i], &lo[i]);
}

__global__ void embed_kernel(const int* __restrict__ ids,
                             const float* __restrict__ tok,
                             const float* __restrict__ pos,
                             float* __restrict__ x) {
    int row = blockIdx.x;
    int s = row % Sc;
    int id = ids[row];
    const float* tr = tok + (size_t)id * Dc;
    const float* pr = pos + (size_t)s * Dc;
    float* xr = x + (size_t)row * Dc;
    for (int d = threadIdx.x; d < Dc; d += blockDim.x) xr[d] = tr[d] + pr[d];
}

template<bool HOUT>
__global__ void ln_kernel(const float* __restrict__ x,
                          const float* __restrict__ w, const float* __restrict__ b,
                          void* __restrict__ yhi, void* __restrict__ ylo) {
    int row = blockIdx.x;
    const float* xr = x + (size_t)row * Dc;
    __shared__ float r1[256], r2[256];
    float s = 0.f, s2 = 0.f;
    for (int d = threadIdx.x; d < Dc; d += 256) {
        float v = xr[d];
        s += v; s2 += v * v;
    }
    r1[threadIdx.x] = s; r2[threadIdx.x] = s2;
    __syncthreads();
    for (int st = 128; st > 0; st >>= 1) {
        if (threadIdx.x < st) {
            r1[threadIdx.x] += r1[threadIdx.x + st];
            r2[threadIdx.x] += r2[threadIdx.x + st];
        }
        __syncthreads();
    }
    float mean = r1[0] * (1.0f / Dc);
    float var = r2[0] * (1.0f / Dc) - mean * mean;
    float rstd = rsqrtf(var + 1e-5f);
    for (int d = threadIdx.x; d < Dc; d += 256) {
        float v = (xr[d] - mean) * rstd * w[d] + b[d];
        size_t o = (size_t)row * Dc + d;
        if (HOUT) split2h(v, (__half*)yhi + o, (__half*)ylo + o);
        else      split2(v, (__nv_bfloat16*)yhi + o, (__nv_bfloat16*)ylo + o);
    }
}

// ---------------------------------------------------------------------------
// launcher
// ---------------------------------------------------------------------------
extern "C" void kernel_launch(void* const* d_in, const int* in_sizes, int n_in,
                              void* d_out, int out_size) {
    const int*   ids   = (const int*)d_in[0];
    const float* tok   = (const float*)d_in[1];
    const float* pos   = (const float*)d_in[2];
    const float* Wq    = (const float*)d_in[3];
    const float* bq    = (const float*)d_in[4];
    const float* Wk    = (const float*)d_in[5];
    const float* bk    = (const float*)d_in[6];
    const float* Wv    = (const float*)d_in[7];
    const float* bv    = (const float*)d_in[8];
    const float* Wo    = (const float*)d_in[9];
    const float* bo    = (const float*)d_in[10];
    const float* ln1w  = (const float*)d_in[11];
    const float* ln1b  = (const float*)d_in[12];
    const float* ln2w  = (const float*)d_in[13];
    const float* ln2b  = (const float*)d_in[14];
    const float* Wup   = (const float*)d_in[15];
    const float* bup   = (const float*)d_in[16];
    const float* Wdown = (const float*)d_in[17];
    const float* bdown = (const float*)d_in[18];
    const float* fnw   = (const float*)d_in[19];
    const float* fnb   = (const float*)d_in[20];
    float* out = (float*)d_out;

    float *x;
    __nv_bfloat16 *qkv, *ahi, *alo, *bhi, *blo, *whi, *wlo;
    __half *thi, *tlo;
    cudaGetSymbolAddress((void**)&x, g_x);
    cudaGetSymbolAddress((void**)&qkv, g_qkv);
    cudaGetSymbolAddress((void**)&ahi, g_ahi);
    cudaGetSymbolAddress((void**)&alo, g_alo);
    cudaGetSymbolAddress((void**)&bhi, g_bhi);
    cudaGetSymbolAddress((void**)&blo, g_blo);
    cudaGetSymbolAddress((void**)&whi, g_whi);
    cudaGetSymbolAddress((void**)&wlo, g_wlo);
    cudaGetSymbolAddress((void**)&thi, g_thi);
    cudaGetSymbolAddress((void**)&tlo, g_tlo);
    __nv_bfloat16 *qhi = qkv,              *qlo = qkv + (size_t)MR * Dc;
    __nv_bfloat16 *khi = qkv + 2ull*MR*Dc, *klo = qkv + 3ull*MR*Dc;
    __nv_bfloat16 *vhi = qkv + 4ull*MR*Dc, *vlo = qkv + 5ull*MR*Dc;

    cudaFuncSetAttribute(gemm_t<true,false,true,32>,   cudaFuncAttributeMaxDynamicSharedMemorySize, SMEM_FP32);
    cudaFuncSetAttribute(gemm_t<true,true,true,32>,    cudaFuncAttributeMaxDynamicSharedMemorySize, SMEM_FP32);
    cudaFuncSetAttribute(gemm_t<true,false,false,32>,  cudaFuncAttributeMaxDynamicSharedMemorySize, SMEM_FP32);
    cudaFuncSetAttribute(gemm_t<true,false,false,64>,  cudaFuncAttributeMaxDynamicSharedMemorySize, SMEM_FP64);
    cudaFuncSetAttribute(attn_mma, cudaFuncAttributeMaxDynamicSharedMemorySize, ATT_SMEM);

    const dim3 tb32(32, 8);
    const dim3 gDD(Dc / 32, Dc / 32);
    const dim3 gDF(Fc / 32, Dc / 32);
    const dim3 gFD(Dc / 32, Fc / 32);

    const dim3 gmQKV(3 * Dc / 128, MR / 128);   // 24 x 32
    const dim3 gmD(Dc / 128, MR / 128);         // 8 x 32
    const dim3 gmF(Fc / 128, MR / 128);         // 32 x 32
    const dim3 gmD2(Dc / 256, MR / 128);        // 4 x 32  (WN=64)
    const dim3 gmV2(Vc / 256, MR / 128);        // 125 x 32 (WN=64)
    const dim3 gA(Sc / 64, Hc, Bc);

    embed_kernel<<<MR, 256>>>(ids, tok, pos, x);
    // weight conversion (all fp16 now)
    for (int l = 0; l < Lc; l++) {
        size_t lb = (size_t)l * WPL;
        wtrans_split<true><<<gDD, tb32>>>(Wq + (size_t)l * Dc * Dc, whi + lb,           wlo + lb,           Dc, Dc);
        wtrans_split<true><<<gDD, tb32>>>(Wk + (size_t)l * Dc * Dc, whi + lb + 1048576, wlo + lb + 1048576, Dc, Dc);
        wtrans_split<true><<<gDD, tb32>>>(Wv + (size_t)l * Dc * Dc, whi + lb + 2097152, wlo + lb + 2097152, Dc, Dc);
        wtrans_split<true><<<gDD, tb32>>>(Wo + (size_t)l * Dc * Dc, whi + lb + 3145728, wlo + lb + 3145728, Dc, Dc);
        wtrans_split<true><<<gDF, tb32>>>(Wup + (size_t)l * Dc * Fc, whi + lb + 4194304, wlo + lb + 4194304, Dc, Fc);
        wtrans_split<true><<<gFD, tb32>>>(Wdown + (size_t)l * Fc * Dc, whi + lb + 8388608, wlo + lb + 8388608, Fc, Dc);
    }
    split_kernel_h<<<(Vc * Dc + 255) / 256, 256>>>(tok, thi, tlo, Vc * Dc);

    for (int l = 0; l < Lc; l++) {
        size_t lb = (size_t)l * WPL;
        ln_kernel<true><<<MR, 256>>>(x, ln1w + l * Dc, ln1b + l * Dc, ahi, alo);
        gemm_t<true,false,true,32><<<gmQKV, 256, SMEM_FP32>>>(
            ahi, alo, whi + lb, nullptr, bq + l * Dc, bk + l * Dc, bv + l * Dc, nullptr,
            nullptr, qkv, nullptr, MR, 3 * Dc, Dc, Dc);
        attn_mma<<<gA, 128, ATT_SMEM>>>(qhi, qlo, khi, klo, vhi, vlo, ahi, alo);
        gemm_t<true,false,false,32><<<gmD, 256, SMEM_FP32>>>(
            ahi, alo, whi + lb + 3145728, nullptr, bo + l * Dc, nullptr, nullptr, x,
            x, nullptr, nullptr, MR, Dc, Dc, 0);
        ln_kernel<true><<<MR, 256>>>(x, ln2w + l * Dc, ln2b + l * Dc, ahi, alo);
        gemm_t<true,true,true,32><<<gmF, 256, SMEM_FP32>>>(
            ahi, alo, whi + lb + 4194304, nullptr, bup + l * Fc, nullptr, nullptr, nullptr,
            nullptr, bhi, blo, MR, Fc, Dc, 0);
        gemm_t<true,false,false,64><<<gmD2, 256, SMEM_FP64>>>(
            bhi, blo, whi + lb + 8388608, nullptr, bdown + l * Dc, nullptr, nullptr, x,
            x, nullptr, nullptr, MR, Dc, Fc, 0);
    }

    ln_kernel<true><<<MR, 256>>>(x, fnw, fnb, ahi, alo);
    gemm_t<true,false,false,64><<<gmV2, 256, SMEM_FP64>>>(
        ahi, alo, (const __nv_bfloat16*)thi, nullptr,
        nullptr, nullptr, nullptr, nullptr, out, nullptr, nullptr, MR, Vc, Dc, 0);
}